// round 12
// baseline (speedup 1.0000x reference)
#include <cuda_runtime.h>
#include <cuda_bf16.h>
#include <math.h>
#include <cstdint>

#define NB 8
#define NV 8192
#define NK 128
#define NC 256
#define NN 65536          // NB*NV
#define NNZ 1048576       // 16*NN
#define BNEPS 1e-5f

// ------------------------- scratch (device globals) -------------------------
static __device__ float d_xspec[NB*NK*NC];
static __device__ float d_xd  [NN*NC];
static __device__ float d_gX  [NN*NC];
static __device__ float d_gY  [NN*NC];
static __device__ float d_h0  [NN*NC];
static __device__ float d_h1  [NN*NC];
static __device__ float d_h2  [NN*NC];
static __device__ float d_stats[1536];
// CSR build scratch
static __device__ int d_cnt [131072];
static __device__ int d_off [131072];
static __device__ int d_bsum[512];
static __device__ int d_perm[2*NNZ];
// bf16 split A for MLP: [NN, 768] hi/lo  (cols: x | xd | gf)
static __device__ __nv_bfloat16 d_Ah[(size_t)NN*768];
static __device__ __nv_bfloat16 d_Al[(size_t)NN*768];
// bf16 split [gX|gY] operand for cplx GEMM: [NN, 512]
static __device__ __nv_bfloat16 d_Gh[(size_t)NN*512];
static __device__ __nv_bfloat16 d_Gl[(size_t)NN*512];
// bf16 split B pool: cplx-interleaved(512x512) | W0T(256x768) | W1T | W2T
#define BOFF_CPLX 0
#define BOFF_W0   262144
#define BOFF_W1   458752
#define BOFF_W2   524288
static __device__ __nv_bfloat16 d_Bh[589824];
static __device__ __nv_bfloat16 d_Bl[589824];
// spectral operands (bf16 split)
static __device__ __nv_bfloat16 d_mtH[(size_t)NB*NK*NV];
static __device__ __nv_bfloat16 d_mtL[(size_t)NB*NK*NV];
static __device__ __nv_bfloat16 d_xtH[(size_t)NB*NC*NV];
static __device__ __nv_bfloat16 d_xtL[(size_t)NB*NC*NV];
static __device__ __nv_bfloat16 d_eH[(size_t)NN*NK];
static __device__ __nv_bfloat16 d_eL[(size_t)NN*NK];
static __device__ __nv_bfloat16 d_ytH[NB*NC*NK];
static __device__ __nv_bfloat16 d_ytL[NB*NC*NK];

__device__ __forceinline__ uint32_t smem_u32(const void* p) {
    uint32_t a;
    asm("{ .reg .u64 t; cvta.to.shared.u64 t, %1; cvt.u32.u64 %0, t; }" : "=r"(a) : "l"(p));
    return a;
}

struct SplitPack { uint4 hi, lo; };
__device__ __forceinline__ SplitPack split8(float4 a, float4 b) {
    union { __nv_bfloat16 h[8]; uint4 u; } H;
    union { __nv_bfloat16 h[8]; uint4 u; } L;
    float v[8] = {a.x, a.y, a.z, a.w, b.x, b.y, b.z, b.w};
#pragma unroll
    for (int j = 0; j < 8; j++) {
        __nv_bfloat16 hh = __float2bfloat16(v[j]);
        H.h[j] = hh;
        L.h[j] = __float2bfloat16(v[j] - __bfloat162float(hh));
    }
    SplitPack r; r.hi = H.u; r.lo = L.u; return r;
}
struct SplitPack4 { uint2 hi, lo; };
__device__ __forceinline__ SplitPack4 split4(const float* v) {
    union { __nv_bfloat16 h[4]; uint2 u; } H;
    union { __nv_bfloat16 h[4]; uint2 u; } L;
#pragma unroll
    for (int j = 0; j < 4; j++) {
        __nv_bfloat16 hh = __float2bfloat16(v[j]);
        H.h[j] = hh;
        L.h[j] = __float2bfloat16(v[j] - __bfloat162float(hh));
    }
    SplitPack4 r; r.hi = H.u; r.lo = L.u; return r;
}
__device__ __forceinline__ void split2w(float a, float b, uint32_t& hi, uint32_t& lo) {
    __nv_bfloat16 ha = __float2bfloat16(a), hb = __float2bfloat16(b);
    __nv_bfloat16 la = __float2bfloat16(a - __bfloat162float(ha));
    __nv_bfloat16 lb = __float2bfloat16(b - __bfloat162float(hb));
    union { __nv_bfloat16 h[2]; uint32_t u; } H, L;
    H.h[0] = ha; H.h[1] = hb; L.h[0] = la; L.h[1] = lb;
    hi = H.u; lo = L.u;
}
__device__ __forceinline__ void split1(float v, __nv_bfloat16* ph, __nv_bfloat16* pl) {
    __nv_bfloat16 h = __float2bfloat16(v);
    *ph = h;
    *pl = __float2bfloat16(v - __bfloat162float(h));
}

// ------------------------------- zero init ----------------------------------
__global__ void k_zero() {
    int i = blockIdx.x * 256 + threadIdx.x;     // < 65536
    float4 z = make_float4(0.f, 0.f, 0.f, 0.f);
    *(float4*)&d_xspec[i * 4] = z;
    if (i < 32768) *(int4*)&d_cnt[i * 4] = make_int4(0, 0, 0, 0);
    if (i < 384)   *(float4*)&d_stats[i * 4] = z;
}

// ========================= CSR build (both matrices) =========================
__global__ void k_hist(const int* __restrict__ gxr, const int* __restrict__ gyr) {
    int i = blockIdx.x * 256 + threadIdx.x;
    atomicAdd(&d_cnt[gxr[i]], 1);
    atomicAdd(&d_cnt[65536 + gyr[i]], 1);
}

__global__ void k_scan1() {
    __shared__ int sh[256];
    int tid = threadIdx.x;
    int i = blockIdx.x * 256 + tid;
    int v = d_cnt[i];
    sh[tid] = v;
    __syncthreads();
    for (int o = 1; o < 256; o <<= 1) {
        int t = (tid >= o) ? sh[tid - o] : 0;
        __syncthreads();
        sh[tid] += t;
        __syncthreads();
    }
    d_off[i] = sh[tid] - v;
    if (tid == 255) d_bsum[blockIdx.x] = sh[255];
}

__global__ void k_scan2() {
    __shared__ int sh[512];
    int tid = threadIdx.x;
    int v = d_bsum[tid];
    sh[tid] = v;
    __syncthreads();
    for (int o = 1; o < 512; o <<= 1) {
        int t = (tid >= o) ? sh[tid - o] : 0;
        __syncthreads();
        sh[tid] += t;
        __syncthreads();
    }
    d_bsum[tid] = sh[tid] - v;
}

__global__ void k_scan3() {
    int i = blockIdx.x * 256 + threadIdx.x;
    int v = d_off[i] + d_bsum[i >> 8];
    d_off[i] = v;
    d_cnt[i] = v;
}

__global__ void k_scatter(const int* __restrict__ gxr, const int* __restrict__ gyr) {
    int i = blockIdx.x * 256 + threadIdx.x;
    int p = atomicAdd(&d_cnt[gxr[i]], 1);
    d_perm[p] = i;
    int q = atomicAdd(&d_cnt[65536 + gyr[i]], 1);
    d_perm[q] = i;
}

// merged CSR spmm: float out + bf16-split into G operand. grid 32768, 256 thr
__global__ __launch_bounds__(256) void k_spmm_csr(
    const int* __restrict__ gxc, const float* __restrict__ gxv,
    const int* __restrict__ gyc, const float* __restrict__ gyv) {
    int g = threadIdx.x >> 6, t = threadIdx.x & 63;
    int idx = blockIdx.x * 4 + g;               // < 131072
    int isX = (idx < 65536);
    const int*   cols = isX ? gxc : gyc;
    const float* vals = isX ? gxv : gyv;
    float* out        = isX ? d_gX : d_gY;
    int r = idx & 65535;
    int s = d_off[idx], e = d_cnt[idx];
    int c = t * 4;
    float4 acc = make_float4(0.f, 0.f, 0.f, 0.f);
    int p = s;
    for (; p + 4 <= e; p += 4) {
        int e0 = d_perm[p], e1 = d_perm[p+1], e2 = d_perm[p+2], e3 = d_perm[p+3];
        int c0 = cols[e0], c1 = cols[e1], c2 = cols[e2], c3 = cols[e3];
        float v0 = vals[e0], v1 = vals[e1], v2 = vals[e2], v3 = vals[e3];
        float4 x0 = *(const float4*)&d_xd[(size_t)c0 * NC + c];
        float4 x1 = *(const float4*)&d_xd[(size_t)c1 * NC + c];
        float4 x2 = *(const float4*)&d_xd[(size_t)c2 * NC + c];
        float4 x3 = *(const float4*)&d_xd[(size_t)c3 * NC + c];
        acc.x += v0*x0.x + v1*x1.x + v2*x2.x + v3*x3.x;
        acc.y += v0*x0.y + v1*x1.y + v2*x2.y + v3*x3.y;
        acc.z += v0*x0.z + v1*x1.z + v2*x2.z + v3*x3.z;
        acc.w += v0*x0.w + v1*x1.w + v2*x2.w + v3*x3.w;
    }
    for (; p < e; p++) {
        int ed = d_perm[p];
        int cl = cols[ed];
        float v = vals[ed];
        float4 xv = *(const float4*)&d_xd[(size_t)cl * NC + c];
        acc.x += v*xv.x; acc.y += v*xv.y; acc.z += v*xv.z; acc.w += v*xv.w;
    }
    *(float4*)&out[(size_t)r * NC + c] = acc;
    SplitPack4 sp = split4(&acc.x);
    size_t go = (size_t)r * 512 + (isX ? 0 : 256) + c;
    *(uint2*)&d_Gh[go] = sp.hi;
    *(uint2*)&d_Gl[go] = sp.lo;
}

// ===================== spectral operand preparation ==========================
__global__ __launch_bounds__(256) void k_trans_mevecs(
    const float* __restrict__ evecs, const float* __restrict__ mass) {
    __shared__ float tile[32][33];
    __shared__ float smass[32];
    int v0 = blockIdx.x * 32, k0 = blockIdx.y * 32, b = blockIdx.z;
    int tid = threadIdx.x;
    int tx = tid & 31, ty = tid >> 5;
    if (tid < 32) smass[tid] = mass[b * NV + v0 + tid];
#pragma unroll
    for (int i = 0; i < 4; i++) {
        int vl = ty + i * 8;
        tile[vl][tx] = evecs[(size_t)(b * NV + v0 + vl) * NK + k0 + tx];
    }
    __syncthreads();
    {
        int k = tid >> 3, vq = (tid & 7) * 4;
        float v[4];
#pragma unroll
        for (int j = 0; j < 4; j++) v[j] = tile[vq + j][k] * smass[vq + j];
        SplitPack4 p = split4(v);
        size_t o = (size_t)(b * NK + k0 + k) * NV + v0 + vq;
        *(uint2*)&d_mtH[o] = p.hi;
        *(uint2*)&d_mtL[o] = p.lo;
    }
    {
        int v = tid >> 3, kq = (tid & 7) * 4;
        float w[4];
#pragma unroll
        for (int j = 0; j < 4; j++) w[j] = tile[v][kq + j];
        SplitPack4 p = split4(w);
        size_t o = (size_t)(b * NV + v0 + v) * NK + k0 + kq;
        *(uint2*)&d_eH[o] = p.hi;
        *(uint2*)&d_eL[o] = p.lo;
    }
}

// x^T + x-split into A cols [0..256). grid (256, 8, 8)
__global__ __launch_bounds__(256) void k_trans_x(const float* __restrict__ x) {
    __shared__ float tile[32][33];
    int v0 = blockIdx.x * 32, c0 = blockIdx.y * 32, b = blockIdx.z;
    int tid = threadIdx.x;
    int tx = tid & 31, ty = tid >> 5;
#pragma unroll
    for (int i = 0; i < 4; i++) {
        int vl = ty + i * 8;
        tile[vl][tx] = x[(size_t)(b * NV + v0 + vl) * NC + c0 + tx];
    }
    __syncthreads();
    {
        int c = tid >> 3, vq = (tid & 7) * 4;
        float v[4];
#pragma unroll
        for (int j = 0; j < 4; j++) v[j] = tile[vq + j][c];
        SplitPack4 p = split4(v);
        size_t o = (size_t)(b * NC + c0 + c) * NV + v0 + vq;
        *(uint2*)&d_xtH[o] = p.hi;
        *(uint2*)&d_xtL[o] = p.lo;
    }
    {
        int v = tid >> 3, cq = (tid & 7) * 4;
        float w[4];
#pragma unroll
        for (int j = 0; j < 4; j++) w[j] = tile[v][cq + j];
        SplitPack4 p = split4(w);
        size_t o = (size_t)(b * NV + v0 + v) * 768 + c0 + cq;
        *(uint2*)&d_Ah[o] = p.hi;
        *(uint2*)&d_Al[o] = p.lo;
    }
}

__global__ void k_coefT(const float* __restrict__ evals, const float* __restrict__ dt) {
    int i = blockIdx.x * 256 + threadIdx.x;   // < 65536
    int kq = (i & 31) * 4;
    int c  = (i >> 5) & 255;
    int b  = i >> 13;
    float t = fmaxf(dt[c], 1e-8f);
    float v[4];
#pragma unroll
    for (int j = 0; j < 4; j++)
        v[j] = expf(-evals[b * NK + kq + j] * t) * d_xspec[(b * NK + kq + j) * NC + c];
    SplitPack4 p = split4(v);
    int o = b * (NC * NK) + c * NK + kq;
    *(uint2*)&d_ytH[o] = p.hi;
    *(uint2*)&d_ytL[o] = p.lo;
}

// ============================ mma primitives =================================
__device__ __forceinline__ void ldsm_x4(uint32_t* r, uint32_t addr) {
    asm volatile("ldmatrix.sync.aligned.m8n8.x4.shared.b16 {%0,%1,%2,%3}, [%4];"
                 : "=r"(r[0]), "=r"(r[1]), "=r"(r[2]), "=r"(r[3]) : "r"(addr));
}
__device__ __forceinline__ void ldsm_x2(uint32_t* r, uint32_t addr) {
    asm volatile("ldmatrix.sync.aligned.m8n8.x2.shared.b16 {%0,%1}, [%2];"
                 : "=r"(r[0]), "=r"(r[1]) : "r"(addr));
}
__device__ __forceinline__ void mma16816(float* c, const uint32_t* a, const uint32_t* b) {
    asm volatile("mma.sync.aligned.m16n8k16.row.col.f32.bf16.bf16.f32 "
                 "{%0,%1,%2,%3}, {%4,%5,%6,%7}, {%8,%9}, {%0,%1,%2,%3};"
                 : "+f"(c[0]), "+f"(c[1]), "+f"(c[2]), "+f"(c[3])
                 : "r"(a[0]), "r"(a[1]), "r"(a[2]), "r"(a[3]), "r"(b[0]), "r"(b[1]));
}
#define CP_ASYNC(sm, gm) \
    asm volatile("cp.async.cg.shared.global [%0], [%1], 16;" :: "r"(sm), "l"(gm))
#define CP_COMMIT() asm volatile("cp.async.commit_group;" ::: "memory")
#define CP_WAIT(n)  asm volatile("cp.async.wait_group %0;" :: "n"(n) : "memory")

#define ASTR 40
#define TILEEL (128*ASTR)
#define SLOT (TILEEL*2*2)            // one operand slot: hi+lo = 20480 bytes
#define GEMM_SMEM (2*4*TILEEL*2)     // xspec kernel: 81920
#define GEMM_SMEM2 (5*SLOT)          // k_mma_gemm: 3 A-slots + 2 B-slots = 102400

#define MMA_BLOCK() do { \
    _Pragma("unroll") \
    for (int mi = 0; mi < 4; mi++) \
        _Pragma("unroll") \
        for (int ni = 0; ni < 4; ni++) \
            mma16816(acc[mi][ni], aH[mi], bH[ni]); \
    _Pragma("unroll") \
    for (int mi = 0; mi < 4; mi++) \
        _Pragma("unroll") \
        for (int ni = 0; ni < 4; ni++) \
            mma16816(acc[mi][ni], aH[mi], bL[ni]); \
    _Pragma("unroll") \
    for (int mi = 0; mi < 4; mi++) \
        _Pragma("unroll") \
        for (int ni = 0; ni < 4; ni++) \
            mma16816(acc[mi][ni], aL[mi], bH[ni]); \
} while (0)

// ------------------- x_spec split-K mma: grid (32, 2, 8) ---------------------
__global__ __launch_bounds__(256, 2) void k_xspec_mma() {
    extern __shared__ __align__(16) __nv_bfloat16 sm[];
    int tid = threadIdx.x;
    int wid = tid >> 5, lane = tid & 31;
    int wm = wid & 1, wn = wid >> 1;
    int kb = blockIdx.x, ch = blockIdx.y, b = blockIdx.z;
    const __nv_bfloat16* Ah = d_mtH + (size_t)b * NK * NV;
    const __nv_bfloat16* Al = d_mtL + (size_t)b * NK * NV;
    const __nv_bfloat16* Bh = d_xtH + (size_t)(b * NC + ch * 128) * NV;
    const __nv_bfloat16* Bl = d_xtL + (size_t)(b * NC + ch * 128) * NV;
    int kbase = kb * 256;

    float acc[4][4][4];
#pragma unroll
    for (int mi = 0; mi < 4; mi++)
#pragma unroll
        for (int ni = 0; ni < 4; ni++)
#pragma unroll
            for (int q = 0; q < 4; q++) acc[mi][ni][q] = 0.f;

    int idx0 = tid * 2, idx1 = tid * 2 + 1;
    int lr0 = idx0 >> 2, ls0 = idx0 & 3;
    int lr1 = idx1 >> 2, ls1 = idx1 & 3;
    uint32_t so0 = (uint32_t)(lr0 * ASTR + ls0 * 8) * 2;
    uint32_t so1 = (uint32_t)(lr1 * ASTR + ls1 * 8) * 2;
    uint32_t smbase = smem_u32(sm);

#define XLOAD(s) do { \
    uint32_t sb = smbase + (uint32_t)((s) & 1) * 4u * TILEEL * 2u; \
    int k0 = kbase + ((s) << 5); \
    CP_ASYNC(sb + so0, Ah + (size_t)lr0 * NV + k0 + ls0*8); \
    CP_ASYNC(sb + so1, Ah + (size_t)lr1 * NV + k0 + ls1*8); \
    CP_ASYNC(sb + TILEEL*2 + so0, Al + (size_t)lr0 * NV + k0 + ls0*8); \
    CP_ASYNC(sb + TILEEL*2 + so1, Al + (size_t)lr1 * NV + k0 + ls1*8); \
    CP_ASYNC(sb + 2*TILEEL*2 + so0, Bh + (size_t)lr0 * NV + k0 + ls0*8); \
    CP_ASYNC(sb + 2*TILEEL*2 + so1, Bh + (size_t)lr1 * NV + k0 + ls1*8); \
    CP_ASYNC(sb + 3*TILEEL*2 + so0, Bl + (size_t)lr0 * NV + k0 + ls0*8); \
    CP_ASYNC(sb + 3*TILEEL*2 + so1, Bl + (size_t)lr1 * NV + k0 + ls1*8); \
} while (0)

    XLOAD(0);
    CP_COMMIT();

    int arow = (lane & 15), acol = (lane >> 4) * 8;
    int brow = (lane & 7),  bcol = ((lane >> 3) & 1) * 8;

    for (int s = 0; s < 8; s++) {
        if (s + 1 < 8) { XLOAD(s + 1); CP_COMMIT(); CP_WAIT(1); }
        else           { CP_WAIT(0); }
        __syncthreads();
        uint32_t sb = smbase + (uint32_t)(s & 1) * 4u * TILEEL * 2u;
        uint32_t Ah_s = sb, Al_s = sb + TILEEL*2, Bh_s = sb + 2*TILEEL*2, Bl_s = sb + 3*TILEEL*2;
#pragma unroll
        for (int ks = 0; ks < 2; ks++) {
            int k0 = ks * 16;
            uint32_t aH[4][4], aL[4][4];
#pragma unroll
            for (int mi = 0; mi < 4; mi++) {
                uint32_t off = (uint32_t)((wm*64 + mi*16 + arow) * ASTR + k0 + acol) * 2;
                ldsm_x4(aH[mi], Ah_s + off);
                ldsm_x4(aL[mi], Al_s + off);
            }
            uint32_t bH[4][2], bL[4][2];
#pragma unroll
            for (int ni = 0; ni < 4; ni++) {
                uint32_t off = (uint32_t)((wn*32 + ni*8 + brow) * ASTR + k0 + bcol) * 2;
                ldsm_x2(bH[ni], Bh_s + off);
                ldsm_x2(bL[ni], Bl_s + off);
            }
            MMA_BLOCK();
        }
        __syncthreads();
    }

    int g4 = lane >> 2, t4 = lane & 3;
#pragma unroll
    for (int mi = 0; mi < 4; mi++) {
        int r = wm*64 + mi*16 + g4;
#pragma unroll
        for (int ni = 0; ni < 4; ni++) {
            int c = ch*128 + wn*32 + ni*8 + t4*2;
            float* o0 = &d_xspec[(b*NK + r) * NC + c];
            float* o1 = &d_xspec[(b*NK + r + 8) * NC + c];
            asm volatile("red.global.add.v2.f32 [%0], {%1,%2};"
                         :: "l"(o0), "f"(acc[mi][ni][0]), "f"(acc[mi][ni][1]) : "memory");
            asm volatile("red.global.add.v2.f32 [%0], {%1,%2};"
                         :: "l"(o1), "f"(acc[mi][ni][2]), "f"(acc[mi][ni][3]) : "memory");
        }
    }
}

// ========================== B-operand prep (bf16 split) ======================
__global__ void k_prep_cplxB(const float* __restrict__ Are, const float* __restrict__ Aim) {
    int i = blockIdx.x * 256 + threadIdx.x;   // < 262144
    int n = i >> 9, k = i & 511;
    int m = n >> 1;
    float v;
    if ((n & 1) == 0) v = (k < 256) ? Are[m*256 + k] : -Aim[m*256 + (k-256)];
    else              v = (k < 256) ? Aim[m*256 + k] :  Are[m*256 + (k-256)];
    split1(v, &d_Bh[BOFF_CPLX + i], &d_Bl[BOFF_CPLX + i]);
}

__global__ void k_prep_wT(const float* __restrict__ W, int K, int N, int off) {
    int i = blockIdx.x * 256 + threadIdx.x;
    if (i >= N * K) return;
    int n = i / K, k = i % K;
    split1(W[k*N + n], &d_Bh[off + i], &d_Bl[off + i]);
}

// relu(bn(h)) -> A cols [0..255]. grid 8192, 256 thr
__global__ void k_bnsplit(const float* __restrict__ h, int statoff,
                          const float* __restrict__ g, const float* __restrict__ be) {
    int tid = threadIdx.x;
    __shared__ float sc[256], sh[256];
    {
        float mean = d_stats[statoff + tid] * (1.0f / NN);
        float var  = d_stats[statoff + 256 + tid] * (1.0f / NN) - mean * mean;
        float s = rsqrtf(var + BNEPS) * g[tid];
        sc[tid] = s;
        sh[tid] = be[tid] - mean * s;
    }
    __syncthreads();
    int idx = blockIdx.x * 256 + tid;          // < 2097152
    size_t row = idx >> 5;
    int c = (idx & 31) * 8;
    size_t o = row * 256 + c;
    float4 h0 = *(const float4*)&h[o], h1 = *(const float4*)&h[o + 4];
    float4 v0, v1;
    v0.x = fmaxf(h0.x * sc[c+0] + sh[c+0], 0.f);
    v0.y = fmaxf(h0.y * sc[c+1] + sh[c+1], 0.f);
    v0.z = fmaxf(h0.z * sc[c+2] + sh[c+2], 0.f);
    v0.w = fmaxf(h0.w * sc[c+3] + sh[c+3], 0.f);
    v1.x = fmaxf(h1.x * sc[c+4] + sh[c+4], 0.f);
    v1.y = fmaxf(h1.y * sc[c+5] + sh[c+5], 0.f);
    v1.z = fmaxf(h1.z * sc[c+6] + sh[c+6], 0.f);
    v1.w = fmaxf(h1.w * sc[c+7] + sh[c+7], 0.f);
    SplitPack p = split8(v0, v1);
    size_t base = row * 768;
    *(uint4*)&d_Ah[base + c] = p.hi;
    *(uint4*)&d_Al[base + c] = p.lo;
}

// ========================= generic mma.sync bf16-split GEMM ==================
// A-ring depth 3 (DRAM-latency cover), B-ring depth 2 (L2-resident weights).
// mode 0: normal epilogue; mode 2: gf epilogue (smem-staged, coalesced).
__global__ __launch_bounds__(256, 2) void k_mma_gemm(
    const __nv_bfloat16* __restrict__ Ah, const __nv_bfloat16* __restrict__ Al, int ldA,
    const __nv_bfloat16* __restrict__ Bh, const __nv_bfloat16* __restrict__ Bl,
    float* __restrict__ out, int ldout, const float* __restrict__ bias, int K,
    float* __restrict__ stats, int bstrideB, int mode, int asplit_off)
{
    extern __shared__ __align__(16) __nv_bfloat16 sm[];
    int tid = threadIdx.x;
    int wid = tid >> 5, lane = tid & 31;
    int wm = wid & 1, wn = wid >> 1;
    int row0 = blockIdx.y * 128, n0 = blockIdx.x * 128;
    if (bstrideB) {
        int b = row0 / NV;
        Bh += (size_t)b * bstrideB;
        Bl += (size_t)b * bstrideB;
    }

    float acc[4][4][4];
#pragma unroll
    for (int mi = 0; mi < 4; mi++)
#pragma unroll
        for (int ni = 0; ni < 4; ni++)
#pragma unroll
            for (int q = 0; q < 4; q++) acc[mi][ni][q] = 0.f;

    int idx0 = tid * 2, idx1 = tid * 2 + 1;
    int lr0 = idx0 >> 2, ls0 = idx0 & 3;
    int lr1 = idx1 >> 2, ls1 = idx1 & 3;
    uint32_t so0 = (uint32_t)(lr0 * ASTR + ls0 * 8) * 2;
    uint32_t so1 = (uint32_t)(lr1 * ASTR + ls1 * 8) * 2;
    uint32_t smbase = smem_u32(sm);

    const int S = K >> 5;

    // A slot i at smbase + i*SLOT (i<3); B slot j at smbase + 3*SLOT + j*SLOT
#define ALOAD(s, slot) do { \
    uint32_t sb = smbase + (uint32_t)(slot) * (uint32_t)SLOT; \
    int k0 = (s) << 5; \
    CP_ASYNC(sb + so0, Ah + (size_t)(row0 + lr0) * ldA + k0 + ls0*8); \
    CP_ASYNC(sb + so1, Ah + (size_t)(row0 + lr1) * ldA + k0 + ls1*8); \
    CP_ASYNC(sb + TILEEL*2 + so0, Al + (size_t)(row0 + lr0) * ldA + k0 + ls0*8); \
    CP_ASYNC(sb + TILEEL*2 + so1, Al + (size_t)(row0 + lr1) * ldA + k0 + ls1*8); \
} while (0)
#define BLOAD(s, slot) do { \
    uint32_t sb = smbase + 3u*(uint32_t)SLOT + (uint32_t)(slot) * (uint32_t)SLOT; \
    int k0 = (s) << 5; \
    CP_ASYNC(sb + so0, Bh + (size_t)(n0 + lr0) * K + k0 + ls0*8); \
    CP_ASYNC(sb + so1, Bh + (size_t)(n0 + lr1) * K + k0 + ls1*8); \
    CP_ASYNC(sb + TILEEL*2 + so0, Bl + (size_t)(n0 + lr0) * K + k0 + ls0*8); \
    CP_ASYNC(sb + TILEEL*2 + so1, Bl + (size_t)(n0 + lr1) * K + k0 + ls1*8); \
} while (0)

    // prologue: commits g0..g4 = A0,B0,A1,B1,A2
    ALOAD(0, 0);            CP_COMMIT();
    BLOAD(0, 0);            CP_COMMIT();
    if (1 < S) ALOAD(1, 1); CP_COMMIT();
    if (1 < S) BLOAD(1, 1); CP_COMMIT();
    if (2 < S) ALOAD(2, 2); CP_COMMIT();

    int arow = (lane & 15), acol = (lane >> 4) * 8;
    int brow = (lane & 7),  bcol = ((lane >> 3) & 1) * 8;

    int am = 0;   // s % 3
    for (int s = 0; s < S; s++) {
        CP_WAIT(2);
        __syncthreads();

        uint32_t Ah_s = smbase + (uint32_t)am * (uint32_t)SLOT;
        uint32_t Al_s = Ah_s + TILEEL*2;
        uint32_t Bh_s = smbase + 3u*(uint32_t)SLOT + (uint32_t)(s & 1) * (uint32_t)SLOT;
        uint32_t Bl_s = Bh_s + TILEEL*2;

#pragma unroll
        for (int ks = 0; ks < 2; ks++) {
            int k0 = ks * 16;
            uint32_t aH[4][4], aL[4][4];
#pragma unroll
            for (int mi = 0; mi < 4; mi++) {
                uint32_t off = (uint32_t)((wm*64 + mi*16 + arow) * ASTR + k0 + acol) * 2;
                ldsm_x4(aH[mi], Ah_s + off);
                ldsm_x4(aL[mi], Al_s + off);
            }
            uint32_t bH[4][2], bL[4][2];
#pragma unroll
            for (int ni = 0; ni < 4; ni++) {
                uint32_t off = (uint32_t)((wn*32 + ni*8 + brow) * ASTR + k0 + bcol) * 2;
                ldsm_x2(bH[ni], Bh_s + off);
                ldsm_x2(bL[ni], Bl_s + off);
            }
            MMA_BLOCK();
        }
        __syncthreads();

        // issue next loads AFTER consumption (slot (s+3)%3 == am, (s+2)%2 == s%2)
        if (s + 3 < S) ALOAD(s + 3, am);
        CP_COMMIT();
        if (s + 2 < S) BLOAD(s + 2, s & 1);
        CP_COMMIT();

        am = (am == 2) ? 0 : am + 1;
    }

    int g4 = lane >> 2, t4 = lane & 3;

    if (mode == 2) {
        // stage (re,im) pairs in smem: [128 rows][64 channels] float2 = 64KB
        float2* sgf = (float2*)sm;
#pragma unroll
        for (int mi = 0; mi < 4; mi++) {
            int rl = wm*64 + mi*16 + g4;
#pragma unroll
            for (int ni = 0; ni < 4; ni++) {
                int chl = wn*16 + ni*4 + t4;
                sgf[rl*64 + chl]       = make_float2(acc[mi][ni][0], acc[mi][ni][1]);
                sgf[(rl+8)*64 + chl]   = make_float2(acc[mi][ni][2], acc[mi][ni][3]);
            }
        }
        __syncthreads();
        int rl = tid >> 1;
        int co = (tid & 1) * 32;
        int r = row0 + rl;
        int chbase = (n0 >> 1) + co;
        const float* gxp = &d_gX[(size_t)r * NC + chbase];
        const float* gyp = &d_gY[(size_t)r * NC + chbase];
        size_t ao = (size_t)r * 768 + 512 + chbase;
#pragma unroll
        for (int j0 = 0; j0 < 32; j0 += 8) {
            float4 gx0 = *(const float4*)(gxp + j0);
            float4 gx1 = *(const float4*)(gxp + j0 + 4);
            float4 gy0 = *(const float4*)(gyp + j0);
            float4 gy1 = *(const float4*)(gyp + j0 + 4);
            float4 t0, t1;
            float2 p;
            p = sgf[rl*64 + co + j0 + 0]; t0.x = tanhf(gx0.x*p.x + gy0.x*p.y);
            p = sgf[rl*64 + co + j0 + 1]; t0.y = tanhf(gx0.y*p.x + gy0.y*p.y);
            p = sgf[rl*64 + co + j0 + 2]; t0.z = tanhf(gx0.z*p.x + gy0.z*p.y);
            p = sgf[rl*64 + co + j0 + 3]; t0.w = tanhf(gx0.w*p.x + gy0.w*p.y);
            p = sgf[rl*64 + co + j0 + 4]; t1.x = tanhf(gx1.x*p.x + gy1.x*p.y);
            p = sgf[rl*64 + co + j0 + 5]; t1.y = tanhf(gx1.y*p.x + gy1.y*p.y);
            p = sgf[rl*64 + co + j0 + 6]; t1.z = tanhf(gx1.z*p.x + gy1.z*p.y);
            p = sgf[rl*64 + co + j0 + 7]; t1.w = tanhf(gx1.w*p.x + gy1.w*p.y);
            SplitPack sp = split8(t0, t1);
            *(uint4*)&d_Ah[ao + j0] = sp.hi;
            *(uint4*)&d_Al[ao + j0] = sp.lo;
        }
        return;
    }

    // mode 0: standard epilogue
    float cs[4][2], cq[4][2];
#pragma unroll
    for (int ni = 0; ni < 4; ni++) { cs[ni][0]=cs[ni][1]=cq[ni][0]=cq[ni][1]=0.f; }

#pragma unroll
    for (int mi = 0; mi < 4; mi++) {
        int r = row0 + wm*64 + mi*16 + g4;
#pragma unroll
        for (int ni = 0; ni < 4; ni++) {
            int c = n0 + wn*32 + ni*8 + t4*2;
            float b0 = 0.f, b1 = 0.f;
            if (bias) { b0 = bias[c]; b1 = bias[c+1]; }
            float v0 = acc[mi][ni][0] + b0, v1 = acc[mi][ni][1] + b1;
            float v2 = acc[mi][ni][2] + b0, v3 = acc[mi][ni][3] + b1;
            *(float2*)&out[(size_t)r * ldout + c]     = make_float2(v0, v1);
            *(float2*)&out[(size_t)(r+8) * ldout + c] = make_float2(v2, v3);
            if (asplit_off >= 0) {
                uint32_t hi, lo;
                split2w(v0, v1, hi, lo);
                *(uint32_t*)&d_Ah[(size_t)r * 768 + asplit_off + c] = hi;
                *(uint32_t*)&d_Al[(size_t)r * 768 + asplit_off + c] = lo;
                split2w(v2, v3, hi, lo);
                *(uint32_t*)&d_Ah[(size_t)(r+8) * 768 + asplit_off + c] = hi;
                *(uint32_t*)&d_Al[(size_t)(r+8) * 768 + asplit_off + c] = lo;
            }
            cs[ni][0] += v0 + v2;  cq[ni][0] += v0*v0 + v2*v2;
            cs[ni][1] += v1 + v3;  cq[ni][1] += v1*v1 + v3*v3;
        }
    }
    if (stats) {
#pragma unroll
        for (int ni = 0; ni < 4; ni++) {
#pragma unroll
            for (int h = 0; h < 2; h++) {
                float s = cs[ni][h], q = cq[ni][h];
                s += __shfl_xor_sync(0xFFFFFFFFu, s, 4);
                q += __shfl_xor_sync(0xFFFFFFFFu, q, 4);
                s += __shfl_xor_sync(0xFFFFFFFFu, s, 8);
                q += __shfl_xor_sync(0xFFFFFFFFu, q, 8);
                s += __shfl_xor_sync(0xFFFFFFFFu, s, 16);
                q += __shfl_xor_sync(0xFFFFFFFFu, q, 16);
                if (g4 == 0) {
                    int c = n0 + wn*32 + ni*8 + t4*2 + h;
                    atomicAdd(&stats[c], s);
                    atomicAdd(&stats[256 + c], q);
                }
            }
        }
    }
}

// out = bn(h2) + x
__global__ void k_final(const float* __restrict__ x, const float* __restrict__ g,
                        const float* __restrict__ be, float* __restrict__ out) {
    int tid = threadIdx.x;
    __shared__ float sc[256], sh[256];
    {
        float mean = d_stats[1024 + tid] * (1.0f / NN);
        float var  = d_stats[1280 + tid] * (1.0f / NN) - mean * mean;
        float s = rsqrtf(var + BNEPS) * g[tid];
        sc[tid] = s;
        sh[tid] = be[tid] - mean * s;
    }
    __syncthreads();
    size_t i = (size_t)(blockIdx.x * 256 + tid) * 4;
    int c = (int)(i & 255);
    float4 h  = *(float4*)&d_h2[i];
    float4 xv = *(const float4*)&x[i];
    float4 o;
    o.x = h.x * sc[c+0] + sh[c+0] + xv.x;
    o.y = h.y * sc[c+1] + sh[c+1] + xv.y;
    o.z = h.z * sc[c+2] + sh[c+2] + xv.z;
    o.w = h.w * sc[c+3] + sh[c+3] + xv.w;
    *(float4*)&out[i] = o;
}

// ------------------------------- launch --------------------------------------
extern "C" void kernel_launch(void* const* d_in, const int* in_sizes, int n_in,
                              void* d_out, int out_size) {
    const float* x       = (const float*)d_in[0];
    const float* mass    = (const float*)d_in[1];
    const float* evals   = (const float*)d_in[2];
    const float* evecs   = (const float*)d_in[3];
    const int*   gx_rows = (const int*)  d_in[4];
    const int*   gx_cols = (const int*)  d_in[5];
    const float* gx_vals = (const float*)d_in[6];
    const int*   gy_rows = (const int*)  d_in[7];
    const int*   gy_cols = (const int*)  d_in[8];
    const float* gy_vals = (const float*)d_in[9];
    const float* dt      = (const float*)d_in[10];
    const float* A_re    = (const float*)d_in[11];
    const float* A_im    = (const float*)d_in[12];
    const float* W0      = (const float*)d_in[13];
    const float* b0      = (const float*)d_in[14];
    const float* g0      = (const float*)d_in[15];
    const float* be0     = (const float*)d_in[16];
    const float* W1      = (const float*)d_in[17];
    const float* b1      = (const float*)d_in[18];
    const float* g1      = (const float*)d_in[19];
    const float* be1     = (const float*)d_in[20];
    const float* W2      = (const float*)d_in[21];
    const float* b2      = (const float*)d_in[22];
    const float* g2      = (const float*)d_in[23];
    const float* be2     = (const float*)d_in[24];
    float* out = (float*)d_out;

    static int smem_set = 0;
    if (!smem_set) {
        cudaFuncSetAttribute(k_mma_gemm, cudaFuncAttributeMaxDynamicSharedMemorySize, GEMM_SMEM2);
        cudaFuncSetAttribute(k_xspec_mma, cudaFuncAttributeMaxDynamicSharedMemorySize, GEMM_SMEM);
        smem_set = 1;
    }

    __nv_bfloat16 *Ah, *Al, *Gh, *Gl, *Bh, *Bl, *eH, *eL, *ytH, *ytL;
    float *h0, *h1, *h2, *stats, *xd;
    cudaGetSymbolAddress((void**)&Ah, d_Ah);
    cudaGetSymbolAddress((void**)&Al, d_Al);
    cudaGetSymbolAddress((void**)&Gh, d_Gh);
    cudaGetSymbolAddress((void**)&Gl, d_Gl);
    cudaGetSymbolAddress((void**)&Bh, d_Bh);
    cudaGetSymbolAddress((void**)&Bl, d_Bl);
    cudaGetSymbolAddress((void**)&eH, d_eH);
    cudaGetSymbolAddress((void**)&eL, d_eL);
    cudaGetSymbolAddress((void**)&ytH, d_ytH);
    cudaGetSymbolAddress((void**)&ytL, d_ytL);
    cudaGetSymbolAddress((void**)&h0, d_h0);
    cudaGetSymbolAddress((void**)&h1, d_h1);
    cudaGetSymbolAddress((void**)&h2, d_h2);
    cudaGetSymbolAddress((void**)&stats, d_stats);
    cudaGetSymbolAddress((void**)&xd, d_xd);

    k_zero<<<256, 256>>>();
    // CSR build
    k_hist<<<4096, 256>>>(gx_rows, gy_rows);
    k_scan1<<<512, 256>>>();
    k_scan2<<<1, 512>>>();
    k_scan3<<<512, 256>>>();
    k_scatter<<<4096, 256>>>(gx_rows, gy_rows);
    // spectral operand prep
    k_trans_mevecs<<<dim3(256, 4, 8), 256>>>(evecs, mass);
    k_trans_x<<<dim3(256, 8, 8), 256>>>(x);
    k_xspec_mma<<<dim3(32, 2, 8), 256, GEMM_SMEM>>>();
    k_coefT<<<256, 256>>>(evals, dt);
    // x_diffuse = evecs @ yT^T  (per-batch B); also split into A cols [256..512)
    k_mma_gemm<<<dim3(2, 512), 256, GEMM_SMEM2>>>(eH, eL, NK, ytH, ytL,
                                                  xd, 256, nullptr, NK, nullptr, NC*NK, 0, 256);
    // sparse gradients: float gX/gY + split into G operand
    k_spmm_csr<<<32768, 256>>>(gx_cols, gx_vals, gy_cols, gy_vals);

    // weight prep
    k_prep_cplxB<<<1024, 256>>>(A_re, A_im);
    k_prep_wT<<<768, 256>>>(W0, 768, 256, BOFF_W0);
    k_prep_wT<<<256, 256>>>(W1, 256, 256, BOFF_W1);
    k_prep_wT<<<256, 256>>>(W2, 256, 256, BOFF_W2);

    // cplx GEMM with fused tanh epilogue -> A cols [512..768)
    k_mma_gemm<<<dim3(4, 512), 256, GEMM_SMEM2>>>(Gh, Gl, 512, Bh + BOFF_CPLX, Bl + BOFF_CPLX,
                                                  h0, 512, nullptr, 512, nullptr, 0, 2, -1);

    // MLP (stats fused into epilogues)
    k_mma_gemm<<<dim3(2, 512), 256, GEMM_SMEM2>>>(Ah, Al, 768, Bh + BOFF_W0, Bl + BOFF_W0,
                                                  h0, 256, b0, 768, stats, 0, 0, -1);
    k_bnsplit<<<8192, 256>>>(h0, 0, g0, be0);
    k_mma_gemm<<<dim3(2, 512), 256, GEMM_SMEM2>>>(Ah, Al, 768, Bh + BOFF_W1, Bl + BOFF_W1,
                                                  h1, 256, b1, 256, stats + 512, 0, 0, -1);
    k_bnsplit<<<8192, 256>>>(h1, 512, g1, be1);
    k_mma_gemm<<<dim3(2, 512), 256, GEMM_SMEM2>>>(Ah, Al, 768, Bh + BOFF_W2, Bl + BOFF_W2,
                                                  h2, 256, b2, 256, stats + 1024, 0, 0, -1);
    k_final<<<16384, 256>>>(x, g2, be2, out);
}

// round 13
// speedup vs baseline: 1.0274x; 1.0274x over previous
#include <cuda_runtime.h>
#include <cuda_bf16.h>
#include <math.h>
#include <cstdint>

#define NB 8
#define NV 8192
#define NK 128
#define NC 256
#define NN 65536          // NB*NV
#define NNZ 1048576       // 16*NN
#define BNEPS 1e-5f

// ------------------------- scratch (device globals) -------------------------
static __device__ float d_xspec[NB*NK*NC];
static __device__ float d_xd  [NN*NC];
static __device__ float d_gX  [NN*NC];
static __device__ float d_gY  [NN*NC];
static __device__ float d_h0  [NN*NC];
static __device__ float d_h1  [NN*NC];
static __device__ float d_h2  [NN*NC];
static __device__ float d_stats[1536];
// CSR build scratch
static __device__ int d_cnt [131072];
static __device__ int d_off [131072];
static __device__ int d_bsum[512];
static __device__ int d_perm[2*NNZ];
// bf16 split A for MLP: [NN, 768] hi/lo  (cols: x | xd | gf)
static __device__ __nv_bfloat16 d_Ah[(size_t)NN*768];
static __device__ __nv_bfloat16 d_Al[(size_t)NN*768];
// bf16 split [gX|gY] operand for cplx GEMM: [NN, 512]
static __device__ __nv_bfloat16 d_Gh[(size_t)NN*512];
static __device__ __nv_bfloat16 d_Gl[(size_t)NN*512];
// bf16 split B pool: cplx-interleaved(512x512) | W0T(256x768) | W1T | W2T
#define BOFF_CPLX 0
#define BOFF_W0   262144
#define BOFF_W1   458752
#define BOFF_W2   524288
static __device__ __nv_bfloat16 d_Bh[589824];
static __device__ __nv_bfloat16 d_Bl[589824];
// spectral operands (bf16 split)
static __device__ __nv_bfloat16 d_mtH[(size_t)NB*NK*NV];
static __device__ __nv_bfloat16 d_mtL[(size_t)NB*NK*NV];
static __device__ __nv_bfloat16 d_xtH[(size_t)NB*NC*NV];
static __device__ __nv_bfloat16 d_xtL[(size_t)NB*NC*NV];
static __device__ __nv_bfloat16 d_eH[(size_t)NN*NK];
static __device__ __nv_bfloat16 d_eL[(size_t)NN*NK];
static __device__ __nv_bfloat16 d_ytH[NB*NC*NK];
static __device__ __nv_bfloat16 d_ytL[NB*NC*NK];

__device__ __forceinline__ uint32_t smem_u32(const void* p) {
    uint32_t a;
    asm("{ .reg .u64 t; cvta.to.shared.u64 t, %1; cvt.u32.u64 %0, t; }" : "=r"(a) : "l"(p));
    return a;
}

struct SplitPack { uint4 hi, lo; };
__device__ __forceinline__ SplitPack split8(float4 a, float4 b) {
    union { __nv_bfloat16 h[8]; uint4 u; } H;
    union { __nv_bfloat16 h[8]; uint4 u; } L;
    float v[8] = {a.x, a.y, a.z, a.w, b.x, b.y, b.z, b.w};
#pragma unroll
    for (int j = 0; j < 8; j++) {
        __nv_bfloat16 hh = __float2bfloat16(v[j]);
        H.h[j] = hh;
        L.h[j] = __float2bfloat16(v[j] - __bfloat162float(hh));
    }
    SplitPack r; r.hi = H.u; r.lo = L.u; return r;
}
struct SplitPack4 { uint2 hi, lo; };
__device__ __forceinline__ SplitPack4 split4(const float* v) {
    union { __nv_bfloat16 h[4]; uint2 u; } H;
    union { __nv_bfloat16 h[4]; uint2 u; } L;
#pragma unroll
    for (int j = 0; j < 4; j++) {
        __nv_bfloat16 hh = __float2bfloat16(v[j]);
        H.h[j] = hh;
        L.h[j] = __float2bfloat16(v[j] - __bfloat162float(hh));
    }
    SplitPack4 r; r.hi = H.u; r.lo = L.u; return r;
}
__device__ __forceinline__ void split2w(float a, float b, uint32_t& hi, uint32_t& lo) {
    __nv_bfloat16 ha = __float2bfloat16(a), hb = __float2bfloat16(b);
    __nv_bfloat16 la = __float2bfloat16(a - __bfloat162float(ha));
    __nv_bfloat16 lb = __float2bfloat16(b - __bfloat162float(hb));
    union { __nv_bfloat16 h[2]; uint32_t u; } H, L;
    H.h[0] = ha; H.h[1] = hb; L.h[0] = la; L.h[1] = lb;
    hi = H.u; lo = L.u;
}
__device__ __forceinline__ void split1(float v, __nv_bfloat16* ph, __nv_bfloat16* pl) {
    __nv_bfloat16 h = __float2bfloat16(v);
    *ph = h;
    *pl = __float2bfloat16(v - __bfloat162float(h));
}

// ------------------------------- zero init ----------------------------------
__global__ void k_zero() {
    int i = blockIdx.x * 256 + threadIdx.x;     // < 65536
    float4 z = make_float4(0.f, 0.f, 0.f, 0.f);
    *(float4*)&d_xspec[i * 4] = z;
    if (i < 32768) *(int4*)&d_cnt[i * 4] = make_int4(0, 0, 0, 0);
    if (i < 384)   *(float4*)&d_stats[i * 4] = z;
}

// ========================= CSR build (both matrices) =========================
__global__ void k_hist(const int* __restrict__ gxr, const int* __restrict__ gyr) {
    int i = blockIdx.x * 256 + threadIdx.x;
    atomicAdd(&d_cnt[gxr[i]], 1);
    atomicAdd(&d_cnt[65536 + gyr[i]], 1);
}

__global__ void k_scan1() {
    __shared__ int sh[256];
    int tid = threadIdx.x;
    int i = blockIdx.x * 256 + tid;
    int v = d_cnt[i];
    sh[tid] = v;
    __syncthreads();
    for (int o = 1; o < 256; o <<= 1) {
        int t = (tid >= o) ? sh[tid - o] : 0;
        __syncthreads();
        sh[tid] += t;
        __syncthreads();
    }
    d_off[i] = sh[tid] - v;
    if (tid == 255) d_bsum[blockIdx.x] = sh[255];
}

__global__ void k_scan2() {
    __shared__ int sh[512];
    int tid = threadIdx.x;
    int v = d_bsum[tid];
    sh[tid] = v;
    __syncthreads();
    for (int o = 1; o < 512; o <<= 1) {
        int t = (tid >= o) ? sh[tid - o] : 0;
        __syncthreads();
        sh[tid] += t;
        __syncthreads();
    }
    d_bsum[tid] = sh[tid] - v;
}

__global__ void k_scan3() {
    int i = blockIdx.x * 256 + threadIdx.x;
    int v = d_off[i] + d_bsum[i >> 8];
    d_off[i] = v;
    d_cnt[i] = v;
}

__global__ void k_scatter(const int* __restrict__ gxr, const int* __restrict__ gyr) {
    int i = blockIdx.x * 256 + threadIdx.x;
    int p = atomicAdd(&d_cnt[gxr[i]], 1);
    d_perm[p] = i;
    int q = atomicAdd(&d_cnt[65536 + gyr[i]], 1);
    d_perm[q] = i;
}

// merged CSR spmm: float out + bf16-split into G operand. grid 32768, 256 thr
__global__ __launch_bounds__(256) void k_spmm_csr(
    const int* __restrict__ gxc, const float* __restrict__ gxv,
    const int* __restrict__ gyc, const float* __restrict__ gyv) {
    int g = threadIdx.x >> 6, t = threadIdx.x & 63;
    int idx = blockIdx.x * 4 + g;               // < 131072
    int isX = (idx < 65536);
    const int*   cols = isX ? gxc : gyc;
    const float* vals = isX ? gxv : gyv;
    float* out        = isX ? d_gX : d_gY;
    int r = idx & 65535;
    int s = d_off[idx], e = d_cnt[idx];
    int c = t * 4;
    float4 acc = make_float4(0.f, 0.f, 0.f, 0.f);
    int p = s;
    for (; p + 4 <= e; p += 4) {
        int e0 = d_perm[p], e1 = d_perm[p+1], e2 = d_perm[p+2], e3 = d_perm[p+3];
        int c0 = cols[e0], c1 = cols[e1], c2 = cols[e2], c3 = cols[e3];
        float v0 = vals[e0], v1 = vals[e1], v2 = vals[e2], v3 = vals[e3];
        float4 x0 = *(const float4*)&d_xd[(size_t)c0 * NC + c];
        float4 x1 = *(const float4*)&d_xd[(size_t)c1 * NC + c];
        float4 x2 = *(const float4*)&d_xd[(size_t)c2 * NC + c];
        float4 x3 = *(const float4*)&d_xd[(size_t)c3 * NC + c];
        acc.x += v0*x0.x + v1*x1.x + v2*x2.x + v3*x3.x;
        acc.y += v0*x0.y + v1*x1.y + v2*x2.y + v3*x3.y;
        acc.z += v0*x0.z + v1*x1.z + v2*x2.z + v3*x3.z;
        acc.w += v0*x0.w + v1*x1.w + v2*x2.w + v3*x3.w;
    }
    for (; p < e; p++) {
        int ed = d_perm[p];
        int cl = cols[ed];
        float v = vals[ed];
        float4 xv = *(const float4*)&d_xd[(size_t)cl * NC + c];
        acc.x += v*xv.x; acc.y += v*xv.y; acc.z += v*xv.z; acc.w += v*xv.w;
    }
    *(float4*)&out[(size_t)r * NC + c] = acc;
    SplitPack4 sp = split4(&acc.x);
    size_t go = (size_t)r * 512 + (isX ? 0 : 256) + c;
    *(uint2*)&d_Gh[go] = sp.hi;
    *(uint2*)&d_Gl[go] = sp.lo;
}

// ===================== spectral operand preparation ==========================
__global__ __launch_bounds__(256) void k_trans_mevecs(
    const float* __restrict__ evecs, const float* __restrict__ mass) {
    __shared__ float tile[32][33];
    __shared__ float smass[32];
    int v0 = blockIdx.x * 32, k0 = blockIdx.y * 32, b = blockIdx.z;
    int tid = threadIdx.x;
    int tx = tid & 31, ty = tid >> 5;
    if (tid < 32) smass[tid] = mass[b * NV + v0 + tid];
#pragma unroll
    for (int i = 0; i < 4; i++) {
        int vl = ty + i * 8;
        tile[vl][tx] = evecs[(size_t)(b * NV + v0 + vl) * NK + k0 + tx];
    }
    __syncthreads();
    {
        int k = tid >> 3, vq = (tid & 7) * 4;
        float v[4];
#pragma unroll
        for (int j = 0; j < 4; j++) v[j] = tile[vq + j][k] * smass[vq + j];
        SplitPack4 p = split4(v);
        size_t o = (size_t)(b * NK + k0 + k) * NV + v0 + vq;
        *(uint2*)&d_mtH[o] = p.hi;
        *(uint2*)&d_mtL[o] = p.lo;
    }
    {
        int v = tid >> 3, kq = (tid & 7) * 4;
        float w[4];
#pragma unroll
        for (int j = 0; j < 4; j++) w[j] = tile[v][kq + j];
        SplitPack4 p = split4(w);
        size_t o = (size_t)(b * NV + v0 + v) * NK + k0 + kq;
        *(uint2*)&d_eH[o] = p.hi;
        *(uint2*)&d_eL[o] = p.lo;
    }
}

// x^T + x-split into A cols [0..256). grid (256, 8, 8)
__global__ __launch_bounds__(256) void k_trans_x(const float* __restrict__ x) {
    __shared__ float tile[32][33];
    int v0 = blockIdx.x * 32, c0 = blockIdx.y * 32, b = blockIdx.z;
    int tid = threadIdx.x;
    int tx = tid & 31, ty = tid >> 5;
#pragma unroll
    for (int i = 0; i < 4; i++) {
        int vl = ty + i * 8;
        tile[vl][tx] = x[(size_t)(b * NV + v0 + vl) * NC + c0 + tx];
    }
    __syncthreads();
    {
        int c = tid >> 3, vq = (tid & 7) * 4;
        float v[4];
#pragma unroll
        for (int j = 0; j < 4; j++) v[j] = tile[vq + j][c];
        SplitPack4 p = split4(v);
        size_t o = (size_t)(b * NC + c0 + c) * NV + v0 + vq;
        *(uint2*)&d_xtH[o] = p.hi;
        *(uint2*)&d_xtL[o] = p.lo;
    }
    {
        int v = tid >> 3, cq = (tid & 7) * 4;
        float w[4];
#pragma unroll
        for (int j = 0; j < 4; j++) w[j] = tile[v][cq + j];
        SplitPack4 p = split4(w);
        size_t o = (size_t)(b * NV + v0 + v) * 768 + c0 + cq;
        *(uint2*)&d_Ah[o] = p.hi;
        *(uint2*)&d_Al[o] = p.lo;
    }
}

__global__ void k_coefT(const float* __restrict__ evals, const float* __restrict__ dt) {
    int i = blockIdx.x * 256 + threadIdx.x;   // < 65536
    int kq = (i & 31) * 4;
    int c  = (i >> 5) & 255;
    int b  = i >> 13;
    float t = fmaxf(dt[c], 1e-8f);
    float v[4];
#pragma unroll
    for (int j = 0; j < 4; j++)
        v[j] = expf(-evals[b * NK + kq + j] * t) * d_xspec[(b * NK + kq + j) * NC + c];
    SplitPack4 p = split4(v);
    int o = b * (NC * NK) + c * NK + kq;
    *(uint2*)&d_ytH[o] = p.hi;
    *(uint2*)&d_ytL[o] = p.lo;
}

// ============================ mma primitives =================================
__device__ __forceinline__ void ldsm_x4(uint32_t* r, uint32_t addr) {
    asm volatile("ldmatrix.sync.aligned.m8n8.x4.shared.b16 {%0,%1,%2,%3}, [%4];"
                 : "=r"(r[0]), "=r"(r[1]), "=r"(r[2]), "=r"(r[3]) : "r"(addr));
}
__device__ __forceinline__ void ldsm_x2(uint32_t* r, uint32_t addr) {
    asm volatile("ldmatrix.sync.aligned.m8n8.x2.shared.b16 {%0,%1}, [%2];"
                 : "=r"(r[0]), "=r"(r[1]) : "r"(addr));
}
__device__ __forceinline__ void mma16816(float* c, const uint32_t* a, const uint32_t* b) {
    asm volatile("mma.sync.aligned.m16n8k16.row.col.f32.bf16.bf16.f32 "
                 "{%0,%1,%2,%3}, {%4,%5,%6,%7}, {%8,%9}, {%0,%1,%2,%3};"
                 : "+f"(c[0]), "+f"(c[1]), "+f"(c[2]), "+f"(c[3])
                 : "r"(a[0]), "r"(a[1]), "r"(a[2]), "r"(a[3]), "r"(b[0]), "r"(b[1]));
}
#define CP_ASYNC(sm, gm) \
    asm volatile("cp.async.cg.shared.global [%0], [%1], 16;" :: "r"(sm), "l"(gm))
#define CP_ASYNC_CA(sm, gm) \
    asm volatile("cp.async.ca.shared.global [%0], [%1], 16;" :: "r"(sm), "l"(gm))
#define CP_COMMIT() asm volatile("cp.async.commit_group;" ::: "memory")
#define CP_WAIT(n)  asm volatile("cp.async.wait_group %0;" :: "n"(n) : "memory")

#define ASTR 40
#define TILEEL (128*ASTR)
#define GEMM_SMEM (2*4*TILEEL*2)   // 81920

#define MMA_BLOCK() do { \
    _Pragma("unroll") \
    for (int mi = 0; mi < 4; mi++) \
        _Pragma("unroll") \
        for (int ni = 0; ni < 4; ni++) \
            mma16816(acc[mi][ni], aH[mi], bH[ni]); \
    _Pragma("unroll") \
    for (int mi = 0; mi < 4; mi++) \
        _Pragma("unroll") \
        for (int ni = 0; ni < 4; ni++) \
            mma16816(acc[mi][ni], aH[mi], bL[ni]); \
    _Pragma("unroll") \
    for (int mi = 0; mi < 4; mi++) \
        _Pragma("unroll") \
        for (int ni = 0; ni < 4; ni++) \
            mma16816(acc[mi][ni], aL[mi], bH[ni]); \
} while (0)

// ------------------- x_spec split-K mma: grid (32, 2, 8) ---------------------
__global__ __launch_bounds__(256, 2) void k_xspec_mma() {
    extern __shared__ __align__(16) __nv_bfloat16 sm[];
    int tid = threadIdx.x;
    int wid = tid >> 5, lane = tid & 31;
    int wm = wid & 1, wn = wid >> 1;
    int kb = blockIdx.x, ch = blockIdx.y, b = blockIdx.z;
    const __nv_bfloat16* Ah = d_mtH + (size_t)b * NK * NV;
    const __nv_bfloat16* Al = d_mtL + (size_t)b * NK * NV;
    const __nv_bfloat16* Bh = d_xtH + (size_t)(b * NC + ch * 128) * NV;
    const __nv_bfloat16* Bl = d_xtL + (size_t)(b * NC + ch * 128) * NV;
    int kbase = kb * 256;

    float acc[4][4][4];
#pragma unroll
    for (int mi = 0; mi < 4; mi++)
#pragma unroll
        for (int ni = 0; ni < 4; ni++)
#pragma unroll
            for (int q = 0; q < 4; q++) acc[mi][ni][q] = 0.f;

    int idx0 = tid * 2, idx1 = tid * 2 + 1;
    int lr0 = idx0 >> 2, ls0 = idx0 & 3;
    int lr1 = idx1 >> 2, ls1 = idx1 & 3;
    uint32_t so0 = (uint32_t)(lr0 * ASTR + ls0 * 8) * 2;
    uint32_t so1 = (uint32_t)(lr1 * ASTR + ls1 * 8) * 2;
    uint32_t smbase = smem_u32(sm);

#define XLOAD(s) do { \
    uint32_t sb = smbase + (uint32_t)((s) & 1) * 4u * TILEEL * 2u; \
    int k0 = kbase + ((s) << 5); \
    CP_ASYNC(sb + so0, Ah + (size_t)lr0 * NV + k0 + ls0*8); \
    CP_ASYNC(sb + so1, Ah + (size_t)lr1 * NV + k0 + ls1*8); \
    CP_ASYNC(sb + TILEEL*2 + so0, Al + (size_t)lr0 * NV + k0 + ls0*8); \
    CP_ASYNC(sb + TILEEL*2 + so1, Al + (size_t)lr1 * NV + k0 + ls1*8); \
    CP_ASYNC(sb + 2*TILEEL*2 + so0, Bh + (size_t)lr0 * NV + k0 + ls0*8); \
    CP_ASYNC(sb + 2*TILEEL*2 + so1, Bh + (size_t)lr1 * NV + k0 + ls1*8); \
    CP_ASYNC(sb + 3*TILEEL*2 + so0, Bl + (size_t)lr0 * NV + k0 + ls0*8); \
    CP_ASYNC(sb + 3*TILEEL*2 + so1, Bl + (size_t)lr1 * NV + k0 + ls1*8); \
} while (0)

    XLOAD(0);
    CP_COMMIT();

    int arow = (lane & 15), acol = (lane >> 4) * 8;
    int brow = (lane & 7),  bcol = ((lane >> 3) & 1) * 8;

    for (int s = 0; s < 8; s++) {
        if (s + 1 < 8) { XLOAD(s + 1); CP_COMMIT(); CP_WAIT(1); }
        else           { CP_WAIT(0); }
        __syncthreads();
        uint32_t sb = smbase + (uint32_t)(s & 1) * 4u * TILEEL * 2u;
        uint32_t Ah_s = sb, Al_s = sb + TILEEL*2, Bh_s = sb + 2*TILEEL*2, Bl_s = sb + 3*TILEEL*2;
#pragma unroll
        for (int ks = 0; ks < 2; ks++) {
            int k0 = ks * 16;
            uint32_t aH[4][4], aL[4][4];
#pragma unroll
            for (int mi = 0; mi < 4; mi++) {
                uint32_t off = (uint32_t)((wm*64 + mi*16 + arow) * ASTR + k0 + acol) * 2;
                ldsm_x4(aH[mi], Ah_s + off);
                ldsm_x4(aL[mi], Al_s + off);
            }
            uint32_t bH[4][2], bL[4][2];
#pragma unroll
            for (int ni = 0; ni < 4; ni++) {
                uint32_t off = (uint32_t)((wn*32 + ni*8 + brow) * ASTR + k0 + bcol) * 2;
                ldsm_x2(bH[ni], Bh_s + off);
                ldsm_x2(bL[ni], Bl_s + off);
            }
            MMA_BLOCK();
        }
        __syncthreads();
    }

    int g4 = lane >> 2, t4 = lane & 3;
#pragma unroll
    for (int mi = 0; mi < 4; mi++) {
        int r = wm*64 + mi*16 + g4;
#pragma unroll
        for (int ni = 0; ni < 4; ni++) {
            int c = ch*128 + wn*32 + ni*8 + t4*2;
            float* o0 = &d_xspec[(b*NK + r) * NC + c];
            float* o1 = &d_xspec[(b*NK + r + 8) * NC + c];
            asm volatile("red.global.add.v2.f32 [%0], {%1,%2};"
                         :: "l"(o0), "f"(acc[mi][ni][0]), "f"(acc[mi][ni][1]) : "memory");
            asm volatile("red.global.add.v2.f32 [%0], {%1,%2};"
                         :: "l"(o1), "f"(acc[mi][ni][2]), "f"(acc[mi][ni][3]) : "memory");
        }
    }
}

// ========================== B-operand prep (bf16 split) ======================
__global__ void k_prep_cplxB(const float* __restrict__ Are, const float* __restrict__ Aim) {
    int i = blockIdx.x * 256 + threadIdx.x;   // < 262144
    int n = i >> 9, k = i & 511;
    int m = n >> 1;
    float v;
    if ((n & 1) == 0) v = (k < 256) ? Are[m*256 + k] : -Aim[m*256 + (k-256)];
    else              v = (k < 256) ? Aim[m*256 + k] :  Are[m*256 + (k-256)];
    split1(v, &d_Bh[BOFF_CPLX + i], &d_Bl[BOFF_CPLX + i]);
}

__global__ void k_prep_wT(const float* __restrict__ W, int K, int N, int off) {
    int i = blockIdx.x * 256 + threadIdx.x;
    if (i >= N * K) return;
    int n = i / K, k = i % K;
    split1(W[k*N + n], &d_Bh[off + i], &d_Bl[off + i]);
}

// relu(bn(h)) -> A cols [0..255]. grid 8192, 256 thr
__global__ void k_bnsplit(const float* __restrict__ h, int statoff,
                          const float* __restrict__ g, const float* __restrict__ be) {
    int tid = threadIdx.x;
    __shared__ float sc[256], sh[256];
    {
        float mean = d_stats[statoff + tid] * (1.0f / NN);
        float var  = d_stats[statoff + 256 + tid] * (1.0f / NN) - mean * mean;
        float s = rsqrtf(var + BNEPS) * g[tid];
        sc[tid] = s;
        sh[tid] = be[tid] - mean * s;
    }
    __syncthreads();
    int idx = blockIdx.x * 256 + tid;          // < 2097152
    size_t row = idx >> 5;
    int c = (idx & 31) * 8;
    size_t o = row * 256 + c;
    float4 h0 = *(const float4*)&h[o], h1 = *(const float4*)&h[o + 4];
    float4 v0, v1;
    v0.x = fmaxf(h0.x * sc[c+0] + sh[c+0], 0.f);
    v0.y = fmaxf(h0.y * sc[c+1] + sh[c+1], 0.f);
    v0.z = fmaxf(h0.z * sc[c+2] + sh[c+2], 0.f);
    v0.w = fmaxf(h0.w * sc[c+3] + sh[c+3], 0.f);
    v1.x = fmaxf(h1.x * sc[c+4] + sh[c+4], 0.f);
    v1.y = fmaxf(h1.y * sc[c+5] + sh[c+5], 0.f);
    v1.z = fmaxf(h1.z * sc[c+6] + sh[c+6], 0.f);
    v1.w = fmaxf(h1.w * sc[c+7] + sh[c+7], 0.f);
    SplitPack p = split8(v0, v1);
    size_t base = row * 768;
    *(uint4*)&d_Ah[base + c] = p.hi;
    *(uint4*)&d_Al[base + c] = p.lo;
}

// ========================= generic mma.sync bf16-split GEMM ==================
// 2-deep double buffer (R11); B loads via cp.async.ca (L1-cached, reused cross-CTA).
__global__ __launch_bounds__(256, 2) void k_mma_gemm(
    const __nv_bfloat16* __restrict__ Ah, const __nv_bfloat16* __restrict__ Al, int ldA,
    const __nv_bfloat16* __restrict__ Bh, const __nv_bfloat16* __restrict__ Bl,
    float* __restrict__ out, int ldout, const float* __restrict__ bias, int K,
    float* __restrict__ stats, int bstrideB, int mode, int asplit_off)
{
    extern __shared__ __align__(16) __nv_bfloat16 sm[];
    int tid = threadIdx.x;
    int wid = tid >> 5, lane = tid & 31;
    int wm = wid & 1, wn = wid >> 1;
    int row0 = blockIdx.y * 128, n0 = blockIdx.x * 128;
    if (bstrideB) {
        int b = row0 / NV;
        Bh += (size_t)b * bstrideB;
        Bl += (size_t)b * bstrideB;
    }

    float acc[4][4][4];
#pragma unroll
    for (int mi = 0; mi < 4; mi++)
#pragma unroll
        for (int ni = 0; ni < 4; ni++)
#pragma unroll
            for (int q = 0; q < 4; q++) acc[mi][ni][q] = 0.f;

    int idx0 = tid * 2, idx1 = tid * 2 + 1;
    int lr0 = idx0 >> 2, ls0 = idx0 & 3;
    int lr1 = idx1 >> 2, ls1 = idx1 & 3;
    uint32_t so0 = (uint32_t)(lr0 * ASTR + ls0 * 8) * 2;
    uint32_t so1 = (uint32_t)(lr1 * ASTR + ls1 * 8) * 2;
    uint32_t smbase = smem_u32(sm);

    const int S = K >> 5;

#define LOADSTAGE(s) do { \
    int buf = (s) & 1; \
    uint32_t sb = smbase + (uint32_t)buf * 4u * TILEEL * 2u; \
    int k0 = (s) << 5; \
    CP_ASYNC(sb + so0, Ah + (size_t)(row0 + lr0) * ldA + k0 + ls0*8); \
    CP_ASYNC(sb + so1, Ah + (size_t)(row0 + lr1) * ldA + k0 + ls1*8); \
    CP_ASYNC(sb + TILEEL*2 + so0, Al + (size_t)(row0 + lr0) * ldA + k0 + ls0*8); \
    CP_ASYNC(sb + TILEEL*2 + so1, Al + (size_t)(row0 + lr1) * ldA + k0 + ls1*8); \
    CP_ASYNC_CA(sb + 2*TILEEL*2 + so0, Bh + (size_t)(n0 + lr0) * K + k0 + ls0*8); \
    CP_ASYNC_CA(sb + 2*TILEEL*2 + so1, Bh + (size_t)(n0 + lr1) * K + k0 + ls1*8); \
    CP_ASYNC_CA(sb + 3*TILEEL*2 + so0, Bl + (size_t)(n0 + lr0) * K + k0 + ls0*8); \
    CP_ASYNC_CA(sb + 3*TILEEL*2 + so1, Bl + (size_t)(n0 + lr1) * K + k0 + ls1*8); \
} while (0)

    LOADSTAGE(0);
    CP_COMMIT();

    int arow = (lane & 15), acol = (lane >> 4) * 8;
    int brow = (lane & 7),  bcol = ((lane >> 3) & 1) * 8;

    for (int s = 0; s < S; s++) {
        if (s + 1 < S) { LOADSTAGE(s + 1); CP_COMMIT(); CP_WAIT(1); }
        else           { CP_WAIT(0); }
        __syncthreads();

        uint32_t sb = smbase + (uint32_t)(s & 1) * 4u * TILEEL * 2u;
        uint32_t Ah_s = sb, Al_s = sb + TILEEL*2, Bh_s = sb + 2*TILEEL*2, Bl_s = sb + 3*TILEEL*2;

#pragma unroll
        for (int ks = 0; ks < 2; ks++) {
            int k0 = ks * 16;
            uint32_t aH[4][4], aL[4][4];
#pragma unroll
            for (int mi = 0; mi < 4; mi++) {
                uint32_t off = (uint32_t)((wm*64 + mi*16 + arow) * ASTR + k0 + acol) * 2;
                ldsm_x4(aH[mi], Ah_s + off);
                ldsm_x4(aL[mi], Al_s + off);
            }
            uint32_t bH[4][2], bL[4][2];
#pragma unroll
            for (int ni = 0; ni < 4; ni++) {
                uint32_t off = (uint32_t)((wn*32 + ni*8 + brow) * ASTR + k0 + bcol) * 2;
                ldsm_x2(bH[ni], Bh_s + off);
                ldsm_x2(bL[ni], Bl_s + off);
            }
            MMA_BLOCK();
        }
        __syncthreads();
    }

    int g4 = lane >> 2, t4 = lane & 3;

    if (mode == 2) {
        // stage (re,im) pairs in smem: [128 rows][64 channels] float2 = 64KB
        float2* sgf = (float2*)sm;
#pragma unroll
        for (int mi = 0; mi < 4; mi++) {
            int rl = wm*64 + mi*16 + g4;
#pragma unroll
            for (int ni = 0; ni < 4; ni++) {
                int chl = wn*16 + ni*4 + t4;
                sgf[rl*64 + chl]       = make_float2(acc[mi][ni][0], acc[mi][ni][1]);
                sgf[(rl+8)*64 + chl]   = make_float2(acc[mi][ni][2], acc[mi][ni][3]);
            }
        }
        __syncthreads();
        int rl = tid >> 1;
        int co = (tid & 1) * 32;
        int r = row0 + rl;
        int chbase = (n0 >> 1) + co;
        const float* gxp = &d_gX[(size_t)r * NC + chbase];
        const float* gyp = &d_gY[(size_t)r * NC + chbase];
        size_t ao = (size_t)r * 768 + 512 + chbase;
#pragma unroll
        for (int j0 = 0; j0 < 32; j0 += 8) {
            float4 gx0 = *(const float4*)(gxp + j0);
            float4 gx1 = *(const float4*)(gxp + j0 + 4);
            float4 gy0 = *(const float4*)(gyp + j0);
            float4 gy1 = *(const float4*)(gyp + j0 + 4);
            float4 t0, t1;
            float2 p;
            p = sgf[rl*64 + co + j0 + 0]; t0.x = tanhf(gx0.x*p.x + gy0.x*p.y);
            p = sgf[rl*64 + co + j0 + 1]; t0.y = tanhf(gx0.y*p.x + gy0.y*p.y);
            p = sgf[rl*64 + co + j0 + 2]; t0.z = tanhf(gx0.z*p.x + gy0.z*p.y);
            p = sgf[rl*64 + co + j0 + 3]; t0.w = tanhf(gx0.w*p.x + gy0.w*p.y);
            p = sgf[rl*64 + co + j0 + 4]; t1.x = tanhf(gx1.x*p.x + gy1.x*p.y);
            p = sgf[rl*64 + co + j0 + 5]; t1.y = tanhf(gx1.y*p.x + gy1.y*p.y);
            p = sgf[rl*64 + co + j0 + 6]; t1.z = tanhf(gx1.z*p.x + gy1.z*p.y);
            p = sgf[rl*64 + co + j0 + 7]; t1.w = tanhf(gx1.w*p.x + gy1.w*p.y);
            SplitPack sp = split8(t0, t1);
            *(uint4*)&d_Ah[ao + j0] = sp.hi;
            *(uint4*)&d_Al[ao + j0] = sp.lo;
        }
        return;
    }

    // mode 0: standard epilogue
    float cs[4][2], cq[4][2];
#pragma unroll
    for (int ni = 0; ni < 4; ni++) { cs[ni][0]=cs[ni][1]=cq[ni][0]=cq[ni][1]=0.f; }

#pragma unroll
    for (int mi = 0; mi < 4; mi++) {
        int r = row0 + wm*64 + mi*16 + g4;
#pragma unroll
        for (int ni = 0; ni < 4; ni++) {
            int c = n0 + wn*32 + ni*8 + t4*2;
            float b0 = 0.f, b1 = 0.f;
            if (bias) { b0 = bias[c]; b1 = bias[c+1]; }
            float v0 = acc[mi][ni][0] + b0, v1 = acc[mi][ni][1] + b1;
            float v2 = acc[mi][ni][2] + b0, v3 = acc[mi][ni][3] + b1;
            *(float2*)&out[(size_t)r * ldout + c]     = make_float2(v0, v1);
            *(float2*)&out[(size_t)(r+8) * ldout + c] = make_float2(v2, v3);
            if (asplit_off >= 0) {
                uint32_t hi, lo;
                split2w(v0, v1, hi, lo);
                *(uint32_t*)&d_Ah[(size_t)r * 768 + asplit_off + c] = hi;
                *(uint32_t*)&d_Al[(size_t)r * 768 + asplit_off + c] = lo;
                split2w(v2, v3, hi, lo);
                *(uint32_t*)&d_Ah[(size_t)(r+8) * 768 + asplit_off + c] = hi;
                *(uint32_t*)&d_Al[(size_t)(r+8) * 768 + asplit_off + c] = lo;
            }
            cs[ni][0] += v0 + v2;  cq[ni][0] += v0*v0 + v2*v2;
            cs[ni][1] += v1 + v3;  cq[ni][1] += v1*v1 + v3*v3;
        }
    }
    if (stats) {
#pragma unroll
        for (int ni = 0; ni < 4; ni++) {
#pragma unroll
            for (int h = 0; h < 2; h++) {
                float s = cs[ni][h], q = cq[ni][h];
                s += __shfl_xor_sync(0xFFFFFFFFu, s, 4);
                q += __shfl_xor_sync(0xFFFFFFFFu, q, 4);
                s += __shfl_xor_sync(0xFFFFFFFFu, s, 8);
                q += __shfl_xor_sync(0xFFFFFFFFu, q, 8);
                s += __shfl_xor_sync(0xFFFFFFFFu, s, 16);
                q += __shfl_xor_sync(0xFFFFFFFFu, q, 16);
                if (g4 == 0) {
                    int c = n0 + wn*32 + ni*8 + t4*2 + h;
                    atomicAdd(&stats[c], s);
                    atomicAdd(&stats[256 + c], q);
                }
            }
        }
    }
}

// out = bn(h2) + x
__global__ void k_final(const float* __restrict__ x, const float* __restrict__ g,
                        const float* __restrict__ be, float* __restrict__ out) {
    int tid = threadIdx.x;
    __shared__ float sc[256], sh[256];
    {
        float mean = d_stats[1024 + tid] * (1.0f / NN);
        float var  = d_stats[1280 + tid] * (1.0f / NN) - mean * mean;
        float s = rsqrtf(var + BNEPS) * g[tid];
        sc[tid] = s;
        sh[tid] = be[tid] - mean * s;
    }
    __syncthreads();
    size_t i = (size_t)(blockIdx.x * 256 + tid) * 4;
    int c = (int)(i & 255);
    float4 h  = *(float4*)&d_h2[i];
    float4 xv = *(const float4*)&x[i];
    float4 o;
    o.x = h.x * sc[c+0] + sh[c+0] + xv.x;
    o.y = h.y * sc[c+1] + sh[c+1] + xv.y;
    o.z = h.z * sc[c+2] + sh[c+2] + xv.z;
    o.w = h.w * sc[c+3] + sh[c+3] + xv.w;
    *(float4*)&out[i] = o;
}

// ------------------------------- launch --------------------------------------
extern "C" void kernel_launch(void* const* d_in, const int* in_sizes, int n_in,
                              void* d_out, int out_size) {
    const float* x       = (const float*)d_in[0];
    const float* mass    = (const float*)d_in[1];
    const float* evals   = (const float*)d_in[2];
    const float* evecs   = (const float*)d_in[3];
    const int*   gx_rows = (const int*)  d_in[4];
    const int*   gx_cols = (const int*)  d_in[5];
    const float* gx_vals = (const float*)d_in[6];
    const int*   gy_rows = (const int*)  d_in[7];
    const int*   gy_cols = (const int*)  d_in[8];
    const float* gy_vals = (const float*)d_in[9];
    const float* dt      = (const float*)d_in[10];
    const float* A_re    = (const float*)d_in[11];
    const float* A_im    = (const float*)d_in[12];
    const float* W0      = (const float*)d_in[13];
    const float* b0      = (const float*)d_in[14];
    const float* g0      = (const float*)d_in[15];
    const float* be0     = (const float*)d_in[16];
    const float* W1      = (const float*)d_in[17];
    const float* b1      = (const float*)d_in[18];
    const float* g1      = (const float*)d_in[19];
    const float* be1     = (const float*)d_in[20];
    const float* W2      = (const float*)d_in[21];
    const float* b2      = (const float*)d_in[22];
    const float* g2      = (const float*)d_in[23];
    const float* be2     = (const float*)d_in[24];
    float* out = (float*)d_out;

    static int smem_set = 0;
    if (!smem_set) {
        cudaFuncSetAttribute(k_mma_gemm, cudaFuncAttributeMaxDynamicSharedMemorySize, GEMM_SMEM);
        cudaFuncSetAttribute(k_xspec_mma, cudaFuncAttributeMaxDynamicSharedMemorySize, GEMM_SMEM);
        smem_set = 1;
    }

    __nv_bfloat16 *Ah, *Al, *Gh, *Gl, *Bh, *Bl, *eH, *eL, *ytH, *ytL;
    float *h0, *h1, *h2, *stats, *xd;
    cudaGetSymbolAddress((void**)&Ah, d_Ah);
    cudaGetSymbolAddress((void**)&Al, d_Al);
    cudaGetSymbolAddress((void**)&Gh, d_Gh);
    cudaGetSymbolAddress((void**)&Gl, d_Gl);
    cudaGetSymbolAddress((void**)&Bh, d_Bh);
    cudaGetSymbolAddress((void**)&Bl, d_Bl);
    cudaGetSymbolAddress((void**)&eH, d_eH);
    cudaGetSymbolAddress((void**)&eL, d_eL);
    cudaGetSymbolAddress((void**)&ytH, d_ytH);
    cudaGetSymbolAddress((void**)&ytL, d_ytL);
    cudaGetSymbolAddress((void**)&h0, d_h0);
    cudaGetSymbolAddress((void**)&h1, d_h1);
    cudaGetSymbolAddress((void**)&h2, d_h2);
    cudaGetSymbolAddress((void**)&stats, d_stats);
    cudaGetSymbolAddress((void**)&xd, d_xd);

    // launches ordered so ncu (-s 5 -c 1) lands on the xdiff k_mma_gemm (index 5)
    k_zero<<<256, 256>>>();
    k_trans_mevecs<<<dim3(256, 4, 8), 256>>>(evecs, mass);
    k_trans_x<<<dim3(256, 8, 8), 256>>>(x);
    k_xspec_mma<<<dim3(32, 2, 8), 256, GEMM_SMEM>>>();
    k_coefT<<<256, 256>>>(evals, dt);
    // [index 5] x_diffuse = evecs @ yT^T  (per-batch B); also split into A [256..512)
    k_mma_gemm<<<dim3(2, 512), 256, GEMM_SMEM>>>(eH, eL, NK, ytH, ytL,
                                                 xd, 256, nullptr, NK, nullptr, NC*NK, 0, 256);
    // CSR build (independent of spectral chain; needed before spmm)
    k_hist<<<4096, 256>>>(gx_rows, gy_rows);
    k_scan1<<<512, 256>>>();
    k_scan2<<<1, 512>>>();
    k_scan3<<<512, 256>>>();
    k_scatter<<<4096, 256>>>(gx_rows, gy_rows);
    // sparse gradients: float gX/gY + split into G operand
    k_spmm_csr<<<32768, 256>>>(gx_cols, gx_vals, gy_cols, gy_vals);

    // weight prep
    k_prep_cplxB<<<1024, 256>>>(A_re, A_im);
    k_prep_wT<<<768, 256>>>(W0, 768, 256, BOFF_W0);
    k_prep_wT<<<256, 256>>>(W1, 256, 256, BOFF_W1);
    k_prep_wT<<<256, 256>>>(W2, 256, 256, BOFF_W2);

    // cplx GEMM with fused tanh epilogue -> A cols [512..768)
    k_mma_gemm<<<dim3(4, 512), 256, GEMM_SMEM>>>(Gh, Gl, 512, Bh + BOFF_CPLX, Bl + BOFF_CPLX,
                                                 h0, 512, nullptr, 512, nullptr, 0, 2, -1);

    // MLP (stats fused into epilogues)
    k_mma_gemm<<<dim3(2, 512), 256, GEMM_SMEM>>>(Ah, Al, 768, Bh + BOFF_W0, Bl + BOFF_W0,
                                                 h0, 256, b0, 768, stats, 0, 0, -1);
    k_bnsplit<<<8192, 256>>>(h0, 0, g0, be0);
    k_mma_gemm<<<dim3(2, 512), 256, GEMM_SMEM>>>(Ah, Al, 768, Bh + BOFF_W1, Bl + BOFF_W1,
                                                 h1, 256, b1, 256, stats + 512, 0, 0, -1);
    k_bnsplit<<<8192, 256>>>(h1, 512, g1, be1);
    k_mma_gemm<<<dim3(2, 512), 256, GEMM_SMEM>>>(Ah, Al, 768, Bh + BOFF_W2, Bl + BOFF_W2,
                                                 h2, 256, b2, 256, stats + 1024, 0, 0, -1);
    k_final<<<16384, 256>>>(x, g2, be2, out);
}

// round 14
// speedup vs baseline: 1.1118x; 1.0822x over previous
#include <cuda_runtime.h>
#include <cuda_bf16.h>
#include <cuda_fp16.h>
#include <math.h>
#include <cstdint>

#define NB 8
#define NV 8192
#define NK 128
#define NC 256
#define NN 65536          // NB*NV
#define NNZ 1048576       // 16*NN
#define BNEPS 1e-5f

// ------------------------- scratch (device globals) -------------------------
static __device__ float d_xspec[NB*NK*NC];
static __device__ float d_xd  [NN*NC];
static __device__ float d_gX  [NN*NC];
static __device__ float d_gY  [NN*NC];
static __device__ float d_h0  [NN*NC];
static __device__ float d_h1  [NN*NC];
static __device__ float d_h2  [NN*NC];
static __device__ float d_stats[1536];
// CSR build scratch
static __device__ int d_cnt [131072];
static __device__ int d_off [131072];
static __device__ int d_bsum[512];
static __device__ int d_perm[2*NNZ];
// bf16 split A for MLP: [NN, 768] hi/lo  (cols: x | xd | gf)
static __device__ __nv_bfloat16 d_Ah[(size_t)NN*768];
static __device__ __nv_bfloat16 d_Al[(size_t)NN*768];
// fp16 single [gX|gY] operand for cplx GEMM: [NN, 512]
static __device__ __half d_GhF[(size_t)NN*512];
// fp16 split cplx-interleaved B: [512, 512]
static __device__ __half d_BhC[262144];
static __device__ __half d_BlC[262144];
// bf16 split B pool: W0T(256x768) | W1T | W2T
#define BOFF_W0   0
#define BOFF_W1   196608
#define BOFF_W2   262144
static __device__ __nv_bfloat16 d_Bh[327680];
static __device__ __nv_bfloat16 d_Bl[327680];
// spectral operands (bf16 split)
static __device__ __nv_bfloat16 d_mtH[(size_t)NB*NK*NV];
static __device__ __nv_bfloat16 d_mtL[(size_t)NB*NK*NV];
static __device__ __nv_bfloat16 d_xtH[(size_t)NB*NC*NV];
static __device__ __nv_bfloat16 d_xtL[(size_t)NB*NC*NV];
static __device__ __nv_bfloat16 d_eH[(size_t)NN*NK];
static __device__ __nv_bfloat16 d_eL[(size_t)NN*NK];
static __device__ __nv_bfloat16 d_ytH[NB*NC*NK];
static __device__ __nv_bfloat16 d_ytL[NB*NC*NK];

__device__ __forceinline__ uint32_t smem_u32(const void* p) {
    uint32_t a;
    asm("{ .reg .u64 t; cvta.to.shared.u64 t, %1; cvt.u32.u64 %0, t; }" : "=r"(a) : "l"(p));
    return a;
}

struct SplitPack { uint4 hi, lo; };
__device__ __forceinline__ SplitPack split8(float4 a, float4 b) {
    union { __nv_bfloat16 h[8]; uint4 u; } H;
    union { __nv_bfloat16 h[8]; uint4 u; } L;
    float v[8] = {a.x, a.y, a.z, a.w, b.x, b.y, b.z, b.w};
#pragma unroll
    for (int j = 0; j < 8; j++) {
        __nv_bfloat16 hh = __float2bfloat16(v[j]);
        H.h[j] = hh;
        L.h[j] = __float2bfloat16(v[j] - __bfloat162float(hh));
    }
    SplitPack r; r.hi = H.u; r.lo = L.u; return r;
}
struct SplitPack4 { uint2 hi, lo; };
__device__ __forceinline__ SplitPack4 split4(const float* v) {
    union { __nv_bfloat16 h[4]; uint2 u; } H;
    union { __nv_bfloat16 h[4]; uint2 u; } L;
#pragma unroll
    for (int j = 0; j < 4; j++) {
        __nv_bfloat16 hh = __float2bfloat16(v[j]);
        H.h[j] = hh;
        L.h[j] = __float2bfloat16(v[j] - __bfloat162float(hh));
    }
    SplitPack4 r; r.hi = H.u; r.lo = L.u; return r;
}
__device__ __forceinline__ void split2w(float a, float b, uint32_t& hi, uint32_t& lo) {
    __nv_bfloat16 ha = __float2bfloat16(a), hb = __float2bfloat16(b);
    __nv_bfloat16 la = __float2bfloat16(a - __bfloat162float(ha));
    __nv_bfloat16 lb = __float2bfloat16(b - __bfloat162float(hb));
    union { __nv_bfloat16 h[2]; uint32_t u; } H, L;
    H.h[0] = ha; H.h[1] = hb; L.h[0] = la; L.h[1] = lb;
    hi = H.u; lo = L.u;
}
__device__ __forceinline__ void split1(float v, __nv_bfloat16* ph, __nv_bfloat16* pl) {
    __nv_bfloat16 h = __float2bfloat16(v);
    *ph = h;
    *pl = __float2bfloat16(v - __bfloat162float(h));
}

// ------------------------------- zero init ----------------------------------
__global__ void k_zero() {
    int i = blockIdx.x * 256 + threadIdx.x;     // < 65536
    float4 z = make_float4(0.f, 0.f, 0.f, 0.f);
    *(float4*)&d_xspec[i * 4] = z;
    if (i < 32768) *(int4*)&d_cnt[i * 4] = make_int4(0, 0, 0, 0);
    if (i < 384)   *(float4*)&d_stats[i * 4] = z;
}

// ========================= CSR build (both matrices) =========================
__global__ void k_hist(const int* __restrict__ gxr, const int* __restrict__ gyr) {
    int i = blockIdx.x * 256 + threadIdx.x;
    atomicAdd(&d_cnt[gxr[i]], 1);
    atomicAdd(&d_cnt[65536 + gyr[i]], 1);
}

__global__ void k_scan1() {
    __shared__ int sh[256];
    int tid = threadIdx.x;
    int i = blockIdx.x * 256 + tid;
    int v = d_cnt[i];
    sh[tid] = v;
    __syncthreads();
    for (int o = 1; o < 256; o <<= 1) {
        int t = (tid >= o) ? sh[tid - o] : 0;
        __syncthreads();
        sh[tid] += t;
        __syncthreads();
    }
    d_off[i] = sh[tid] - v;
    if (tid == 255) d_bsum[blockIdx.x] = sh[255];
}

__global__ void k_scan2() {
    __shared__ int sh[512];
    int tid = threadIdx.x;
    int v = d_bsum[tid];
    sh[tid] = v;
    __syncthreads();
    for (int o = 1; o < 512; o <<= 1) {
        int t = (tid >= o) ? sh[tid - o] : 0;
        __syncthreads();
        sh[tid] += t;
        __syncthreads();
    }
    d_bsum[tid] = sh[tid] - v;
}

__global__ void k_scan3() {
    int i = blockIdx.x * 256 + threadIdx.x;
    int v = d_off[i] + d_bsum[i >> 8];
    d_off[i] = v;
    d_cnt[i] = v;
}

__global__ void k_scatter(const int* __restrict__ gxr, const int* __restrict__ gyr) {
    int i = blockIdx.x * 256 + threadIdx.x;
    int p = atomicAdd(&d_cnt[gxr[i]], 1);
    d_perm[p] = i;
    int q = atomicAdd(&d_cnt[65536 + gyr[i]], 1);
    d_perm[q] = i;
}

// merged CSR spmm: float out + fp16 into G operand. grid 32768, 256 thr
__global__ __launch_bounds__(256) void k_spmm_csr(
    const int* __restrict__ gxc, const float* __restrict__ gxv,
    const int* __restrict__ gyc, const float* __restrict__ gyv) {
    int g = threadIdx.x >> 6, t = threadIdx.x & 63;
    int idx = blockIdx.x * 4 + g;               // < 131072
    int isX = (idx < 65536);
    const int*   cols = isX ? gxc : gyc;
    const float* vals = isX ? gxv : gyv;
    float* out        = isX ? d_gX : d_gY;
    int r = idx & 65535;
    int s = d_off[idx], e = d_cnt[idx];
    int c = t * 4;
    float4 acc = make_float4(0.f, 0.f, 0.f, 0.f);
    int p = s;
    for (; p + 4 <= e; p += 4) {
        int e0 = d_perm[p], e1 = d_perm[p+1], e2 = d_perm[p+2], e3 = d_perm[p+3];
        int c0 = cols[e0], c1 = cols[e1], c2 = cols[e2], c3 = cols[e3];
        float v0 = vals[e0], v1 = vals[e1], v2 = vals[e2], v3 = vals[e3];
        float4 x0 = *(const float4*)&d_xd[(size_t)c0 * NC + c];
        float4 x1 = *(const float4*)&d_xd[(size_t)c1 * NC + c];
        float4 x2 = *(const float4*)&d_xd[(size_t)c2 * NC + c];
        float4 x3 = *(const float4*)&d_xd[(size_t)c3 * NC + c];
        acc.x += v0*x0.x + v1*x1.x + v2*x2.x + v3*x3.x;
        acc.y += v0*x0.y + v1*x1.y + v2*x2.y + v3*x3.y;
        acc.z += v0*x0.z + v1*x1.z + v2*x2.z + v3*x3.z;
        acc.w += v0*x0.w + v1*x1.w + v2*x2.w + v3*x3.w;
    }
    for (; p < e; p++) {
        int ed = d_perm[p];
        int cl = cols[ed];
        float v = vals[ed];
        float4 xv = *(const float4*)&d_xd[(size_t)cl * NC + c];
        acc.x += v*xv.x; acc.y += v*xv.y; acc.z += v*xv.z; acc.w += v*xv.w;
    }
    *(float4*)&out[(size_t)r * NC + c] = acc;
    union { __half h[4]; uint2 u; } P;
    P.h[0] = __float2half(acc.x);
    P.h[1] = __float2half(acc.y);
    P.h[2] = __float2half(acc.z);
    P.h[3] = __float2half(acc.w);
    *(uint2*)&d_GhF[(size_t)r * 512 + (isX ? 0 : 256) + c] = P.u;
}

// ===================== spectral operand preparation ==========================
__global__ __launch_bounds__(256) void k_trans_mevecs(
    const float* __restrict__ evecs, const float* __restrict__ mass) {
    __shared__ float tile[32][33];
    __shared__ float smass[32];
    int v0 = blockIdx.x * 32, k0 = blockIdx.y * 32, b = blockIdx.z;
    int tid = threadIdx.x;
    int tx = tid & 31, ty = tid >> 5;
    if (tid < 32) smass[tid] = mass[b * NV + v0 + tid];
#pragma unroll
    for (int i = 0; i < 4; i++) {
        int vl = ty + i * 8;
        tile[vl][tx] = evecs[(size_t)(b * NV + v0 + vl) * NK + k0 + tx];
    }
    __syncthreads();
    {
        int k = tid >> 3, vq = (tid & 7) * 4;
        float v[4];
#pragma unroll
        for (int j = 0; j < 4; j++) v[j] = tile[vq + j][k] * smass[vq + j];
        SplitPack4 p = split4(v);
        size_t o = (size_t)(b * NK + k0 + k) * NV + v0 + vq;
        *(uint2*)&d_mtH[o] = p.hi;
        *(uint2*)&d_mtL[o] = p.lo;
    }
    {
        int v = tid >> 3, kq = (tid & 7) * 4;
        float w[4];
#pragma unroll
        for (int j = 0; j < 4; j++) w[j] = tile[v][kq + j];
        SplitPack4 p = split4(w);
        size_t o = (size_t)(b * NV + v0 + v) * NK + k0 + kq;
        *(uint2*)&d_eH[o] = p.hi;
        *(uint2*)&d_eL[o] = p.lo;
    }
}

// x^T + x-split into A cols [0..256). grid (256, 8, 8)
__global__ __launch_bounds__(256) void k_trans_x(const float* __restrict__ x) {
    __shared__ float tile[32][33];
    int v0 = blockIdx.x * 32, c0 = blockIdx.y * 32, b = blockIdx.z;
    int tid = threadIdx.x;
    int tx = tid & 31, ty = tid >> 5;
#pragma unroll
    for (int i = 0; i < 4; i++) {
        int vl = ty + i * 8;
        tile[vl][tx] = x[(size_t)(b * NV + v0 + vl) * NC + c0 + tx];
    }
    __syncthreads();
    {
        int c = tid >> 3, vq = (tid & 7) * 4;
        float v[4];
#pragma unroll
        for (int j = 0; j < 4; j++) v[j] = tile[vq + j][c];
        SplitPack4 p = split4(v);
        size_t o = (size_t)(b * NC + c0 + c) * NV + v0 + vq;
        *(uint2*)&d_xtH[o] = p.hi;
        *(uint2*)&d_xtL[o] = p.lo;
    }
    {
        int v = tid >> 3, cq = (tid & 7) * 4;
        float w[4];
#pragma unroll
        for (int j = 0; j < 4; j++) w[j] = tile[v][cq + j];
        SplitPack4 p = split4(w);
        size_t o = (size_t)(b * NV + v0 + v) * 768 + c0 + cq;
        *(uint2*)&d_Ah[o] = p.hi;
        *(uint2*)&d_Al[o] = p.lo;
    }
}

__global__ void k_coefT(const float* __restrict__ evals, const float* __restrict__ dt) {
    int i = blockIdx.x * 256 + threadIdx.x;   // < 65536
    int kq = (i & 31) * 4;
    int c  = (i >> 5) & 255;
    int b  = i >> 13;
    float t = fmaxf(dt[c], 1e-8f);
    float v[4];
#pragma unroll
    for (int j = 0; j < 4; j++)
        v[j] = expf(-evals[b * NK + kq + j] * t) * d_xspec[(b * NK + kq + j) * NC + c];
    SplitPack4 p = split4(v);
    int o = b * (NC * NK) + c * NK + kq;
    *(uint2*)&d_ytH[o] = p.hi;
    *(uint2*)&d_ytL[o] = p.lo;
}

// ============================ mma primitives =================================
__device__ __forceinline__ void ldsm_x4(uint32_t* r, uint32_t addr) {
    asm volatile("ldmatrix.sync.aligned.m8n8.x4.shared.b16 {%0,%1,%2,%3}, [%4];"
                 : "=r"(r[0]), "=r"(r[1]), "=r"(r[2]), "=r"(r[3]) : "r"(addr));
}
__device__ __forceinline__ void ldsm_x2(uint32_t* r, uint32_t addr) {
    asm volatile("ldmatrix.sync.aligned.m8n8.x2.shared.b16 {%0,%1}, [%2];"
                 : "=r"(r[0]), "=r"(r[1]) : "r"(addr));
}
__device__ __forceinline__ void mma16816(float* c, const uint32_t* a, const uint32_t* b) {
    asm volatile("mma.sync.aligned.m16n8k16.row.col.f32.bf16.bf16.f32 "
                 "{%0,%1,%2,%3}, {%4,%5,%6,%7}, {%8,%9}, {%0,%1,%2,%3};"
                 : "+f"(c[0]), "+f"(c[1]), "+f"(c[2]), "+f"(c[3])
                 : "r"(a[0]), "r"(a[1]), "r"(a[2]), "r"(a[3]), "r"(b[0]), "r"(b[1]));
}
__device__ __forceinline__ void mma16816h(float* c, const uint32_t* a, const uint32_t* b) {
    asm volatile("mma.sync.aligned.m16n8k16.row.col.f32.f16.f16.f32 "
                 "{%0,%1,%2,%3}, {%4,%5,%6,%7}, {%8,%9}, {%0,%1,%2,%3};"
                 : "+f"(c[0]), "+f"(c[1]), "+f"(c[2]), "+f"(c[3])
                 : "r"(a[0]), "r"(a[1]), "r"(a[2]), "r"(a[3]), "r"(b[0]), "r"(b[1]));
}
#define CP_ASYNC(sm, gm) \
    asm volatile("cp.async.cg.shared.global [%0], [%1], 16;" :: "r"(sm), "l"(gm))
#define CP_ASYNC_CA(sm, gm) \
    asm volatile("cp.async.ca.shared.global [%0], [%1], 16;" :: "r"(sm), "l"(gm))
#define CP_COMMIT() asm volatile("cp.async.commit_group;" ::: "memory")
#define CP_WAIT(n)  asm volatile("cp.async.wait_group %0;" :: "n"(n) : "memory")

#define ASTR 40
#define TILEEL (128*ASTR)
#define GEMM_SMEM (2*4*TILEEL*2)   // 81920
#define SLOT3 (TILEEL*2)           // 10240 bytes (one matrix tile)
#define CPLX_SMEM 65536            // max(2*3*SLOT3=61440, gf staging 65536)

#define MMA_BLOCK() do { \
    _Pragma("unroll") \
    for (int mi = 0; mi < 4; mi++) \
        _Pragma("unroll") \
        for (int ni = 0; ni < 4; ni++) \
            mma16816(acc[mi][ni], aH[mi], bH[ni]); \
    _Pragma("unroll") \
    for (int mi = 0; mi < 4; mi++) \
        _Pragma("unroll") \
        for (int ni = 0; ni < 4; ni++) \
            mma16816(acc[mi][ni], aH[mi], bL[ni]); \
    _Pragma("unroll") \
    for (int mi = 0; mi < 4; mi++) \
        _Pragma("unroll") \
        for (int ni = 0; ni < 4; ni++) \
            mma16816(acc[mi][ni], aL[mi], bH[ni]); \
} while (0)

// ------------------- x_spec split-K mma: grid (32, 2, 8) ---------------------
__global__ __launch_bounds__(256, 2) void k_xspec_mma() {
    extern __shared__ __align__(16) __nv_bfloat16 sm[];
    int tid = threadIdx.x;
    int wid = tid >> 5, lane = tid & 31;
    int wm = wid & 1, wn = wid >> 1;
    int kb = blockIdx.x, ch = blockIdx.y, b = blockIdx.z;
    const __nv_bfloat16* Ah = d_mtH + (size_t)b * NK * NV;
    const __nv_bfloat16* Al = d_mtL + (size_t)b * NK * NV;
    const __nv_bfloat16* Bh = d_xtH + (size_t)(b * NC + ch * 128) * NV;
    const __nv_bfloat16* Bl = d_xtL + (size_t)(b * NC + ch * 128) * NV;
    int kbase = kb * 256;

    float acc[4][4][4];
#pragma unroll
    for (int mi = 0; mi < 4; mi++)
#pragma unroll
        for (int ni = 0; ni < 4; ni++)
#pragma unroll
            for (int q = 0; q < 4; q++) acc[mi][ni][q] = 0.f;

    int idx0 = tid * 2, idx1 = tid * 2 + 1;
    int lr0 = idx0 >> 2, ls0 = idx0 & 3;
    int lr1 = idx1 >> 2, ls1 = idx1 & 3;
    uint32_t so0 = (uint32_t)(lr0 * ASTR + ls0 * 8) * 2;
    uint32_t so1 = (uint32_t)(lr1 * ASTR + ls1 * 8) * 2;
    uint32_t smbase = smem_u32(sm);

#define XLOAD(s) do { \
    uint32_t sb = smbase + (uint32_t)((s) & 1) * 4u * TILEEL * 2u; \
    int k0 = kbase + ((s) << 5); \
    CP_ASYNC(sb + so0, Ah + (size_t)lr0 * NV + k0 + ls0*8); \
    CP_ASYNC(sb + so1, Ah + (size_t)lr1 * NV + k0 + ls1*8); \
    CP_ASYNC(sb + TILEEL*2 + so0, Al + (size_t)lr0 * NV + k0 + ls0*8); \
    CP_ASYNC(sb + TILEEL*2 + so1, Al + (size_t)lr1 * NV + k0 + ls1*8); \
    CP_ASYNC(sb + 2*TILEEL*2 + so0, Bh + (size_t)lr0 * NV + k0 + ls0*8); \
    CP_ASYNC(sb + 2*TILEEL*2 + so1, Bh + (size_t)lr1 * NV + k0 + ls1*8); \
    CP_ASYNC(sb + 3*TILEEL*2 + so0, Bl + (size_t)lr0 * NV + k0 + ls0*8); \
    CP_ASYNC(sb + 3*TILEEL*2 + so1, Bl + (size_t)lr1 * NV + k0 + ls1*8); \
} while (0)

    XLOAD(0);
    CP_COMMIT();

    int arow = (lane & 15), acol = (lane >> 4) * 8;
    int brow = (lane & 7),  bcol = ((lane >> 3) & 1) * 8;

    for (int s = 0; s < 8; s++) {
        if (s + 1 < 8) { XLOAD(s + 1); CP_COMMIT(); CP_WAIT(1); }
        else           { CP_WAIT(0); }
        __syncthreads();
        uint32_t sb = smbase + (uint32_t)(s & 1) * 4u * TILEEL * 2u;
        uint32_t Ah_s = sb, Al_s = sb + TILEEL*2, Bh_s = sb + 2*TILEEL*2, Bl_s = sb + 3*TILEEL*2;
#pragma unroll
        for (int ks = 0; ks < 2; ks++) {
            int k0 = ks * 16;
            uint32_t aH[4][4], aL[4][4];
#pragma unroll
            for (int mi = 0; mi < 4; mi++) {
                uint32_t off = (uint32_t)((wm*64 + mi*16 + arow) * ASTR + k0 + acol) * 2;
                ldsm_x4(aH[mi], Ah_s + off);
                ldsm_x4(aL[mi], Al_s + off);
            }
            uint32_t bH[4][2], bL[4][2];
#pragma unroll
            for (int ni = 0; ni < 4; ni++) {
                uint32_t off = (uint32_t)((wn*32 + ni*8 + brow) * ASTR + k0 + bcol) * 2;
                ldsm_x2(bH[ni], Bh_s + off);
                ldsm_x2(bL[ni], Bl_s + off);
            }
            MMA_BLOCK();
        }
        __syncthreads();
    }

    int g4 = lane >> 2, t4 = lane & 3;
#pragma unroll
    for (int mi = 0; mi < 4; mi++) {
        int r = wm*64 + mi*16 + g4;
#pragma unroll
        for (int ni = 0; ni < 4; ni++) {
            int c = ch*128 + wn*32 + ni*8 + t4*2;
            float* o0 = &d_xspec[(b*NK + r) * NC + c];
            float* o1 = &d_xspec[(b*NK + r + 8) * NC + c];
            asm volatile("red.global.add.v2.f32 [%0], {%1,%2};"
                         :: "l"(o0), "f"(acc[mi][ni][0]), "f"(acc[mi][ni][1]) : "memory");
            asm volatile("red.global.add.v2.f32 [%0], {%1,%2};"
                         :: "l"(o1), "f"(acc[mi][ni][2]), "f"(acc[mi][ni][3]) : "memory");
        }
    }
}

// ========================== B-operand prep ==================================
// interleaved cplx B'' (fp16 split): row 2m = [Are[m,:] | -Aim[m,:]], 2m+1 = [Aim | Are]
__global__ void k_prep_cplxB(const float* __restrict__ Are, const float* __restrict__ Aim) {
    int i = blockIdx.x * 256 + threadIdx.x;   // < 262144
    int n = i >> 9, k = i & 511;
    int m = n >> 1;
    float v;
    if ((n & 1) == 0) v = (k < 256) ? Are[m*256 + k] : -Aim[m*256 + (k-256)];
    else              v = (k < 256) ? Aim[m*256 + k] :  Are[m*256 + (k-256)];
    __half h = __float2half(v);
    d_BhC[i] = h;
    d_BlC[i] = __float2half(v - __half2float(h));
}

__global__ void k_prep_wT(const float* __restrict__ W, int K, int N, int off) {
    int i = blockIdx.x * 256 + threadIdx.x;
    if (i >= N * K) return;
    int n = i / K, k = i % K;
    split1(W[k*N + n], &d_Bh[off + i], &d_Bl[off + i]);
}

// relu(bn(h)) -> A cols [0..255]. grid 8192, 256 thr
__global__ void k_bnsplit(const float* __restrict__ h, int statoff,
                          const float* __restrict__ g, const float* __restrict__ be) {
    int tid = threadIdx.x;
    __shared__ float sc[256], sh[256];
    {
        float mean = d_stats[statoff + tid] * (1.0f / NN);
        float var  = d_stats[statoff + 256 + tid] * (1.0f / NN) - mean * mean;
        float s = rsqrtf(var + BNEPS) * g[tid];
        sc[tid] = s;
        sh[tid] = be[tid] - mean * s;
    }
    __syncthreads();
    int idx = blockIdx.x * 256 + tid;          // < 2097152
    size_t row = idx >> 5;
    int c = (idx & 31) * 8;
    size_t o = row * 256 + c;
    float4 h0 = *(const float4*)&h[o], h1 = *(const float4*)&h[o + 4];
    float4 v0, v1;
    v0.x = fmaxf(h0.x * sc[c+0] + sh[c+0], 0.f);
    v0.y = fmaxf(h0.y * sc[c+1] + sh[c+1], 0.f);
    v0.z = fmaxf(h0.z * sc[c+2] + sh[c+2], 0.f);
    v0.w = fmaxf(h0.w * sc[c+3] + sh[c+3], 0.f);
    v1.x = fmaxf(h1.x * sc[c+4] + sh[c+4], 0.f);
    v1.y = fmaxf(h1.y * sc[c+5] + sh[c+5], 0.f);
    v1.z = fmaxf(h1.z * sc[c+6] + sh[c+6], 0.f);
    v1.w = fmaxf(h1.w * sc[c+7] + sh[c+7], 0.f);
    SplitPack p = split8(v0, v1);
    size_t base = row * 768;
    *(uint4*)&d_Ah[base + c] = p.hi;
    *(uint4*)&d_Al[base + c] = p.lo;
}

// ================= cplx GEMM: fp16 2-term, fused tanh epilogue ===============
// A = G (fp16 single, ld 512); B = cplx interleaved fp16 split (K=512).
// grid (4, 512), 256 thr. Writes gf split into A cols [512..768).
__global__ __launch_bounds__(256, 2) void k_mma_cplx() {
    extern __shared__ __align__(16) __half smh[];
    int tid = threadIdx.x;
    int wid = tid >> 5, lane = tid & 31;
    int wm = wid & 1, wn = wid >> 1;
    int row0 = blockIdx.y * 128, n0 = blockIdx.x * 128;
    const int K = 512, S = 16;

    float acc[4][4][4];
#pragma unroll
    for (int mi = 0; mi < 4; mi++)
#pragma unroll
        for (int ni = 0; ni < 4; ni++)
#pragma unroll
            for (int q = 0; q < 4; q++) acc[mi][ni][q] = 0.f;

    int idx0 = tid * 2, idx1 = tid * 2 + 1;
    int lr0 = idx0 >> 2, ls0 = idx0 & 3;
    int lr1 = idx1 >> 2, ls1 = idx1 & 3;
    uint32_t so0 = (uint32_t)(lr0 * ASTR + ls0 * 8) * 2;
    uint32_t so1 = (uint32_t)(lr1 * ASTR + ls1 * 8) * 2;
    uint32_t smbase = smem_u32(smh);

#define CLOAD(s) do { \
    uint32_t sb = smbase + (uint32_t)((s) & 1) * 3u * (uint32_t)SLOT3; \
    int k0 = (s) << 5; \
    CP_ASYNC(sb + so0, d_GhF + (size_t)(row0 + lr0) * 512 + k0 + ls0*8); \
    CP_ASYNC(sb + so1, d_GhF + (size_t)(row0 + lr1) * 512 + k0 + ls1*8); \
    CP_ASYNC_CA(sb + SLOT3 + so0, d_BhC + (size_t)(n0 + lr0) * 512 + k0 + ls0*8); \
    CP_ASYNC_CA(sb + SLOT3 + so1, d_BhC + (size_t)(n0 + lr1) * 512 + k0 + ls1*8); \
    CP_ASYNC_CA(sb + 2*SLOT3 + so0, d_BlC + (size_t)(n0 + lr0) * 512 + k0 + ls0*8); \
    CP_ASYNC_CA(sb + 2*SLOT3 + so1, d_BlC + (size_t)(n0 + lr1) * 512 + k0 + ls1*8); \
} while (0)

    CLOAD(0);
    CP_COMMIT();

    int arow = (lane & 15), acol = (lane >> 4) * 8;
    int brow = (lane & 7),  bcol = ((lane >> 3) & 1) * 8;

    for (int s = 0; s < S; s++) {
        if (s + 1 < S) { CLOAD(s + 1); CP_COMMIT(); CP_WAIT(1); }
        else           { CP_WAIT(0); }
        __syncthreads();
        uint32_t sb = smbase + (uint32_t)(s & 1) * 3u * (uint32_t)SLOT3;
        uint32_t A_s = sb, Bh_s = sb + SLOT3, Bl_s = sb + 2*SLOT3;
#pragma unroll
        for (int ks = 0; ks < 2; ks++) {
            int k0 = ks * 16;
            uint32_t aF[4][4];
#pragma unroll
            for (int mi = 0; mi < 4; mi++) {
                uint32_t off = (uint32_t)((wm*64 + mi*16 + arow) * ASTR + k0 + acol) * 2;
                ldsm_x4(aF[mi], A_s + off);
            }
            uint32_t bH[4][2], bL[4][2];
#pragma unroll
            for (int ni = 0; ni < 4; ni++) {
                uint32_t off = (uint32_t)((wn*32 + ni*8 + brow) * ASTR + k0 + bcol) * 2;
                ldsm_x2(bH[ni], Bh_s + off);
                ldsm_x2(bL[ni], Bl_s + off);
            }
#pragma unroll
            for (int mi = 0; mi < 4; mi++)
#pragma unroll
                for (int ni = 0; ni < 4; ni++)
                    mma16816h(acc[mi][ni], aF[mi], bH[ni]);
#pragma unroll
            for (int mi = 0; mi < 4; mi++)
#pragma unroll
                for (int ni = 0; ni < 4; ni++)
                    mma16816h(acc[mi][ni], aF[mi], bL[ni]);
        }
        __syncthreads();
    }

    int g4 = lane >> 2, t4 = lane & 3;
    // gf epilogue: stage (re,im) pairs in smem [128][64] float2 = 64KB
    float2* sgf = (float2*)smh;
#pragma unroll
    for (int mi = 0; mi < 4; mi++) {
        int rl = wm*64 + mi*16 + g4;
#pragma unroll
        for (int ni = 0; ni < 4; ni++) {
            int chl = wn*16 + ni*4 + t4;
            sgf[rl*64 + chl]       = make_float2(acc[mi][ni][0], acc[mi][ni][1]);
            sgf[(rl+8)*64 + chl]   = make_float2(acc[mi][ni][2], acc[mi][ni][3]);
        }
    }
    __syncthreads();
    int rl = tid >> 1;
    int co = (tid & 1) * 32;
    int r = row0 + rl;
    int chbase = (n0 >> 1) + co;
    const float* gxp = &d_gX[(size_t)r * NC + chbase];
    const float* gyp = &d_gY[(size_t)r * NC + chbase];
    size_t ao = (size_t)r * 768 + 512 + chbase;
#pragma unroll
    for (int j0 = 0; j0 < 32; j0 += 8) {
        float4 gx0 = *(const float4*)(gxp + j0);
        float4 gx1 = *(const float4*)(gxp + j0 + 4);
        float4 gy0 = *(const float4*)(gyp + j0);
        float4 gy1 = *(const float4*)(gyp + j0 + 4);
        float4 t0, t1;
        float2 p;
        p = sgf[rl*64 + co + j0 + 0]; t0.x = tanhf(gx0.x*p.x + gy0.x*p.y);
        p = sgf[rl*64 + co + j0 + 1]; t0.y = tanhf(gx0.y*p.x + gy0.y*p.y);
        p = sgf[rl*64 + co + j0 + 2]; t0.z = tanhf(gx0.z*p.x + gy0.z*p.y);
        p = sgf[rl*64 + co + j0 + 3]; t0.w = tanhf(gx0.w*p.x + gy0.w*p.y);
        p = sgf[rl*64 + co + j0 + 4]; t1.x = tanhf(gx1.x*p.x + gy1.x*p.y);
        p = sgf[rl*64 + co + j0 + 5]; t1.y = tanhf(gx1.y*p.x + gy1.y*p.y);
        p = sgf[rl*64 + co + j0 + 6]; t1.z = tanhf(gx1.z*p.x + gy1.z*p.y);
        p = sgf[rl*64 + co + j0 + 7]; t1.w = tanhf(gx1.w*p.x + gy1.w*p.y);
        SplitPack sp = split8(t0, t1);
        *(uint4*)&d_Ah[ao + j0] = sp.hi;
        *(uint4*)&d_Al[ao + j0] = sp.lo;
    }
}

// ========================= generic mma.sync bf16-split GEMM ==================
__global__ __launch_bounds__(256, 2) void k_mma_gemm(
    const __nv_bfloat16* __restrict__ Ah, const __nv_bfloat16* __restrict__ Al, int ldA,
    const __nv_bfloat16* __restrict__ Bh, const __nv_bfloat16* __restrict__ Bl,
    float* __restrict__ out, int ldout, const float* __restrict__ bias, int K,
    float* __restrict__ stats, int bstrideB, int asplit_off)
{
    extern __shared__ __align__(16) __nv_bfloat16 sm[];
    int tid = threadIdx.x;
    int wid = tid >> 5, lane = tid & 31;
    int wm = wid & 1, wn = wid >> 1;
    int row0 = blockIdx.y * 128, n0 = blockIdx.x * 128;
    if (bstrideB) {
        int b = row0 / NV;
        Bh += (size_t)b * bstrideB;
        Bl += (size_t)b * bstrideB;
    }

    float acc[4][4][4];
#pragma unroll
    for (int mi = 0; mi < 4; mi++)
#pragma unroll
        for (int ni = 0; ni < 4; ni++)
#pragma unroll
            for (int q = 0; q < 4; q++) acc[mi][ni][q] = 0.f;

    int idx0 = tid * 2, idx1 = tid * 2 + 1;
    int lr0 = idx0 >> 2, ls0 = idx0 & 3;
    int lr1 = idx1 >> 2, ls1 = idx1 & 3;
    uint32_t so0 = (uint32_t)(lr0 * ASTR + ls0 * 8) * 2;
    uint32_t so1 = (uint32_t)(lr1 * ASTR + ls1 * 8) * 2;
    uint32_t smbase = smem_u32(sm);

    const int S = K >> 5;

#define LOADSTAGE(s) do { \
    int buf = (s) & 1; \
    uint32_t sb = smbase + (uint32_t)buf * 4u * TILEEL * 2u; \
    int k0 = (s) << 5; \
    CP_ASYNC(sb + so0, Ah + (size_t)(row0 + lr0) * ldA + k0 + ls0*8); \
    CP_ASYNC(sb + so1, Ah + (size_t)(row0 + lr1) * ldA + k0 + ls1*8); \
    CP_ASYNC(sb + TILEEL*2 + so0, Al + (size_t)(row0 + lr0) * ldA + k0 + ls0*8); \
    CP_ASYNC(sb + TILEEL*2 + so1, Al + (size_t)(row0 + lr1) * ldA + k0 + ls1*8); \
    CP_ASYNC_CA(sb + 2*TILEEL*2 + so0, Bh + (size_t)(n0 + lr0) * K + k0 + ls0*8); \
    CP_ASYNC_CA(sb + 2*TILEEL*2 + so1, Bh + (size_t)(n0 + lr1) * K + k0 + ls1*8); \
    CP_ASYNC_CA(sb + 3*TILEEL*2 + so0, Bl + (size_t)(n0 + lr0) * K + k0 + ls0*8); \
    CP_ASYNC_CA(sb + 3*TILEEL*2 + so1, Bl + (size_t)(n0 + lr1) * K + k0 + ls1*8); \
} while (0)

    LOADSTAGE(0);
    CP_COMMIT();

    int arow = (lane & 15), acol = (lane >> 4) * 8;
    int brow = (lane & 7),  bcol = ((lane >> 3) & 1) * 8;

    for (int s = 0; s < S; s++) {
        if (s + 1 < S) { LOADSTAGE(s + 1); CP_COMMIT(); CP_WAIT(1); }
        else           { CP_WAIT(0); }
        __syncthreads();

        uint32_t sb = smbase + (uint32_t)(s & 1) * 4u * TILEEL * 2u;
        uint32_t Ah_s = sb, Al_s = sb + TILEEL*2, Bh_s = sb + 2*TILEEL*2, Bl_s = sb + 3*TILEEL*2;

#pragma unroll
        for (int ks = 0; ks < 2; ks++) {
            int k0 = ks * 16;
            uint32_t aH[4][4], aL[4][4];
#pragma unroll
            for (int mi = 0; mi < 4; mi++) {
                uint32_t off = (uint32_t)((wm*64 + mi*16 + arow) * ASTR + k0 + acol) * 2;
                ldsm_x4(aH[mi], Ah_s + off);
                ldsm_x4(aL[mi], Al_s + off);
            }
            uint32_t bH[4][2], bL[4][2];
#pragma unroll
            for (int ni = 0; ni < 4; ni++) {
                uint32_t off = (uint32_t)((wn*32 + ni*8 + brow) * ASTR + k0 + bcol) * 2;
                ldsm_x2(bH[ni], Bh_s + off);
                ldsm_x2(bL[ni], Bl_s + off);
            }
            MMA_BLOCK();
        }
        __syncthreads();
    }

    int g4 = lane >> 2, t4 = lane & 3;

    float cs[4][2], cq[4][2];
#pragma unroll
    for (int ni = 0; ni < 4; ni++) { cs[ni][0]=cs[ni][1]=cq[ni][0]=cq[ni][1]=0.f; }

#pragma unroll
    for (int mi = 0; mi < 4; mi++) {
        int r = row0 + wm*64 + mi*16 + g4;
#pragma unroll
        for (int ni = 0; ni < 4; ni++) {
            int c = n0 + wn*32 + ni*8 + t4*2;
            float b0 = 0.f, b1 = 0.f;
            if (bias) { b0 = bias[c]; b1 = bias[c+1]; }
            float v0 = acc[mi][ni][0] + b0, v1 = acc[mi][ni][1] + b1;
            float v2 = acc[mi][ni][2] + b0, v3 = acc[mi][ni][3] + b1;
            *(float2*)&out[(size_t)r * ldout + c]     = make_float2(v0, v1);
            *(float2*)&out[(size_t)(r+8) * ldout + c] = make_float2(v2, v3);
            if (asplit_off >= 0) {
                uint32_t hi, lo;
                split2w(v0, v1, hi, lo);
                *(uint32_t*)&d_Ah[(size_t)r * 768 + asplit_off + c] = hi;
                *(uint32_t*)&d_Al[(size_t)r * 768 + asplit_off + c] = lo;
                split2w(v2, v3, hi, lo);
                *(uint32_t*)&d_Ah[(size_t)(r+8) * 768 + asplit_off + c] = hi;
                *(uint32_t*)&d_Al[(size_t)(r+8) * 768 + asplit_off + c] = lo;
            }
            cs[ni][0] += v0 + v2;  cq[ni][0] += v0*v0 + v2*v2;
            cs[ni][1] += v1 + v3;  cq[ni][1] += v1*v1 + v3*v3;
        }
    }
    if (stats) {
#pragma unroll
        for (int ni = 0; ni < 4; ni++) {
#pragma unroll
            for (int h = 0; h < 2; h++) {
                float s = cs[ni][h], q = cq[ni][h];
                s += __shfl_xor_sync(0xFFFFFFFFu, s, 4);
                q += __shfl_xor_sync(0xFFFFFFFFu, q, 4);
                s += __shfl_xor_sync(0xFFFFFFFFu, s, 8);
                q += __shfl_xor_sync(0xFFFFFFFFu, q, 8);
                s += __shfl_xor_sync(0xFFFFFFFFu, s, 16);
                q += __shfl_xor_sync(0xFFFFFFFFu, q, 16);
                if (g4 == 0) {
                    int c = n0 + wn*32 + ni*8 + t4*2 + h;
                    atomicAdd(&stats[c], s);
                    atomicAdd(&stats[256 + c], q);
                }
            }
        }
    }
}

// out = bn(h2) + x
__global__ void k_final(const float* __restrict__ x, const float* __restrict__ g,
                        const float* __restrict__ be, float* __restrict__ out) {
    int tid = threadIdx.x;
    __shared__ float sc[256], sh[256];
    {
        float mean = d_stats[1024 + tid] * (1.0f / NN);
        float var  = d_stats[1280 + tid] * (1.0f / NN) - mean * mean;
        float s = rsqrtf(var + BNEPS) * g[tid];
        sc[tid] = s;
        sh[tid] = be[tid] - mean * s;
    }
    __syncthreads();
    size_t i = (size_t)(blockIdx.x * 256 + tid) * 4;
    int c = (int)(i & 255);
    float4 h  = *(float4*)&d_h2[i];
    float4 xv = *(const float4*)&x[i];
    float4 o;
    o.x = h.x * sc[c+0] + sh[c+0] + xv.x;
    o.y = h.y * sc[c+1] + sh[c+1] + xv.y;
    o.z = h.z * sc[c+2] + sh[c+2] + xv.z;
    o.w = h.w * sc[c+3] + sh[c+3] + xv.w;
    *(float4*)&out[i] = o;
}

// ------------------------------- launch --------------------------------------
extern "C" void kernel_launch(void* const* d_in, const int* in_sizes, int n_in,
                              void* d_out, int out_size) {
    const float* x       = (const float*)d_in[0];
    const float* mass    = (const float*)d_in[1];
    const float* evals   = (const float*)d_in[2];
    const float* evecs   = (const float*)d_in[3];
    const int*   gx_rows = (const int*)  d_in[4];
    const int*   gx_cols = (const int*)  d_in[5];
    const float* gx_vals = (const float*)d_in[6];
    const int*   gy_rows = (const int*)  d_in[7];
    const int*   gy_cols = (const int*)  d_in[8];
    const float* gy_vals = (const float*)d_in[9];
    const float* dt      = (const float*)d_in[10];
    const float* A_re    = (const float*)d_in[11];
    const float* A_im    = (const float*)d_in[12];
    const float* W0      = (const float*)d_in[13];
    const float* b0      = (const float*)d_in[14];
    const float* g0      = (const float*)d_in[15];
    const float* be0     = (const float*)d_in[16];
    const float* W1      = (const float*)d_in[17];
    const float* b1      = (const float*)d_in[18];
    const float* g1      = (const float*)d_in[19];
    const float* be1     = (const float*)d_in[20];
    const float* W2      = (const float*)d_in[21];
    const float* b2      = (const float*)d_in[22];
    const float* g2      = (const float*)d_in[23];
    const float* be2     = (const float*)d_in[24];
    float* out = (float*)d_out;

    static int smem_set = 0;
    if (!smem_set) {
        cudaFuncSetAttribute(k_mma_gemm, cudaFuncAttributeMaxDynamicSharedMemorySize, GEMM_SMEM);
        cudaFuncSetAttribute(k_xspec_mma, cudaFuncAttributeMaxDynamicSharedMemorySize, GEMM_SMEM);
        cudaFuncSetAttribute(k_mma_cplx, cudaFuncAttributeMaxDynamicSharedMemorySize, CPLX_SMEM);
        smem_set = 1;
    }

    __nv_bfloat16 *Ah, *Al, *Bh, *Bl, *eH, *eL, *ytH, *ytL;
    float *h0, *h1, *h2, *stats, *xd;
    cudaGetSymbolAddress((void**)&Ah, d_Ah);
    cudaGetSymbolAddress((void**)&Al, d_Al);
    cudaGetSymbolAddress((void**)&Bh, d_Bh);
    cudaGetSymbolAddress((void**)&Bl, d_Bl);
    cudaGetSymbolAddress((void**)&eH, d_eH);
    cudaGetSymbolAddress((void**)&eL, d_eL);
    cudaGetSymbolAddress((void**)&ytH, d_ytH);
    cudaGetSymbolAddress((void**)&ytL, d_ytL);
    cudaGetSymbolAddress((void**)&h0, d_h0);
    cudaGetSymbolAddress((void**)&h1, d_h1);
    cudaGetSymbolAddress((void**)&h2, d_h2);
    cudaGetSymbolAddress((void**)&stats, d_stats);
    cudaGetSymbolAddress((void**)&xd, d_xd);

    k_zero<<<256, 256>>>();
    k_trans_mevecs<<<dim3(256, 4, 8), 256>>>(evecs, mass);
    k_trans_x<<<dim3(256, 8, 8), 256>>>(x);
    k_xspec_mma<<<dim3(32, 2, 8), 256, GEMM_SMEM>>>();
    k_coefT<<<256, 256>>>(evals, dt);
    // x_diffuse = evecs @ yT^T  (per-batch B); also split into A cols [256..512)
    k_mma_gemm<<<dim3(2, 512), 256, GEMM_SMEM>>>(eH, eL, NK, ytH, ytL,
                                                 xd, 256, nullptr, NK, nullptr, NC*NK, 256);
    // CSR build
    k_hist<<<4096, 256>>>(gx_rows, gy_rows);
    k_scan1<<<512, 256>>>();
    k_scan2<<<1, 512>>>();
    k_scan3<<<512, 256>>>();
    k_scatter<<<4096, 256>>>(gx_rows, gy_rows);
    // sparse gradients: float gX/gY + fp16 G operand
    k_spmm_csr<<<32768, 256>>>(gx_cols, gx_vals, gy_cols, gy_vals);

    // weight prep
    k_prep_cplxB<<<1024, 256>>>(A_re, A_im);
    k_prep_wT<<<768, 256>>>(W0, 768, 256, BOFF_W0);
    k_prep_wT<<<256, 256>>>(W1, 256, 256, BOFF_W1);
    k_prep_wT<<<256, 256>>>(W2, 256, 256, BOFF_W2);

    // cplx GEMM (fp16 2-term) with fused tanh epilogue -> A cols [512..768)
    k_mma_cplx<<<dim3(4, 512), 256, CPLX_SMEM>>>();

    // MLP (stats fused into epilogues)
    k_mma_gemm<<<dim3(2, 512), 256, GEMM_SMEM>>>(Ah, Al, 768, Bh + BOFF_W0, Bl + BOFF_W0,
                                                 h0, 256, b0, 768, stats, 0, -1);
    k_bnsplit<<<8192, 256>>>(h0, 0, g0, be0);
    k_mma_gemm<<<dim3(2, 512), 256, GEMM_SMEM>>>(Ah, Al, 768, Bh + BOFF_W1, Bl + BOFF_W1,
                                                 h1, 256, b1, 256, stats + 512, 0, -1);
    k_bnsplit<<<8192, 256>>>(h1, 512, g1, be1);
    k_mma_gemm<<<dim3(2, 512), 256, GEMM_SMEM>>>(Ah, Al, 768, Bh + BOFF_W2, Bl + BOFF_W2,
                                                 h2, 256, b2, 256, stats + 1024, 0, -1);
    k_final<<<16384, 256>>>(x, g2, be2, out);
}

// round 15
// speedup vs baseline: 1.2643x; 1.1371x over previous
#include <cuda_runtime.h>
#include <cuda_bf16.h>
#include <cuda_fp16.h>
#include <math.h>
#include <cstdint>

#define NB 8
#define NV 8192
#define NK 128
#define NC 256
#define NN 65536          // NB*NV
#define NNZ 1048576       // 16*NN
#define BNEPS 1e-5f

// ------------------------- scratch (device globals) -------------------------
static __device__ float d_xspec[NB*NK*NC];
static __device__ float d_xd  [NN*NC];
static __device__ float d_gX  [NN*NC];
static __device__ float d_gY  [NN*NC];
static __device__ float d_h0  [NN*NC];
static __device__ float d_h1  [NN*NC];
static __device__ float d_h2  [NN*NC];
static __device__ float d_stats[1536];
// CSR build scratch
static __device__ int d_cnt [131072];
static __device__ int d_off [131072];
static __device__ int d_bsum[512];
static __device__ int d_perm[2*NNZ];
// fp16 single A for MLP: [NN, 768]  (cols: x | xd | gf)
static __device__ __half d_Af[(size_t)NN*768];
// fp16 single [gX|gY] operand for cplx GEMM: [NN, 512]
static __device__ __half d_GhF[(size_t)NN*512];
// fp16 split cplx-interleaved B: [512, 512]
static __device__ __half d_BhC[262144];
static __device__ __half d_BlC[262144];
// fp16 split W pool: W0T(256x768) | W1T | W2T
#define BOFF_W0   0
#define BOFF_W1   196608
#define BOFF_W2   262144
static __device__ __half d_BhW[327680];
static __device__ __half d_BlW[327680];
// xdiff operands: evecs fp16 single; yt fp16 split
static __device__ __half d_eF[(size_t)NN*NK];
static __device__ __half d_ytHf[NB*NC*NK];
static __device__ __half d_ytLf[NB*NC*NK];
// spectral operands for xspec (bf16 split, accuracy anchor)
static __device__ __nv_bfloat16 d_mtH[(size_t)NB*NK*NV];
static __device__ __nv_bfloat16 d_mtL[(size_t)NB*NK*NV];
static __device__ __nv_bfloat16 d_xtH[(size_t)NB*NC*NV];
static __device__ __nv_bfloat16 d_xtL[(size_t)NB*NC*NV];

__device__ __forceinline__ uint32_t smem_u32(const void* p) {
    uint32_t a;
    asm("{ .reg .u64 t; cvta.to.shared.u64 t, %1; cvt.u32.u64 %0, t; }" : "=r"(a) : "l"(p));
    return a;
}

struct SplitPack4 { uint2 hi, lo; };
__device__ __forceinline__ SplitPack4 split4bf(const float* v) {
    union { __nv_bfloat16 h[4]; uint2 u; } H;
    union { __nv_bfloat16 h[4]; uint2 u; } L;
#pragma unroll
    for (int j = 0; j < 4; j++) {
        __nv_bfloat16 hh = __float2bfloat16(v[j]);
        H.h[j] = hh;
        L.h[j] = __float2bfloat16(v[j] - __bfloat162float(hh));
    }
    SplitPack4 r; r.hi = H.u; r.lo = L.u; return r;
}
// fp16 packers
__device__ __forceinline__ uint2 pack4h(const float* v) {
    union { __half h[4]; uint2 u; } P;
#pragma unroll
    for (int j = 0; j < 4; j++) P.h[j] = __float2half(v[j]);
    return P.u;
}
__device__ __forceinline__ uint4 pack8h(float4 a, float4 b) {
    union { __half h[8]; uint4 u; } P;
    P.h[0] = __float2half(a.x); P.h[1] = __float2half(a.y);
    P.h[2] = __float2half(a.z); P.h[3] = __float2half(a.w);
    P.h[4] = __float2half(b.x); P.h[5] = __float2half(b.y);
    P.h[6] = __float2half(b.z); P.h[7] = __float2half(b.w);
    return P.u;
}
__device__ __forceinline__ uint32_t pack2h(float a, float b) {
    union { __half h[2]; uint32_t u; } P;
    P.h[0] = __float2half(a); P.h[1] = __float2half(b);
    return P.u;
}
__device__ __forceinline__ void splith(float v, __half* ph, __half* pl) {
    __half h = __float2half(v);
    *ph = h;
    *pl = __float2half(v - __half2float(h));
}

// ------------------------------- zero init ----------------------------------
__global__ void k_zero() {
    int i = blockIdx.x * 256 + threadIdx.x;     // < 65536
    float4 z = make_float4(0.f, 0.f, 0.f, 0.f);
    *(float4*)&d_xspec[i * 4] = z;
    if (i < 32768) *(int4*)&d_cnt[i * 4] = make_int4(0, 0, 0, 0);
    if (i < 384)   *(float4*)&d_stats[i * 4] = z;
}

// ========================= CSR build (both matrices) =========================
__global__ void k_hist(const int* __restrict__ gxr, const int* __restrict__ gyr) {
    int i = blockIdx.x * 256 + threadIdx.x;
    atomicAdd(&d_cnt[gxr[i]], 1);
    atomicAdd(&d_cnt[65536 + gyr[i]], 1);
}

__global__ void k_scan1() {
    __shared__ int sh[256];
    int tid = threadIdx.x;
    int i = blockIdx.x * 256 + tid;
    int v = d_cnt[i];
    sh[tid] = v;
    __syncthreads();
    for (int o = 1; o < 256; o <<= 1) {
        int t = (tid >= o) ? sh[tid - o] : 0;
        __syncthreads();
        sh[tid] += t;
        __syncthreads();
    }
    d_off[i] = sh[tid] - v;
    if (tid == 255) d_bsum[blockIdx.x] = sh[255];
}

__global__ void k_scan2() {
    __shared__ int sh[512];
    int tid = threadIdx.x;
    int v = d_bsum[tid];
    sh[tid] = v;
    __syncthreads();
    for (int o = 1; o < 512; o <<= 1) {
        int t = (tid >= o) ? sh[tid - o] : 0;
        __syncthreads();
        sh[tid] += t;
        __syncthreads();
    }
    d_bsum[tid] = sh[tid] - v;
}

__global__ void k_scan3() {
    int i = blockIdx.x * 256 + threadIdx.x;
    int v = d_off[i] + d_bsum[i >> 8];
    d_off[i] = v;
    d_cnt[i] = v;
}

__global__ void k_scatter(const int* __restrict__ gxr, const int* __restrict__ gyr) {
    int i = blockIdx.x * 256 + threadIdx.x;
    int p = atomicAdd(&d_cnt[gxr[i]], 1);
    d_perm[p] = i;
    int q = atomicAdd(&d_cnt[65536 + gyr[i]], 1);
    d_perm[q] = i;
}

// merged CSR spmm: float out + fp16 into G operand. grid 32768, 256 thr
__global__ __launch_bounds__(256) void k_spmm_csr(
    const int* __restrict__ gxc, const float* __restrict__ gxv,
    const int* __restrict__ gyc, const float* __restrict__ gyv) {
    int g = threadIdx.x >> 6, t = threadIdx.x & 63;
    int idx = blockIdx.x * 4 + g;               // < 131072
    int isX = (idx < 65536);
    const int*   cols = isX ? gxc : gyc;
    const float* vals = isX ? gxv : gyv;
    float* out        = isX ? d_gX : d_gY;
    int r = idx & 65535;
    int s = d_off[idx], e = d_cnt[idx];
    int c = t * 4;
    float4 acc = make_float4(0.f, 0.f, 0.f, 0.f);
    int p = s;
    for (; p + 4 <= e; p += 4) {
        int e0 = d_perm[p], e1 = d_perm[p+1], e2 = d_perm[p+2], e3 = d_perm[p+3];
        int c0 = cols[e0], c1 = cols[e1], c2 = cols[e2], c3 = cols[e3];
        float v0 = vals[e0], v1 = vals[e1], v2 = vals[e2], v3 = vals[e3];
        float4 x0 = *(const float4*)&d_xd[(size_t)c0 * NC + c];
        float4 x1 = *(const float4*)&d_xd[(size_t)c1 * NC + c];
        float4 x2 = *(const float4*)&d_xd[(size_t)c2 * NC + c];
        float4 x3 = *(const float4*)&d_xd[(size_t)c3 * NC + c];
        acc.x += v0*x0.x + v1*x1.x + v2*x2.x + v3*x3.x;
        acc.y += v0*x0.y + v1*x1.y + v2*x2.y + v3*x3.y;
        acc.z += v0*x0.z + v1*x1.z + v2*x2.z + v3*x3.z;
        acc.w += v0*x0.w + v1*x1.w + v2*x2.w + v3*x3.w;
    }
    for (; p < e; p++) {
        int ed = d_perm[p];
        int cl = cols[ed];
        float v = vals[ed];
        float4 xv = *(const float4*)&d_xd[(size_t)cl * NC + c];
        acc.x += v*xv.x; acc.y += v*xv.y; acc.z += v*xv.z; acc.w += v*xv.w;
    }
    *(float4*)&out[(size_t)r * NC + c] = acc;
    *(uint2*)&d_GhF[(size_t)r * 512 + (isX ? 0 : 256) + c] = pack4h(&acc.x);
}

// ===================== spectral operand preparation ==========================
// mt bf16 split (xspec A) + evecs fp16 single (xdiff A). grid (256, 4, 8)
__global__ __launch_bounds__(256) void k_trans_mevecs(
    const float* __restrict__ evecs, const float* __restrict__ mass) {
    __shared__ float tile[32][33];
    __shared__ float smass[32];
    int v0 = blockIdx.x * 32, k0 = blockIdx.y * 32, b = blockIdx.z;
    int tid = threadIdx.x;
    int tx = tid & 31, ty = tid >> 5;
    if (tid < 32) smass[tid] = mass[b * NV + v0 + tid];
#pragma unroll
    for (int i = 0; i < 4; i++) {
        int vl = ty + i * 8;
        tile[vl][tx] = evecs[(size_t)(b * NV + v0 + vl) * NK + k0 + tx];
    }
    __syncthreads();
    {
        int k = tid >> 3, vq = (tid & 7) * 4;
        float v[4];
#pragma unroll
        for (int j = 0; j < 4; j++) v[j] = tile[vq + j][k] * smass[vq + j];
        SplitPack4 p = split4bf(v);
        size_t o = (size_t)(b * NK + k0 + k) * NV + v0 + vq;
        *(uint2*)&d_mtH[o] = p.hi;
        *(uint2*)&d_mtL[o] = p.lo;
    }
    {
        int v = tid >> 3, kq = (tid & 7) * 4;
        float w[4];
#pragma unroll
        for (int j = 0; j < 4; j++) w[j] = tile[v][kq + j];
        size_t o = (size_t)(b * NV + v0 + v) * NK + k0 + kq;
        *(uint2*)&d_eF[o] = pack4h(w);
    }
}

// x^T bf16 split (xspec B) + x fp16 into A cols [0..256). grid (256, 8, 8)
__global__ __launch_bounds__(256) void k_trans_x(const float* __restrict__ x) {
    __shared__ float tile[32][33];
    int v0 = blockIdx.x * 32, c0 = blockIdx.y * 32, b = blockIdx.z;
    int tid = threadIdx.x;
    int tx = tid & 31, ty = tid >> 5;
#pragma unroll
    for (int i = 0; i < 4; i++) {
        int vl = ty + i * 8;
        tile[vl][tx] = x[(size_t)(b * NV + v0 + vl) * NC + c0 + tx];
    }
    __syncthreads();
    {
        int c = tid >> 3, vq = (tid & 7) * 4;
        float v[4];
#pragma unroll
        for (int j = 0; j < 4; j++) v[j] = tile[vq + j][c];
        SplitPack4 p = split4bf(v);
        size_t o = (size_t)(b * NC + c0 + c) * NV + v0 + vq;
        *(uint2*)&d_xtH[o] = p.hi;
        *(uint2*)&d_xtL[o] = p.lo;
    }
    {
        int v = tid >> 3, cq = (tid & 7) * 4;
        float w[4];
#pragma unroll
        for (int j = 0; j < 4; j++) w[j] = tile[v][cq + j];
        size_t o = (size_t)(b * NV + v0 + v) * 768 + c0 + cq;
        *(uint2*)&d_Af[o] = pack4h(w);
    }
}

// yT fp16 split. grid 256
__global__ void k_coefT(const float* __restrict__ evals, const float* __restrict__ dt) {
    int i = blockIdx.x * 256 + threadIdx.x;   // < 65536
    int kq = (i & 31) * 4;
    int c  = (i >> 5) & 255;
    int b  = i >> 13;
    float t = fmaxf(dt[c], 1e-8f);
    union { __half h[4]; uint2 u; } H, L;
#pragma unroll
    for (int j = 0; j < 4; j++) {
        float v = expf(-evals[b * NK + kq + j] * t) * d_xspec[(b * NK + kq + j) * NC + c];
        __half hh = __float2half(v);
        H.h[j] = hh;
        L.h[j] = __float2half(v - __half2float(hh));
    }
    int o = b * (NC * NK) + c * NK + kq;
    *(uint2*)&d_ytHf[o] = H.u;
    *(uint2*)&d_ytLf[o] = L.u;
}

// ============================ mma primitives =================================
__device__ __forceinline__ void ldsm_x4(uint32_t* r, uint32_t addr) {
    asm volatile("ldmatrix.sync.aligned.m8n8.x4.shared.b16 {%0,%1,%2,%3}, [%4];"
                 : "=r"(r[0]), "=r"(r[1]), "=r"(r[2]), "=r"(r[3]) : "r"(addr));
}
__device__ __forceinline__ void ldsm_x2(uint32_t* r, uint32_t addr) {
    asm volatile("ldmatrix.sync.aligned.m8n8.x2.shared.b16 {%0,%1}, [%2];"
                 : "=r"(r[0]), "=r"(r[1]) : "r"(addr));
}
__device__ __forceinline__ void mma16816(float* c, const uint32_t* a, const uint32_t* b) {
    asm volatile("mma.sync.aligned.m16n8k16.row.col.f32.bf16.bf16.f32 "
                 "{%0,%1,%2,%3}, {%4,%5,%6,%7}, {%8,%9}, {%0,%1,%2,%3};"
                 : "+f"(c[0]), "+f"(c[1]), "+f"(c[2]), "+f"(c[3])
                 : "r"(a[0]), "r"(a[1]), "r"(a[2]), "r"(a[3]), "r"(b[0]), "r"(b[1]));
}
__device__ __forceinline__ void mma16816h(float* c, const uint32_t* a, const uint32_t* b) {
    asm volatile("mma.sync.aligned.m16n8k16.row.col.f32.f16.f16.f32 "
                 "{%0,%1,%2,%3}, {%4,%5,%6,%7}, {%8,%9}, {%0,%1,%2,%3};"
                 : "+f"(c[0]), "+f"(c[1]), "+f"(c[2]), "+f"(c[3])
                 : "r"(a[0]), "r"(a[1]), "r"(a[2]), "r"(a[3]), "r"(b[0]), "r"(b[1]));
}
#define CP_ASYNC(sm, gm) \
    asm volatile("cp.async.cg.shared.global [%0], [%1], 16;" :: "r"(sm), "l"(gm))
#define CP_ASYNC_CA(sm, gm) \
    asm volatile("cp.async.ca.shared.global [%0], [%1], 16;" :: "r"(sm), "l"(gm))
#define CP_COMMIT() asm volatile("cp.async.commit_group;" ::: "memory")
#define CP_WAIT(n)  asm volatile("cp.async.wait_group %0;" :: "n"(n) : "memory")

#define ASTR 40
#define TILEEL (128*ASTR)
#define GEMM_SMEM (2*4*TILEEL*2)   // xspec bf16 kernel: 81920
#define SLOT3 (TILEEL*2)           // 10240 bytes (one tile)
#define HSMEM 65536                // fp16 kernel: max(2*3*SLOT3=61440, gf staging 65536)

// ------------------- x_spec split-K mma (bf16 3-term): grid (32, 2, 8) -------
__global__ __launch_bounds__(256, 2) void k_xspec_mma() {
    extern __shared__ __align__(16) __nv_bfloat16 sm[];
    int tid = threadIdx.x;
    int wid = tid >> 5, lane = tid & 31;
    int wm = wid & 1, wn = wid >> 1;
    int kb = blockIdx.x, ch = blockIdx.y, b = blockIdx.z;
    const __nv_bfloat16* Ah = d_mtH + (size_t)b * NK * NV;
    const __nv_bfloat16* Al = d_mtL + (size_t)b * NK * NV;
    const __nv_bfloat16* Bh = d_xtH + (size_t)(b * NC + ch * 128) * NV;
    const __nv_bfloat16* Bl = d_xtL + (size_t)(b * NC + ch * 128) * NV;
    int kbase = kb * 256;

    float acc[4][4][4];
#pragma unroll
    for (int mi = 0; mi < 4; mi++)
#pragma unroll
        for (int ni = 0; ni < 4; ni++)
#pragma unroll
            for (int q = 0; q < 4; q++) acc[mi][ni][q] = 0.f;

    int idx0 = tid * 2, idx1 = tid * 2 + 1;
    int lr0 = idx0 >> 2, ls0 = idx0 & 3;
    int lr1 = idx1 >> 2, ls1 = idx1 & 3;
    uint32_t so0 = (uint32_t)(lr0 * ASTR + ls0 * 8) * 2;
    uint32_t so1 = (uint32_t)(lr1 * ASTR + ls1 * 8) * 2;
    uint32_t smbase = smem_u32(sm);

#define XLOAD(s) do { \
    uint32_t sb = smbase + (uint32_t)((s) & 1) * 4u * TILEEL * 2u; \
    int k0 = kbase + ((s) << 5); \
    CP_ASYNC(sb + so0, Ah + (size_t)lr0 * NV + k0 + ls0*8); \
    CP_ASYNC(sb + so1, Ah + (size_t)lr1 * NV + k0 + ls1*8); \
    CP_ASYNC(sb + TILEEL*2 + so0, Al + (size_t)lr0 * NV + k0 + ls0*8); \
    CP_ASYNC(sb + TILEEL*2 + so1, Al + (size_t)lr1 * NV + k0 + ls1*8); \
    CP_ASYNC(sb + 2*TILEEL*2 + so0, Bh + (size_t)lr0 * NV + k0 + ls0*8); \
    CP_ASYNC(sb + 2*TILEEL*2 + so1, Bh + (size_t)lr1 * NV + k0 + ls1*8); \
    CP_ASYNC(sb + 3*TILEEL*2 + so0, Bl + (size_t)lr0 * NV + k0 + ls0*8); \
    CP_ASYNC(sb + 3*TILEEL*2 + so1, Bl + (size_t)lr1 * NV + k0 + ls1*8); \
} while (0)

    XLOAD(0);
    CP_COMMIT();

    int arow = (lane & 15), acol = (lane >> 4) * 8;
    int brow = (lane & 7),  bcol = ((lane >> 3) & 1) * 8;

    for (int s = 0; s < 8; s++) {
        if (s + 1 < 8) { XLOAD(s + 1); CP_COMMIT(); CP_WAIT(1); }
        else           { CP_WAIT(0); }
        __syncthreads();
        uint32_t sb = smbase + (uint32_t)(s & 1) * 4u * TILEEL * 2u;
        uint32_t Ah_s = sb, Al_s = sb + TILEEL*2, Bh_s = sb + 2*TILEEL*2, Bl_s = sb + 3*TILEEL*2;
#pragma unroll
        for (int ks = 0; ks < 2; ks++) {
            int k0 = ks * 16;
            uint32_t aH[4][4], aL[4][4];
#pragma unroll
            for (int mi = 0; mi < 4; mi++) {
                uint32_t off = (uint32_t)((wm*64 + mi*16 + arow) * ASTR + k0 + acol) * 2;
                ldsm_x4(aH[mi], Ah_s + off);
                ldsm_x4(aL[mi], Al_s + off);
            }
            uint32_t bH[4][2], bL[4][2];
#pragma unroll
            for (int ni = 0; ni < 4; ni++) {
                uint32_t off = (uint32_t)((wn*32 + ni*8 + brow) * ASTR + k0 + bcol) * 2;
                ldsm_x2(bH[ni], Bh_s + off);
                ldsm_x2(bL[ni], Bl_s + off);
            }
#pragma unroll
            for (int mi = 0; mi < 4; mi++)
#pragma unroll
                for (int ni = 0; ni < 4; ni++)
                    mma16816(acc[mi][ni], aH[mi], bH[ni]);
#pragma unroll
            for (int mi = 0; mi < 4; mi++)
#pragma unroll
                for (int ni = 0; ni < 4; ni++)
                    mma16816(acc[mi][ni], aH[mi], bL[ni]);
#pragma unroll
            for (int mi = 0; mi < 4; mi++)
#pragma unroll
                for (int ni = 0; ni < 4; ni++)
                    mma16816(acc[mi][ni], aL[mi], bH[ni]);
        }
        __syncthreads();
    }

    int g4 = lane >> 2, t4 = lane & 3;
#pragma unroll
    for (int mi = 0; mi < 4; mi++) {
        int r = wm*64 + mi*16 + g4;
#pragma unroll
        for (int ni = 0; ni < 4; ni++) {
            int c = ch*128 + wn*32 + ni*8 + t4*2;
            float* o0 = &d_xspec[(b*NK + r) * NC + c];
            float* o1 = &d_xspec[(b*NK + r + 8) * NC + c];
            asm volatile("red.global.add.v2.f32 [%0], {%1,%2};"
                         :: "l"(o0), "f"(acc[mi][ni][0]), "f"(acc[mi][ni][1]) : "memory");
            asm volatile("red.global.add.v2.f32 [%0], {%1,%2};"
                         :: "l"(o1), "f"(acc[mi][ni][2]), "f"(acc[mi][ni][3]) : "memory");
        }
    }
}

// ========================== B-operand prep ==================================
__global__ void k_prep_cplxB(const float* __restrict__ Are, const float* __restrict__ Aim) {
    int i = blockIdx.x * 256 + threadIdx.x;   // < 262144
    int n = i >> 9, k = i & 511;
    int m = n >> 1;
    float v;
    if ((n & 1) == 0) v = (k < 256) ? Are[m*256 + k] : -Aim[m*256 + (k-256)];
    else              v = (k < 256) ? Aim[m*256 + k] :  Are[m*256 + (k-256)];
    splith(v, &d_BhC[i], &d_BlC[i]);
}

__global__ void k_prep_wT(const float* __restrict__ W, int K, int N, int off) {
    int i = blockIdx.x * 256 + threadIdx.x;
    if (i >= N * K) return;
    int n = i / K, k = i % K;
    splith(W[k*N + n], &d_BhW[off + i], &d_BlW[off + i]);
}

// relu(bn(h)) -> A cols [0..255] (fp16). grid 8192, 256 thr
__global__ void k_bnsplit(const float* __restrict__ h, int statoff,
                          const float* __restrict__ g, const float* __restrict__ be) {
    int tid = threadIdx.x;
    __shared__ float sc[256], sh[256];
    {
        float mean = d_stats[statoff + tid] * (1.0f / NN);
        float var  = d_stats[statoff + 256 + tid] * (1.0f / NN) - mean * mean;
        float s = rsqrtf(var + BNEPS) * g[tid];
        sc[tid] = s;
        sh[tid] = be[tid] - mean * s;
    }
    __syncthreads();
    int idx = blockIdx.x * 256 + tid;          // < 2097152
    size_t row = idx >> 5;
    int c = (idx & 31) * 8;
    size_t o = row * 256 + c;
    float4 h0 = *(const float4*)&h[o], h1 = *(const float4*)&h[o + 4];
    float4 v0, v1;
    v0.x = fmaxf(h0.x * sc[c+0] + sh[c+0], 0.f);
    v0.y = fmaxf(h0.y * sc[c+1] + sh[c+1], 0.f);
    v0.z = fmaxf(h0.z * sc[c+2] + sh[c+2], 0.f);
    v0.w = fmaxf(h0.w * sc[c+3] + sh[c+3], 0.f);
    v1.x = fmaxf(h1.x * sc[c+4] + sh[c+4], 0.f);
    v1.y = fmaxf(h1.y * sc[c+5] + sh[c+5], 0.f);
    v1.z = fmaxf(h1.z * sc[c+6] + sh[c+6], 0.f);
    v1.w = fmaxf(h1.w * sc[c+7] + sh[c+7], 0.f);
    *(uint4*)&d_Af[row * 768 + c] = pack8h(v0, v1);
}

// =================== generic fp16 2-MMA GEMM =================================
// C = A(single fp16) @ (Bh+Bl)(fp16 split)^T.  grid (N/128, M/128), 256 thr.
// mode 0: out+bias (+stats, +fp16 asplit); mode 2: gf epilogue (tanh -> A[512..768)).
__global__ __launch_bounds__(256, 2) void k_mma_h(
    const __half* __restrict__ Af, int ldA,
    const __half* __restrict__ Bh, const __half* __restrict__ Bl,
    float* __restrict__ out, int ldout, const float* __restrict__ bias, int K,
    float* __restrict__ stats, int bstrideB, int mode, int asplit_off)
{
    extern __shared__ __align__(16) __half smh[];
    int tid = threadIdx.x;
    int wid = tid >> 5, lane = tid & 31;
    int wm = wid & 1, wn = wid >> 1;
    int row0 = blockIdx.y * 128, n0 = blockIdx.x * 128;
    if (bstrideB) {
        int b = row0 / NV;
        Bh += (size_t)b * bstrideB;
        Bl += (size_t)b * bstrideB;
    }
    const int S = K >> 5;

    float acc[4][4][4];
#pragma unroll
    for (int mi = 0; mi < 4; mi++)
#pragma unroll
        for (int ni = 0; ni < 4; ni++)
#pragma unroll
            for (int q = 0; q < 4; q++) acc[mi][ni][q] = 0.f;

    int idx0 = tid * 2, idx1 = tid * 2 + 1;
    int lr0 = idx0 >> 2, ls0 = idx0 & 3;
    int lr1 = idx1 >> 2, ls1 = idx1 & 3;
    uint32_t so0 = (uint32_t)(lr0 * ASTR + ls0 * 8) * 2;
    uint32_t so1 = (uint32_t)(lr1 * ASTR + ls1 * 8) * 2;
    uint32_t smbase = smem_u32(smh);

#define HLOAD(s) do { \
    uint32_t sb = smbase + (uint32_t)((s) & 1) * 3u * (uint32_t)SLOT3; \
    int k0 = (s) << 5; \
    CP_ASYNC(sb + so0, Af + (size_t)(row0 + lr0) * ldA + k0 + ls0*8); \
    CP_ASYNC(sb + so1, Af + (size_t)(row0 + lr1) * ldA + k0 + ls1*8); \
    CP_ASYNC_CA(sb + SLOT3 + so0, Bh + (size_t)(n0 + lr0) * K + k0 + ls0*8); \
    CP_ASYNC_CA(sb + SLOT3 + so1, Bh + (size_t)(n0 + lr1) * K + k0 + ls1*8); \
    CP_ASYNC_CA(sb + 2*SLOT3 + so0, Bl + (size_t)(n0 + lr0) * K + k0 + ls0*8); \
    CP_ASYNC_CA(sb + 2*SLOT3 + so1, Bl + (size_t)(n0 + lr1) * K + k0 + ls1*8); \
} while (0)

    HLOAD(0);
    CP_COMMIT();

    int arow = (lane & 15), acol = (lane >> 4) * 8;
    int brow = (lane & 7),  bcol = ((lane >> 3) & 1) * 8;

    for (int s = 0; s < S; s++) {
        if (s + 1 < S) { HLOAD(s + 1); CP_COMMIT(); CP_WAIT(1); }
        else           { CP_WAIT(0); }
        __syncthreads();
        uint32_t sb = smbase + (uint32_t)(s & 1) * 3u * (uint32_t)SLOT3;
        uint32_t A_s = sb, Bh_s = sb + SLOT3, Bl_s = sb + 2*SLOT3;
#pragma unroll
        for (int ks = 0; ks < 2; ks++) {
            int k0 = ks * 16;
            uint32_t aF[4][4];
#pragma unroll
            for (int mi = 0; mi < 4; mi++) {
                uint32_t off = (uint32_t)((wm*64 + mi*16 + arow) * ASTR + k0 + acol) * 2;
                ldsm_x4(aF[mi], A_s + off);
            }
            uint32_t bH[4][2], bL[4][2];
#pragma unroll
            for (int ni = 0; ni < 4; ni++) {
                uint32_t off = (uint32_t)((wn*32 + ni*8 + brow) * ASTR + k0 + bcol) * 2;
                ldsm_x2(bH[ni], Bh_s + off);
                ldsm_x2(bL[ni], Bl_s + off);
            }
#pragma unroll
            for (int mi = 0; mi < 4; mi++)
#pragma unroll
                for (int ni = 0; ni < 4; ni++)
                    mma16816h(acc[mi][ni], aF[mi], bH[ni]);
#pragma unroll
            for (int mi = 0; mi < 4; mi++)
#pragma unroll
                for (int ni = 0; ni < 4; ni++)
                    mma16816h(acc[mi][ni], aF[mi], bL[ni]);
        }
        __syncthreads();
    }

    int g4 = lane >> 2, t4 = lane & 3;

    if (mode == 2) {
        // gf epilogue: stage (re,im) pairs in smem [128][64] float2 = 64KB
        float2* sgf = (float2*)smh;
#pragma unroll
        for (int mi = 0; mi < 4; mi++) {
            int rl = wm*64 + mi*16 + g4;
#pragma unroll
            for (int ni = 0; ni < 4; ni++) {
                int chl = wn*16 + ni*4 + t4;
                sgf[rl*64 + chl]       = make_float2(acc[mi][ni][0], acc[mi][ni][1]);
                sgf[(rl+8)*64 + chl]   = make_float2(acc[mi][ni][2], acc[mi][ni][3]);
            }
        }
        __syncthreads();
        int rl = tid >> 1;
        int co = (tid & 1) * 32;
        int r = row0 + rl;
        int chbase = (n0 >> 1) + co;
        const float* gxp = &d_gX[(size_t)r * NC + chbase];
        const float* gyp = &d_gY[(size_t)r * NC + chbase];
        size_t ao = (size_t)r * 768 + 512 + chbase;
#pragma unroll
        for (int j0 = 0; j0 < 32; j0 += 8) {
            float4 gx0 = *(const float4*)(gxp + j0);
            float4 gx1 = *(const float4*)(gxp + j0 + 4);
            float4 gy0 = *(const float4*)(gyp + j0);
            float4 gy1 = *(const float4*)(gyp + j0 + 4);
            float4 t0, t1;
            float2 p;
            p = sgf[rl*64 + co + j0 + 0]; t0.x = tanhf(gx0.x*p.x + gy0.x*p.y);
            p = sgf[rl*64 + co + j0 + 1]; t0.y = tanhf(gx0.y*p.x + gy0.y*p.y);
            p = sgf[rl*64 + co + j0 + 2]; t0.z = tanhf(gx0.z*p.x + gy0.z*p.y);
            p = sgf[rl*64 + co + j0 + 3]; t0.w = tanhf(gx0.w*p.x + gy0.w*p.y);
            p = sgf[rl*64 + co + j0 + 4]; t1.x = tanhf(gx1.x*p.x + gy1.x*p.y);
            p = sgf[rl*64 + co + j0 + 5]; t1.y = tanhf(gx1.y*p.x + gy1.y*p.y);
            p = sgf[rl*64 + co + j0 + 6]; t1.z = tanhf(gx1.z*p.x + gy1.z*p.y);
            p = sgf[rl*64 + co + j0 + 7]; t1.w = tanhf(gx1.w*p.x + gy1.w*p.y);
            *(uint4*)&d_Af[ao + j0] = pack8h(t0, t1);
        }
        return;
    }

    // mode 0: standard epilogue
    float cs[4][2], cq[4][2];
#pragma unroll
    for (int ni = 0; ni < 4; ni++) { cs[ni][0]=cs[ni][1]=cq[ni][0]=cq[ni][1]=0.f; }

#pragma unroll
    for (int mi = 0; mi < 4; mi++) {
        int r = row0 + wm*64 + mi*16 + g4;
#pragma unroll
        for (int ni = 0; ni < 4; ni++) {
            int c = n0 + wn*32 + ni*8 + t4*2;
            float b0 = 0.f, b1 = 0.f;
            if (bias) { b0 = bias[c]; b1 = bias[c+1]; }
            float v0 = acc[mi][ni][0] + b0, v1 = acc[mi][ni][1] + b1;
            float v2 = acc[mi][ni][2] + b0, v3 = acc[mi][ni][3] + b1;
            *(float2*)&out[(size_t)r * ldout + c]     = make_float2(v0, v1);
            *(float2*)&out[(size_t)(r+8) * ldout + c] = make_float2(v2, v3);
            if (asplit_off >= 0) {
                *(uint32_t*)&d_Af[(size_t)r * 768 + asplit_off + c]     = pack2h(v0, v1);
                *(uint32_t*)&d_Af[(size_t)(r+8) * 768 + asplit_off + c] = pack2h(v2, v3);
            }
            cs[ni][0] += v0 + v2;  cq[ni][0] += v0*v0 + v2*v2;
            cs[ni][1] += v1 + v3;  cq[ni][1] += v1*v1 + v3*v3;
        }
    }
    if (stats) {
#pragma unroll
        for (int ni = 0; ni < 4; ni++) {
#pragma unroll
            for (int h = 0; h < 2; h++) {
                float s = cs[ni][h], q = cq[ni][h];
                s += __shfl_xor_sync(0xFFFFFFFFu, s, 4);
                q += __shfl_xor_sync(0xFFFFFFFFu, q, 4);
                s += __shfl_xor_sync(0xFFFFFFFFu, s, 8);
                q += __shfl_xor_sync(0xFFFFFFFFu, q, 8);
                s += __shfl_xor_sync(0xFFFFFFFFu, s, 16);
                q += __shfl_xor_sync(0xFFFFFFFFu, q, 16);
                if (g4 == 0) {
                    int c = n0 + wn*32 + ni*8 + t4*2 + h;
                    atomicAdd(&stats[c], s);
                    atomicAdd(&stats[256 + c], q);
                }
            }
        }
    }
}

// out = bn(h2) + x
__global__ void k_final(const float* __restrict__ x, const float* __restrict__ g,
                        const float* __restrict__ be, float* __restrict__ out) {
    int tid = threadIdx.x;
    __shared__ float sc[256], sh[256];
    {
        float mean = d_stats[1024 + tid] * (1.0f / NN);
        float var  = d_stats[1280 + tid] * (1.0f / NN) - mean * mean;
        float s = rsqrtf(var + BNEPS) * g[tid];
        sc[tid] = s;
        sh[tid] = be[tid] - mean * s;
    }
    __syncthreads();
    size_t i = (size_t)(blockIdx.x * 256 + tid) * 4;
    int c = (int)(i & 255);
    float4 h  = *(float4*)&d_h2[i];
    float4 xv = *(const float4*)&x[i];
    float4 o;
    o.x = h.x * sc[c+0] + sh[c+0] + xv.x;
    o.y = h.y * sc[c+1] + sh[c+1] + xv.y;
    o.z = h.z * sc[c+2] + sh[c+2] + xv.z;
    o.w = h.w * sc[c+3] + sh[c+3] + xv.w;
    *(float4*)&out[i] = o;
}

// ------------------------------- launch --------------------------------------
extern "C" void kernel_launch(void* const* d_in, const int* in_sizes, int n_in,
                              void* d_out, int out_size) {
    const float* x       = (const float*)d_in[0];
    const float* mass    = (const float*)d_in[1];
    const float* evals   = (const float*)d_in[2];
    const float* evecs   = (const float*)d_in[3];
    const int*   gx_rows = (const int*)  d_in[4];
    const int*   gx_cols = (const int*)  d_in[5];
    const float* gx_vals = (const float*)d_in[6];
    const int*   gy_rows = (const int*)  d_in[7];
    const int*   gy_cols = (const int*)  d_in[8];
    const float* gy_vals = (const float*)d_in[9];
    const float* dt      = (const float*)d_in[10];
    const float* A_re    = (const float*)d_in[11];
    const float* A_im    = (const float*)d_in[12];
    const float* W0      = (const float*)d_in[13];
    const float* b0      = (const float*)d_in[14];
    const float* g0      = (const float*)d_in[15];
    const float* be0     = (const float*)d_in[16];
    const float* W1      = (const float*)d_in[17];
    const float* b1      = (const float*)d_in[18];
    const float* g1      = (const float*)d_in[19];
    const float* be1     = (const float*)d_in[20];
    const float* W2      = (const float*)d_in[21];
    const float* b2      = (const float*)d_in[22];
    const float* g2      = (const float*)d_in[23];
    const float* be2     = (const float*)d_in[24];
    float* out = (float*)d_out;

    static int smem_set = 0;
    if (!smem_set) {
        cudaFuncSetAttribute(k_xspec_mma, cudaFuncAttributeMaxDynamicSharedMemorySize, GEMM_SMEM);
        cudaFuncSetAttribute(k_mma_h, cudaFuncAttributeMaxDynamicSharedMemorySize, HSMEM);
        smem_set = 1;
    }

    __half *Af, *GhF, *BhC, *BlC, *BhW, *BlW, *eF, *ytHf, *ytLf;
    float *h0, *h1, *h2, *stats, *xd;
    cudaGetSymbolAddress((void**)&Af, d_Af);
    cudaGetSymbolAddress((void**)&GhF, d_GhF);
    cudaGetSymbolAddress((void**)&BhC, d_BhC);
    cudaGetSymbolAddress((void**)&BlC, d_BlC);
    cudaGetSymbolAddress((void**)&BhW, d_BhW);
    cudaGetSymbolAddress((void**)&BlW, d_BlW);
    cudaGetSymbolAddress((void**)&eF, d_eF);
    cudaGetSymbolAddress((void**)&ytHf, d_ytHf);
    cudaGetSymbolAddress((void**)&ytLf, d_ytLf);
    cudaGetSymbolAddress((void**)&h0, d_h0);
    cudaGetSymbolAddress((void**)&h1, d_h1);
    cudaGetSymbolAddress((void**)&h2, d_h2);
    cudaGetSymbolAddress((void**)&stats, d_stats);
    cudaGetSymbolAddress((void**)&xd, d_xd);

    k_zero<<<256, 256>>>();
    k_trans_mevecs<<<dim3(256, 4, 8), 256>>>(evecs, mass);
    k_trans_x<<<dim3(256, 8, 8), 256>>>(x);
    k_xspec_mma<<<dim3(32, 2, 8), 256, GEMM_SMEM>>>();
    k_coefT<<<256, 256>>>(evals, dt);
    // x_diffuse = evecs @ yT^T (fp16 2-MMA, per-batch B); split into A [256..512)
    k_mma_h<<<dim3(2, 512), 256, HSMEM>>>(eF, NK, ytHf, ytLf,
                                          xd, 256, nullptr, NK, nullptr, NC*NK, 0, 256);
    // CSR build
    k_hist<<<4096, 256>>>(gx_rows, gy_rows);
    k_scan1<<<512, 256>>>();
    k_scan2<<<1, 512>>>();
    k_scan3<<<512, 256>>>();
    k_scatter<<<4096, 256>>>(gx_rows, gy_rows);
    // sparse gradients: float gX/gY + fp16 G operand
    k_spmm_csr<<<32768, 256>>>(gx_cols, gx_vals, gy_cols, gy_vals);

    // weight prep
    k_prep_cplxB<<<1024, 256>>>(A_re, A_im);
    k_prep_wT<<<768, 256>>>(W0, 768, 256, BOFF_W0);
    k_prep_wT<<<256, 256>>>(W1, 256, 256, BOFF_W1);
    k_prep_wT<<<256, 256>>>(W2, 256, 256, BOFF_W2);

    // cplx GEMM (fp16 2-MMA) with fused tanh epilogue -> A cols [512..768)
    k_mma_h<<<dim3(4, 512), 256, HSMEM>>>(GhF, 512, BhC, BlC,
                                          h0, 512, nullptr, 512, nullptr, 0, 2, -1);

    // MLP (fp16 2-MMA, stats fused)
    k_mma_h<<<dim3(2, 512), 256, HSMEM>>>(Af, 768, BhW + BOFF_W0, BlW + BOFF_W0,
                                          h0, 256, b0, 768, stats, 0, 0, -1);
    k_bnsplit<<<8192, 256>>>(h0, 0, g0, be0);
    k_mma_h<<<dim3(2, 512), 256, HSMEM>>>(Af, 768, BhW + BOFF_W1, BlW + BOFF_W1,
                                          h1, 256, b1, 256, stats + 512, 0, 0, -1);
    k_bnsplit<<<8192, 256>>>(h1, 512, g1, be1);
    k_mma_h<<<dim3(2, 512), 256, HSMEM>>>(Af, 768, BhW + BOFF_W2, BlW + BOFF_W2,
                                          h2, 256, b2, 256, stats + 1024, 0, 0, -1);
    k_final<<<16384, 256>>>(x, g2, be2, out);
}

// round 16
// speedup vs baseline: 1.3497x; 1.0675x over previous
#include <cuda_runtime.h>
#include <cuda_bf16.h>
#include <cuda_fp16.h>
#include <math.h>
#include <cstdint>

#define NB 8
#define NV 8192
#define NK 128
#define NC 256
#define NN 65536          // NB*NV
#define NNZ 1048576       // 16*NN
#define BNEPS 1e-5f

// ------------------------- scratch (device globals) -------------------------
static __device__ float d_xspec[NB*NK*NC];
static __device__ float d_gX  [NN*NC];
static __device__ float d_gY  [NN*NC];
static __device__ float d_h0  [NN*NC];
static __device__ float d_h1  [NN*NC];
static __device__ float d_h2  [NN*NC];
static __device__ float d_stats[1536];
// CSR build scratch
static __device__ int d_cnt [131072];
static __device__ int d_off [131072];
static __device__ int d_bsum[512];
static __device__ int d_perm[2*NNZ];
// fp16 single A for MLP: [NN, 768]  (cols: x | xd | gf)  — xd cols also feed spmm
static __device__ __half d_Af[(size_t)NN*768];
// fp16 single [gX|gY] operand for cplx GEMM: [NN, 512]
static __device__ __half d_GhF[(size_t)NN*512];
// fp16 split cplx-interleaved B: [512, 512]
static __device__ __half d_BhC[262144];
static __device__ __half d_BlC[262144];
// fp16 split W pool: W0T(256x768) | W1T | W2T
#define BOFF_W0   0
#define BOFF_W1   196608
#define BOFF_W2   262144
static __device__ __half d_BhW[327680];
static __device__ __half d_BlW[327680];
// xdiff operands: evecs fp16 single; yt fp16 split
static __device__ __half d_eF[(size_t)NN*NK];
static __device__ __half d_ytHf[NB*NC*NK];
static __device__ __half d_ytLf[NB*NC*NK];
// spectral operands for xspec (bf16 split, accuracy anchor)
static __device__ __nv_bfloat16 d_mtH[(size_t)NB*NK*NV];
static __device__ __nv_bfloat16 d_mtL[(size_t)NB*NK*NV];
static __device__ __nv_bfloat16 d_xtH[(size_t)NB*NC*NV];
static __device__ __nv_bfloat16 d_xtL[(size_t)NB*NC*NV];

__device__ __forceinline__ uint32_t smem_u32(const void* p) {
    uint32_t a;
    asm("{ .reg .u64 t; cvta.to.shared.u64 t, %1; cvt.u32.u64 %0, t; }" : "=r"(a) : "l"(p));
    return a;
}

struct SplitPack4 { uint2 hi, lo; };
__device__ __forceinline__ SplitPack4 split4bf(const float* v) {
    union { __nv_bfloat16 h[4]; uint2 u; } H;
    union { __nv_bfloat16 h[4]; uint2 u; } L;
#pragma unroll
    for (int j = 0; j < 4; j++) {
        __nv_bfloat16 hh = __float2bfloat16(v[j]);
        H.h[j] = hh;
        L.h[j] = __float2bfloat16(v[j] - __bfloat162float(hh));
    }
    SplitPack4 r; r.hi = H.u; r.lo = L.u; return r;
}
__device__ __forceinline__ uint2 pack4h(const float* v) {
    union { __half h[4]; uint2 u; } P;
#pragma unroll
    for (int j = 0; j < 4; j++) P.h[j] = __float2half(v[j]);
    return P.u;
}
__device__ __forceinline__ uint4 pack8h(float4 a, float4 b) {
    union { __half h[8]; uint4 u; } P;
    P.h[0] = __float2half(a.x); P.h[1] = __float2half(a.y);
    P.h[2] = __float2half(a.z); P.h[3] = __float2half(a.w);
    P.h[4] = __float2half(b.x); P.h[5] = __float2half(b.y);
    P.h[6] = __float2half(b.z); P.h[7] = __float2half(b.w);
    return P.u;
}
__device__ __forceinline__ uint32_t pack2h(float a, float b) {
    union { __half h[2]; uint32_t u; } P;
    P.h[0] = __float2half(a); P.h[1] = __float2half(b);
    return P.u;
}
__device__ __forceinline__ void splith(float v, __half* ph, __half* pl) {
    __half h = __float2half(v);
    *ph = h;
    *pl = __float2half(v - __half2float(h));
}

// ------------------------------- zero init ----------------------------------
__global__ void k_zero() {
    int i = blockIdx.x * 256 + threadIdx.x;     // < 65536
    float4 z = make_float4(0.f, 0.f, 0.f, 0.f);
    *(float4*)&d_xspec[i * 4] = z;
    if (i < 32768) *(int4*)&d_cnt[i * 4] = make_int4(0, 0, 0, 0);
    if (i < 384)   *(float4*)&d_stats[i * 4] = z;
}

// ========================= CSR build (both matrices) =========================
__global__ void k_hist(const int* __restrict__ gxr, const int* __restrict__ gyr) {
    int i = blockIdx.x * 256 + threadIdx.x;
    atomicAdd(&d_cnt[gxr[i]], 1);
    atomicAdd(&d_cnt[65536 + gyr[i]], 1);
}

__global__ void k_scan1() {
    __shared__ int sh[256];
    int tid = threadIdx.x;
    int i = blockIdx.x * 256 + tid;
    int v = d_cnt[i];
    sh[tid] = v;
    __syncthreads();
    for (int o = 1; o < 256; o <<= 1) {
        int t = (tid >= o) ? sh[tid - o] : 0;
        __syncthreads();
        sh[tid] += t;
        __syncthreads();
    }
    d_off[i] = sh[tid] - v;
    if (tid == 255) d_bsum[blockIdx.x] = sh[255];
}

__global__ void k_scan2() {
    __shared__ int sh[512];
    int tid = threadIdx.x;
    int v = d_bsum[tid];
    sh[tid] = v;
    __syncthreads();
    for (int o = 1; o < 512; o <<= 1) {
        int t = (tid >= o) ? sh[tid - o] : 0;
        __syncthreads();
        sh[tid] += t;
        __syncthreads();
    }
    d_bsum[tid] = sh[tid] - v;
}

__global__ void k_scan3() {
    int i = blockIdx.x * 256 + threadIdx.x;
    int v = d_off[i] + d_bsum[i >> 8];
    d_off[i] = v;
    d_cnt[i] = v;
}

__global__ void k_scatter(const int* __restrict__ gxr, const int* __restrict__ gyr) {
    int i = blockIdx.x * 256 + threadIdx.x;
    int p = atomicAdd(&d_cnt[gxr[i]], 1);
    d_perm[p] = i;
    int q = atomicAdd(&d_cnt[65536 + gyr[i]], 1);
    d_perm[q] = i;
}

// merged CSR spmm: gathers fp16 xd from d_Af cols [256..512).
// float out (gX/gY) + fp16 into G operand. grid 32768, 256 thr
__global__ __launch_bounds__(256) void k_spmm_csr(
    const int* __restrict__ gxc, const float* __restrict__ gxv,
    const int* __restrict__ gyc, const float* __restrict__ gyv) {
    int g = threadIdx.x >> 6, t = threadIdx.x & 63;
    int idx = blockIdx.x * 4 + g;               // < 131072
    int isX = (idx < 65536);
    const int*   cols = isX ? gxc : gyc;
    const float* vals = isX ? gxv : gyv;
    float* out        = isX ? d_gX : d_gY;
    int r = idx & 65535;
    int s = d_off[idx], e = d_cnt[idx];
    int c = t * 4;
    const __half* xdF = d_Af + 256 + c;         // row stride 768
    float4 acc = make_float4(0.f, 0.f, 0.f, 0.f);
    int p = s;
    for (; p + 4 <= e; p += 4) {
        int e0 = d_perm[p], e1 = d_perm[p+1], e2 = d_perm[p+2], e3 = d_perm[p+3];
        int c0 = cols[e0], c1 = cols[e1], c2 = cols[e2], c3 = cols[e3];
        float v0 = vals[e0], v1 = vals[e1], v2 = vals[e2], v3 = vals[e3];
        uint2 r0 = *(const uint2*)&xdF[(size_t)c0 * 768];
        uint2 r1 = *(const uint2*)&xdF[(size_t)c1 * 768];
        uint2 r2 = *(const uint2*)&xdF[(size_t)c2 * 768];
        uint2 r3 = *(const uint2*)&xdF[(size_t)c3 * 768];
        float2 a0 = __half22float2(*(__half2*)&r0.x), b0 = __half22float2(*(__half2*)&r0.y);
        float2 a1 = __half22float2(*(__half2*)&r1.x), b1 = __half22float2(*(__half2*)&r1.y);
        float2 a2 = __half22float2(*(__half2*)&r2.x), b2 = __half22float2(*(__half2*)&r2.y);
        float2 a3 = __half22float2(*(__half2*)&r3.x), b3 = __half22float2(*(__half2*)&r3.y);
        acc.x += v0*a0.x + v1*a1.x + v2*a2.x + v3*a3.x;
        acc.y += v0*a0.y + v1*a1.y + v2*a2.y + v3*a3.y;
        acc.z += v0*b0.x + v1*b1.x + v2*b2.x + v3*b3.x;
        acc.w += v0*b0.y + v1*b1.y + v2*b2.y + v3*b3.y;
    }
    for (; p < e; p++) {
        int ed = d_perm[p];
        int cl = cols[ed];
        float v = vals[ed];
        uint2 r0 = *(const uint2*)&xdF[(size_t)cl * 768];
        float2 a0 = __half22float2(*(__half2*)&r0.x), b0 = __half22float2(*(__half2*)&r0.y);
        acc.x += v*a0.x; acc.y += v*a0.y; acc.z += v*b0.x; acc.w += v*b0.y;
    }
    *(float4*)&out[(size_t)r * NC + c] = acc;
    *(uint2*)&d_GhF[(size_t)r * 512 + (isX ? 0 : 256) + c] = pack4h(&acc.x);
}

// ===================== spectral operand preparation ==========================
__global__ __launch_bounds__(256) void k_trans_mevecs(
    const float* __restrict__ evecs, const float* __restrict__ mass) {
    __shared__ float tile[32][33];
    __shared__ float smass[32];
    int v0 = blockIdx.x * 32, k0 = blockIdx.y * 32, b = blockIdx.z;
    int tid = threadIdx.x;
    int tx = tid & 31, ty = tid >> 5;
    if (tid < 32) smass[tid] = mass[b * NV + v0 + tid];
#pragma unroll
    for (int i = 0; i < 4; i++) {
        int vl = ty + i * 8;
        tile[vl][tx] = evecs[(size_t)(b * NV + v0 + vl) * NK + k0 + tx];
    }
    __syncthreads();
    {
        int k = tid >> 3, vq = (tid & 7) * 4;
        float v[4];
#pragma unroll
        for (int j = 0; j < 4; j++) v[j] = tile[vq + j][k] * smass[vq + j];
        SplitPack4 p = split4bf(v);
        size_t o = (size_t)(b * NK + k0 + k) * NV + v0 + vq;
        *(uint2*)&d_mtH[o] = p.hi;
        *(uint2*)&d_mtL[o] = p.lo;
    }
    {
        int v = tid >> 3, kq = (tid & 7) * 4;
        float w[4];
#pragma unroll
        for (int j = 0; j < 4; j++) w[j] = tile[v][kq + j];
        size_t o = (size_t)(b * NV + v0 + v) * NK + k0 + kq;
        *(uint2*)&d_eF[o] = pack4h(w);
    }
}

__global__ __launch_bounds__(256) void k_trans_x(const float* __restrict__ x) {
    __shared__ float tile[32][33];
    int v0 = blockIdx.x * 32, c0 = blockIdx.y * 32, b = blockIdx.z;
    int tid = threadIdx.x;
    int tx = tid & 31, ty = tid >> 5;
#pragma unroll
    for (int i = 0; i < 4; i++) {
        int vl = ty + i * 8;
        tile[vl][tx] = x[(size_t)(b * NV + v0 + vl) * NC + c0 + tx];
    }
    __syncthreads();
    {
        int c = tid >> 3, vq = (tid & 7) * 4;
        float v[4];
#pragma unroll
        for (int j = 0; j < 4; j++) v[j] = tile[vq + j][c];
        SplitPack4 p = split4bf(v);
        size_t o = (size_t)(b * NC + c0 + c) * NV + v0 + vq;
        *(uint2*)&d_xtH[o] = p.hi;
        *(uint2*)&d_xtL[o] = p.lo;
    }
    {
        int v = tid >> 3, cq = (tid & 7) * 4;
        float w[4];
#pragma unroll
        for (int j = 0; j < 4; j++) w[j] = tile[v][cq + j];
        size_t o = (size_t)(b * NV + v0 + v) * 768 + c0 + cq;
        *(uint2*)&d_Af[o] = pack4h(w);
    }
}

__global__ void k_coefT(const float* __restrict__ evals, const float* __restrict__ dt) {
    int i = blockIdx.x * 256 + threadIdx.x;   // < 65536
    int kq = (i & 31) * 4;
    int c  = (i >> 5) & 255;
    int b  = i >> 13;
    float t = fmaxf(dt[c], 1e-8f);
    union { __half h[4]; uint2 u; } H, L;
#pragma unroll
    for (int j = 0; j < 4; j++) {
        float v = expf(-evals[b * NK + kq + j] * t) * d_xspec[(b * NK + kq + j) * NC + c];
        __half hh = __float2half(v);
        H.h[j] = hh;
        L.h[j] = __float2half(v - __half2float(hh));
    }
    int o = b * (NC * NK) + c * NK + kq;
    *(uint2*)&d_ytHf[o] = H.u;
    *(uint2*)&d_ytLf[o] = L.u;
}

// ============================ mma primitives =================================
__device__ __forceinline__ void ldsm_x4(uint32_t* r, uint32_t addr) {
    asm volatile("ldmatrix.sync.aligned.m8n8.x4.shared.b16 {%0,%1,%2,%3}, [%4];"
                 : "=r"(r[0]), "=r"(r[1]), "=r"(r[2]), "=r"(r[3]) : "r"(addr));
}
__device__ __forceinline__ void ldsm_x2(uint32_t* r, uint32_t addr) {
    asm volatile("ldmatrix.sync.aligned.m8n8.x2.shared.b16 {%0,%1}, [%2];"
                 : "=r"(r[0]), "=r"(r[1]) : "r"(addr));
}
__device__ __forceinline__ void mma16816(float* c, const uint32_t* a, const uint32_t* b) {
    asm volatile("mma.sync.aligned.m16n8k16.row.col.f32.bf16.bf16.f32 "
                 "{%0,%1,%2,%3}, {%4,%5,%6,%7}, {%8,%9}, {%0,%1,%2,%3};"
                 : "+f"(c[0]), "+f"(c[1]), "+f"(c[2]), "+f"(c[3])
                 : "r"(a[0]), "r"(a[1]), "r"(a[2]), "r"(a[3]), "r"(b[0]), "r"(b[1]));
}
__device__ __forceinline__ void mma16816h(float* c, const uint32_t* a, const uint32_t* b) {
    asm volatile("mma.sync.aligned.m16n8k16.row.col.f32.f16.f16.f32 "
                 "{%0,%1,%2,%3}, {%4,%5,%6,%7}, {%8,%9}, {%0,%1,%2,%3};"
                 : "+f"(c[0]), "+f"(c[1]), "+f"(c[2]), "+f"(c[3])
                 : "r"(a[0]), "r"(a[1]), "r"(a[2]), "r"(a[3]), "r"(b[0]), "r"(b[1]));
}
#define CP_ASYNC(sm, gm) \
    asm volatile("cp.async.cg.shared.global [%0], [%1], 16;" :: "r"(sm), "l"(gm))
#define CP_ASYNC_CA(sm, gm) \
    asm volatile("cp.async.ca.shared.global [%0], [%1], 16;" :: "r"(sm), "l"(gm))
#define CP_COMMIT() asm volatile("cp.async.commit_group;" ::: "memory")
#define CP_WAIT(n)  asm volatile("cp.async.wait_group %0;" :: "n"(n) : "memory")

#define ASTR 40
#define TILEEL (128*ASTR)
#define GEMM_SMEM (2*4*TILEEL*2)   // xspec bf16 kernel: 81920
#define SLOT3 (TILEEL*2)           // 10240 bytes
#define HSMEM 65536                // fp16 kernel

// ------------------- x_spec split-K mma (bf16 3-term): grid (32, 2, 8) -------
__global__ __launch_bounds__(256, 2) void k_xspec_mma() {
    extern __shared__ __align__(16) __nv_bfloat16 sm[];
    int tid = threadIdx.x;
    int wid = tid >> 5, lane = tid & 31;
    int wm = wid & 1, wn = wid >> 1;
    int kb = blockIdx.x, ch = blockIdx.y, b = blockIdx.z;
    const __nv_bfloat16* Ah = d_mtH + (size_t)b * NK * NV;
    const __nv_bfloat16* Al = d_mtL + (size_t)b * NK * NV;
    const __nv_bfloat16* Bh = d_xtH + (size_t)(b * NC + ch * 128) * NV;
    const __nv_bfloat16* Bl = d_xtL + (size_t)(b * NC + ch * 128) * NV;
    int kbase = kb * 256;

    float acc[4][4][4];
#pragma unroll
    for (int mi = 0; mi < 4; mi++)
#pragma unroll
        for (int ni = 0; ni < 4; ni++)
#pragma unroll
            for (int q = 0; q < 4; q++) acc[mi][ni][q] = 0.f;

    int idx0 = tid * 2, idx1 = tid * 2 + 1;
    int lr0 = idx0 >> 2, ls0 = idx0 & 3;
    int lr1 = idx1 >> 2, ls1 = idx1 & 3;
    uint32_t so0 = (uint32_t)(lr0 * ASTR + ls0 * 8) * 2;
    uint32_t so1 = (uint32_t)(lr1 * ASTR + ls1 * 8) * 2;
    uint32_t smbase = smem_u32(sm);

#define XLOAD(s) do { \
    uint32_t sb = smbase + (uint32_t)((s) & 1) * 4u * TILEEL * 2u; \
    int k0 = kbase + ((s) << 5); \
    CP_ASYNC(sb + so0, Ah + (size_t)lr0 * NV + k0 + ls0*8); \
    CP_ASYNC(sb + so1, Ah + (size_t)lr1 * NV + k0 + ls1*8); \
    CP_ASYNC(sb + TILEEL*2 + so0, Al + (size_t)lr0 * NV + k0 + ls0*8); \
    CP_ASYNC(sb + TILEEL*2 + so1, Al + (size_t)lr1 * NV + k0 + ls1*8); \
    CP_ASYNC(sb + 2*TILEEL*2 + so0, Bh + (size_t)lr0 * NV + k0 + ls0*8); \
    CP_ASYNC(sb + 2*TILEEL*2 + so1, Bh + (size_t)lr1 * NV + k0 + ls1*8); \
    CP_ASYNC(sb + 3*TILEEL*2 + so0, Bl + (size_t)lr0 * NV + k0 + ls0*8); \
    CP_ASYNC(sb + 3*TILEEL*2 + so1, Bl + (size_t)lr1 * NV + k0 + ls1*8); \
} while (0)

    XLOAD(0);
    CP_COMMIT();

    int arow = (lane & 15), acol = (lane >> 4) * 8;
    int brow = (lane & 7),  bcol = ((lane >> 3) & 1) * 8;

    for (int s = 0; s < 8; s++) {
        if (s + 1 < 8) { XLOAD(s + 1); CP_COMMIT(); CP_WAIT(1); }
        else           { CP_WAIT(0); }
        __syncthreads();
        uint32_t sb = smbase + (uint32_t)(s & 1) * 4u * TILEEL * 2u;
        uint32_t Ah_s = sb, Al_s = sb + TILEEL*2, Bh_s = sb + 2*TILEEL*2, Bl_s = sb + 3*TILEEL*2;
#pragma unroll
        for (int ks = 0; ks < 2; ks++) {
            int k0 = ks * 16;
            uint32_t aH[4][4], aL[4][4];
#pragma unroll
            for (int mi = 0; mi < 4; mi++) {
                uint32_t off = (uint32_t)((wm*64 + mi*16 + arow) * ASTR + k0 + acol) * 2;
                ldsm_x4(aH[mi], Ah_s + off);
                ldsm_x4(aL[mi], Al_s + off);
            }
            uint32_t bH[4][2], bL[4][2];
#pragma unroll
            for (int ni = 0; ni < 4; ni++) {
                uint32_t off = (uint32_t)((wn*32 + ni*8 + brow) * ASTR + k0 + bcol) * 2;
                ldsm_x2(bH[ni], Bh_s + off);
                ldsm_x2(bL[ni], Bl_s + off);
            }
#pragma unroll
            for (int mi = 0; mi < 4; mi++)
#pragma unroll
                for (int ni = 0; ni < 4; ni++)
                    mma16816(acc[mi][ni], aH[mi], bH[ni]);
#pragma unroll
            for (int mi = 0; mi < 4; mi++)
#pragma unroll
                for (int ni = 0; ni < 4; ni++)
                    mma16816(acc[mi][ni], aH[mi], bL[ni]);
#pragma unroll
            for (int mi = 0; mi < 4; mi++)
#pragma unroll
                for (int ni = 0; ni < 4; ni++)
                    mma16816(acc[mi][ni], aL[mi], bH[ni]);
        }
        __syncthreads();
    }

    int g4 = lane >> 2, t4 = lane & 3;
#pragma unroll
    for (int mi = 0; mi < 4; mi++) {
        int r = wm*64 + mi*16 + g4;
#pragma unroll
        for (int ni = 0; ni < 4; ni++) {
            int c = ch*128 + wn*32 + ni*8 + t4*2;
            float* o0 = &d_xspec[(b*NK + r) * NC + c];
            float* o1 = &d_xspec[(b*NK + r + 8) * NC + c];
            asm volatile("red.global.add.v2.f32 [%0], {%1,%2};"
                         :: "l"(o0), "f"(acc[mi][ni][0]), "f"(acc[mi][ni][1]) : "memory");
            asm volatile("red.global.add.v2.f32 [%0], {%1,%2};"
                         :: "l"(o1), "f"(acc[mi][ni][2]), "f"(acc[mi][ni][3]) : "memory");
        }
    }
}

// ========================== B-operand prep ==================================
__global__ void k_prep_cplxB(const float* __restrict__ Are, const float* __restrict__ Aim) {
    int i = blockIdx.x * 256 + threadIdx.x;   // < 262144
    int n = i >> 9, k = i & 511;
    int m = n >> 1;
    float v;
    if ((n & 1) == 0) v = (k < 256) ? Are[m*256 + k] : -Aim[m*256 + (k-256)];
    else              v = (k < 256) ? Aim[m*256 + k] :  Are[m*256 + (k-256)];
    splith(v, &d_BhC[i], &d_BlC[i]);
}

__global__ void k_prep_wT(const float* __restrict__ W, int K, int N, int off) {
    int i = blockIdx.x * 256 + threadIdx.x;
    if (i >= N * K) return;
    int n = i / K, k = i % K;
    splith(W[k*N + n], &d_BhW[off + i], &d_BlW[off + i]);
}

// relu(bn(h)) -> A cols [0..255] (fp16). grid 8192, 256 thr
__global__ void k_bnsplit(const float* __restrict__ h, int statoff,
                          const float* __restrict__ g, const float* __restrict__ be) {
    int tid = threadIdx.x;
    __shared__ float sc[256], sh[256];
    {
        float mean = d_stats[statoff + tid] * (1.0f / NN);
        float var  = d_stats[statoff + 256 + tid] * (1.0f / NN) - mean * mean;
        float s = rsqrtf(var + BNEPS) * g[tid];
        sc[tid] = s;
        sh[tid] = be[tid] - mean * s;
    }
    __syncthreads();
    int idx = blockIdx.x * 256 + tid;          // < 2097152
    size_t row = idx >> 5;
    int c = (idx & 31) * 8;
    size_t o = row * 256 + c;
    float4 h0 = *(const float4*)&h[o], h1 = *(const float4*)&h[o + 4];
    float4 v0, v1;
    v0.x = fmaxf(h0.x * sc[c+0] + sh[c+0], 0.f);
    v0.y = fmaxf(h0.y * sc[c+1] + sh[c+1], 0.f);
    v0.z = fmaxf(h0.z * sc[c+2] + sh[c+2], 0.f);
    v0.w = fmaxf(h0.w * sc[c+3] + sh[c+3], 0.f);
    v1.x = fmaxf(h1.x * sc[c+4] + sh[c+4], 0.f);
    v1.y = fmaxf(h1.y * sc[c+5] + sh[c+5], 0.f);
    v1.z = fmaxf(h1.z * sc[c+6] + sh[c+6], 0.f);
    v1.w = fmaxf(h1.w * sc[c+7] + sh[c+7], 0.f);
    *(uint4*)&d_Af[row * 768 + c] = pack8h(v0, v1);
}

// =================== generic fp16 2-MMA GEMM =================================
// C = A(single fp16) @ (Bh+Bl)(fp16 split)^T.  grid (N/128, M/128), 256 thr.
// mode 0: optional float out+bias (+stats, +fp16 asplit); mode 2: gf epilogue.
__global__ __launch_bounds__(256, 2) void k_mma_h(
    const __half* __restrict__ Af, int ldA,
    const __half* __restrict__ Bh, const __half* __restrict__ Bl,
    float* __restrict__ out, int ldout, const float* __restrict__ bias, int K,
    float* __restrict__ stats, int bstrideB, int mode, int asplit_off)
{
    extern __shared__ __align__(16) __half smh[];
    int tid = threadIdx.x;
    int wid = tid >> 5, lane = tid & 31;
    int wm = wid & 1, wn = wid >> 1;
    int row0 = blockIdx.y * 128, n0 = blockIdx.x * 128;
    if (bstrideB) {
        int b = row0 / NV;
        Bh += (size_t)b * bstrideB;
        Bl += (size_t)b * bstrideB;
    }
    const int S = K >> 5;

    float acc[4][4][4];
#pragma unroll
    for (int mi = 0; mi < 4; mi++)
#pragma unroll
        for (int ni = 0; ni < 4; ni++)
#pragma unroll
            for (int q = 0; q < 4; q++) acc[mi][ni][q] = 0.f;

    int idx0 = tid * 2, idx1 = tid * 2 + 1;
    int lr0 = idx0 >> 2, ls0 = idx0 & 3;
    int lr1 = idx1 >> 2, ls1 = idx1 & 3;
    uint32_t so0 = (uint32_t)(lr0 * ASTR + ls0 * 8) * 2;
    uint32_t so1 = (uint32_t)(lr1 * ASTR + ls1 * 8) * 2;
    uint32_t smbase = smem_u32(smh);

#define HLOAD(s) do { \
    uint32_t sb = smbase + (uint32_t)((s) & 1) * 3u * (uint32_t)SLOT3; \
    int k0 = (s) << 5; \
    CP_ASYNC(sb + so0, Af + (size_t)(row0 + lr0) * ldA + k0 + ls0*8); \
    CP_ASYNC(sb + so1, Af + (size_t)(row0 + lr1) * ldA + k0 + ls1*8); \
    CP_ASYNC_CA(sb + SLOT3 + so0, Bh + (size_t)(n0 + lr0) * K + k0 + ls0*8); \
    CP_ASYNC_CA(sb + SLOT3 + so1, Bh + (size_t)(n0 + lr1) * K + k0 + ls1*8); \
    CP_ASYNC_CA(sb + 2*SLOT3 + so0, Bl + (size_t)(n0 + lr0) * K + k0 + ls0*8); \
    CP_ASYNC_CA(sb + 2*SLOT3 + so1, Bl + (size_t)(n0 + lr1) * K + k0 + ls1*8); \
} while (0)

    HLOAD(0);
    CP_COMMIT();

    int arow = (lane & 15), acol = (lane >> 4) * 8;
    int brow = (lane & 7),  bcol = ((lane >> 3) & 1) * 8;

    for (int s = 0; s < S; s++) {
        if (s + 1 < S) { HLOAD(s + 1); CP_COMMIT(); CP_WAIT(1); }
        else           { CP_WAIT(0); }
        __syncthreads();
        uint32_t sb = smbase + (uint32_t)(s & 1) * 3u * (uint32_t)SLOT3;
        uint32_t A_s = sb, Bh_s = sb + SLOT3, Bl_s = sb + 2*SLOT3;
#pragma unroll
        for (int ks = 0; ks < 2; ks++) {
            int k0 = ks * 16;
            uint32_t aF[4][4];
#pragma unroll
            for (int mi = 0; mi < 4; mi++) {
                uint32_t off = (uint32_t)((wm*64 + mi*16 + arow) * ASTR + k0 + acol) * 2;
                ldsm_x4(aF[mi], A_s + off);
            }
            uint32_t bH[4][2], bL[4][2];
#pragma unroll
            for (int ni = 0; ni < 4; ni++) {
                uint32_t off = (uint32_t)((wn*32 + ni*8 + brow) * ASTR + k0 + bcol) * 2;
                ldsm_x2(bH[ni], Bh_s + off);
                ldsm_x2(bL[ni], Bl_s + off);
            }
#pragma unroll
            for (int mi = 0; mi < 4; mi++)
#pragma unroll
                for (int ni = 0; ni < 4; ni++)
                    mma16816h(acc[mi][ni], aF[mi], bH[ni]);
#pragma unroll
            for (int mi = 0; mi < 4; mi++)
#pragma unroll
                for (int ni = 0; ni < 4; ni++)
                    mma16816h(acc[mi][ni], aF[mi], bL[ni]);
        }
        __syncthreads();
    }

    int g4 = lane >> 2, t4 = lane & 3;

    if (mode == 2) {
        float2* sgf = (float2*)smh;
#pragma unroll
        for (int mi = 0; mi < 4; mi++) {
            int rl = wm*64 + mi*16 + g4;
#pragma unroll
            for (int ni = 0; ni < 4; ni++) {
                int chl = wn*16 + ni*4 + t4;
                sgf[rl*64 + chl]       = make_float2(acc[mi][ni][0], acc[mi][ni][1]);
                sgf[(rl+8)*64 + chl]   = make_float2(acc[mi][ni][2], acc[mi][ni][3]);
            }
        }
        __syncthreads();
        int rl = tid >> 1;
        int co = (tid & 1) * 32;
        int r = row0 + rl;
        int chbase = (n0 >> 1) + co;
        const float* gxp = &d_gX[(size_t)r * NC + chbase];
        const float* gyp = &d_gY[(size_t)r * NC + chbase];
        size_t ao = (size_t)r * 768 + 512 + chbase;
#pragma unroll
        for (int j0 = 0; j0 < 32; j0 += 8) {
            float4 gx0 = *(const float4*)(gxp + j0);
            float4 gx1 = *(const float4*)(gxp + j0 + 4);
            float4 gy0 = *(const float4*)(gyp + j0);
            float4 gy1 = *(const float4*)(gyp + j0 + 4);
            float4 t0, t1;
            float2 p;
            p = sgf[rl*64 + co + j0 + 0]; t0.x = tanhf(gx0.x*p.x + gy0.x*p.y);
            p = sgf[rl*64 + co + j0 + 1]; t0.y = tanhf(gx0.y*p.x + gy0.y*p.y);
            p = sgf[rl*64 + co + j0 + 2]; t0.z = tanhf(gx0.z*p.x + gy0.z*p.y);
            p = sgf[rl*64 + co + j0 + 3]; t0.w = tanhf(gx0.w*p.x + gy0.w*p.y);
            p = sgf[rl*64 + co + j0 + 4]; t1.x = tanhf(gx1.x*p.x + gy1.x*p.y);
            p = sgf[rl*64 + co + j0 + 5]; t1.y = tanhf(gx1.y*p.x + gy1.y*p.y);
            p = sgf[rl*64 + co + j0 + 6]; t1.z = tanhf(gx1.z*p.x + gy1.z*p.y);
            p = sgf[rl*64 + co + j0 + 7]; t1.w = tanhf(gx1.w*p.x + gy1.w*p.y);
            *(uint4*)&d_Af[ao + j0] = pack8h(t0, t1);
        }
        return;
    }

    // mode 0
    float cs[4][2], cq[4][2];
#pragma unroll
    for (int ni = 0; ni < 4; ni++) { cs[ni][0]=cs[ni][1]=cq[ni][0]=cq[ni][1]=0.f; }

#pragma unroll
    for (int mi = 0; mi < 4; mi++) {
        int r = row0 + wm*64 + mi*16 + g4;
#pragma unroll
        for (int ni = 0; ni < 4; ni++) {
            int c = n0 + wn*32 + ni*8 + t4*2;
            float b0 = 0.f, b1 = 0.f;
            if (bias) { b0 = bias[c]; b1 = bias[c+1]; }
            float v0 = acc[mi][ni][0] + b0, v1 = acc[mi][ni][1] + b1;
            float v2 = acc[mi][ni][2] + b0, v3 = acc[mi][ni][3] + b1;
            if (out) {
                *(float2*)&out[(size_t)r * ldout + c]     = make_float2(v0, v1);
                *(float2*)&out[(size_t)(r+8) * ldout + c] = make_float2(v2, v3);
            }
            if (asplit_off >= 0) {
                *(uint32_t*)&d_Af[(size_t)r * 768 + asplit_off + c]     = pack2h(v0, v1);
                *(uint32_t*)&d_Af[(size_t)(r+8) * 768 + asplit_off + c] = pack2h(v2, v3);
            }
            cs[ni][0] += v0 + v2;  cq[ni][0] += v0*v0 + v2*v2;
            cs[ni][1] += v1 + v3;  cq[ni][1] += v1*v1 + v3*v3;
        }
    }
    if (stats) {
#pragma unroll
        for (int ni = 0; ni < 4; ni++) {
#pragma unroll
            for (int h = 0; h < 2; h++) {
                float s = cs[ni][h], q = cq[ni][h];
                s += __shfl_xor_sync(0xFFFFFFFFu, s, 4);
                q += __shfl_xor_sync(0xFFFFFFFFu, q, 4);
                s += __shfl_xor_sync(0xFFFFFFFFu, s, 8);
                q += __shfl_xor_sync(0xFFFFFFFFu, q, 8);
                s += __shfl_xor_sync(0xFFFFFFFFu, s, 16);
                q += __shfl_xor_sync(0xFFFFFFFFu, q, 16);
                if (g4 == 0) {
                    int c = n0 + wn*32 + ni*8 + t4*2 + h;
                    atomicAdd(&stats[c], s);
                    atomicAdd(&stats[256 + c], q);
                }
            }
        }
    }
}

// out = bn(h2) + x
__global__ void k_final(const float* __restrict__ x, const float* __restrict__ g,
                        const float* __restrict__ be, float* __restrict__ out) {
    int tid = threadIdx.x;
    __shared__ float sc[256], sh[256];
    {
        float mean = d_stats[1024 + tid] * (1.0f / NN);
        float var  = d_stats[1280 + tid] * (1.0f / NN) - mean * mean;
        float s = rsqrtf(var + BNEPS) * g[tid];
        sc[tid] = s;
        sh[tid] = be[tid] - mean * s;
    }
    __syncthreads();
    size_t i = (size_t)(blockIdx.x * 256 + tid) * 4;
    int c = (int)(i & 255);
    float4 h  = *(float4*)&d_h2[i];
    float4 xv = *(const float4*)&x[i];
    float4 o;
    o.x = h.x * sc[c+0] + sh[c+0] + xv.x;
    o.y = h.y * sc[c+1] + sh[c+1] + xv.y;
    o.z = h.z * sc[c+2] + sh[c+2] + xv.z;
    o.w = h.w * sc[c+3] + sh[c+3] + xv.w;
    *(float4*)&out[i] = o;
}

// ------------------------------- launch --------------------------------------
extern "C" void kernel_launch(void* const* d_in, const int* in_sizes, int n_in,
                              void* d_out, int out_size) {
    const float* x       = (const float*)d_in[0];
    const float* mass    = (const float*)d_in[1];
    const float* evals   = (const float*)d_in[2];
    const float* evecs   = (const float*)d_in[3];
    const int*   gx_rows = (const int*)  d_in[4];
    const int*   gx_cols = (const int*)  d_in[5];
    const float* gx_vals = (const float*)d_in[6];
    const int*   gy_rows = (const int*)  d_in[7];
    const int*   gy_cols = (const int*)  d_in[8];
    const float* gy_vals = (const float*)d_in[9];
    const float* dt      = (const float*)d_in[10];
    const float* A_re    = (const float*)d_in[11];
    const float* A_im    = (const float*)d_in[12];
    const float* W0      = (const float*)d_in[13];
    const float* b0      = (const float*)d_in[14];
    const float* g0      = (const float*)d_in[15];
    const float* be0     = (const float*)d_in[16];
    const float* W1      = (const float*)d_in[17];
    const float* b1      = (const float*)d_in[18];
    const float* g1      = (const float*)d_in[19];
    const float* be1     = (const float*)d_in[20];
    const float* W2      = (const float*)d_in[21];
    const float* b2      = (const float*)d_in[22];
    const float* g2      = (const float*)d_in[23];
    const float* be2     = (const float*)d_in[24];
    float* out = (float*)d_out;

    static int smem_set = 0;
    if (!smem_set) {
        cudaFuncSetAttribute(k_xspec_mma, cudaFuncAttributeMaxDynamicSharedMemorySize, GEMM_SMEM);
        cudaFuncSetAttribute(k_mma_h, cudaFuncAttributeMaxDynamicSharedMemorySize, HSMEM);
        smem_set = 1;
    }

    __half *Af, *GhF, *BhC, *BlC, *BhW, *BlW, *eF, *ytHf, *ytLf;
    float *h0, *h1, *h2, *stats;
    cudaGetSymbolAddress((void**)&Af, d_Af);
    cudaGetSymbolAddress((void**)&GhF, d_GhF);
    cudaGetSymbolAddress((void**)&BhC, d_BhC);
    cudaGetSymbolAddress((void**)&BlC, d_BlC);
    cudaGetSymbolAddress((void**)&BhW, d_BhW);
    cudaGetSymbolAddress((void**)&BlW, d_BlW);
    cudaGetSymbolAddress((void**)&eF, d_eF);
    cudaGetSymbolAddress((void**)&ytHf, d_ytHf);
    cudaGetSymbolAddress((void**)&ytLf, d_ytLf);
    cudaGetSymbolAddress((void**)&h0, d_h0);
    cudaGetSymbolAddress((void**)&h1, d_h1);
    cudaGetSymbolAddress((void**)&h2, d_h2);
    cudaGetSymbolAddress((void**)&stats, d_stats);

    k_zero<<<256, 256>>>();
    k_trans_mevecs<<<dim3(256, 4, 8), 256>>>(evecs, mass);
    k_trans_x<<<dim3(256, 8, 8), 256>>>(x);
    k_xspec_mma<<<dim3(32, 2, 8), 256, GEMM_SMEM>>>();
    k_coefT<<<256, 256>>>(evals, dt);
    // x_diffuse (fp16 2-MMA, per-batch B): fp16 only -> A cols [256..512)
    k_mma_h<<<dim3(2, 512), 256, HSMEM>>>(eF, NK, ytHf, ytLf,
                                          nullptr, 0, nullptr, NK, nullptr, NC*NK, 0, 256);
    // CSR build
    k_hist<<<4096, 256>>>(gx_rows, gy_rows);
    k_scan1<<<512, 256>>>();
    k_scan2<<<1, 512>>>();
    k_scan3<<<512, 256>>>();
    k_scatter<<<4096, 256>>>(gx_rows, gy_rows);
    // sparse gradients: fp16 gathers from A[256..512); float gX/gY + fp16 G
    k_spmm_csr<<<32768, 256>>>(gx_cols, gx_vals, gy_cols, gy_vals);

    // weight prep
    k_prep_cplxB<<<1024, 256>>>(A_re, A_im);
    k_prep_wT<<<768, 256>>>(W0, 768, 256, BOFF_W0);
    k_prep_wT<<<256, 256>>>(W1, 256, 256, BOFF_W1);
    k_prep_wT<<<256, 256>>>(W2, 256, 256, BOFF_W2);

    // cplx GEMM (fp16 2-MMA) with fused tanh epilogue -> A cols [512..768)
    k_mma_h<<<dim3(4, 512), 256, HSMEM>>>(GhF, 512, BhC, BlC,
                                          h0, 512, nullptr, 512, nullptr, 0, 2, -1);

    // MLP (fp16 2-MMA, stats fused)
    k_mma_h<<<dim3(2, 512), 256, HSMEM>>>(Af, 768, BhW + BOFF_W0, BlW + BOFF_W0,
                                          h0, 256, b0, 768, stats, 0, 0, -1);
    k_bnsplit<<<8192, 256>>>(h0, 0, g0, be0);
    k_mma_h<<<dim3(2, 512), 256, HSMEM>>>(Af, 768, BhW + BOFF_W1, BlW + BOFF_W1,
                                          h1, 256, b1, 256, stats + 512, 0, 0, -1);
    k_bnsplit<<<8192, 256>>>(h1, 512, g1, be1);
    k_mma_h<<<dim3(2, 512), 256, HSMEM>>>(Af, 768, BhW + BOFF_W2, BlW + BOFF_W2,
                                          h2, 256, b2, 256, stats + 1024, 0, 0, -1);
    k_final<<<16384, 256>>>(x, g2, be2, out);
}

// round 17
// speedup vs baseline: 1.4040x; 1.0402x over previous
#include <cuda_runtime.h>
#include <cuda_bf16.h>
#include <cuda_fp16.h>
#include <math.h>
#include <cstdint>

#define NB 8
#define NV 8192
#define NK 128
#define NC 256
#define NN 65536          // NB*NV
#define NNZ 1048576       // 16*NN
#define BNEPS 1e-5f

// ------------------------- scratch (device globals) -------------------------
static __device__ float d_xspec[NB*NK*NC];
static __device__ __half d_h0 [NN*NC];
static __device__ __half d_h1 [NN*NC];
static __device__ __half d_h2 [NN*NC];
static __device__ float d_stats[1536];
// CSR build scratch
static __device__ int d_cnt [131072];
static __device__ int d_off [131072];
static __device__ int d_bsum[512];
static __device__ int d_perm[2*NNZ];
// fp16 single A for MLP: [NN, 768]  (cols: x | xd | gf)  — xd cols also feed spmm
static __device__ __half d_Af[(size_t)NN*768];
// fp16 single [gX|gY] operand (written by spmm; read by cplx GEMM + gf epilogue)
static __device__ __half d_GhF[(size_t)NN*512];
// fp16 split cplx-interleaved B: [512, 512]
static __device__ __half d_BhC[262144];
static __device__ __half d_BlC[262144];
// fp16 split W pool: W0T(256x768) | W1T | W2T
#define BOFF_W0   0
#define BOFF_W1   196608
#define BOFF_W2   262144
static __device__ __half d_BhW[327680];
static __device__ __half d_BlW[327680];
// xdiff operands: evecs fp16 single; yt fp16 split
static __device__ __half d_eF[(size_t)NN*NK];
static __device__ __half d_ytHf[NB*NC*NK];
static __device__ __half d_ytLf[NB*NC*NK];
// spectral operands for xspec (bf16 split, accuracy anchor)
static __device__ __nv_bfloat16 d_mtH[(size_t)NB*NK*NV];
static __device__ __nv_bfloat16 d_mtL[(size_t)NB*NK*NV];
static __device__ __nv_bfloat16 d_xtH[(size_t)NB*NC*NV];
static __device__ __nv_bfloat16 d_xtL[(size_t)NB*NC*NV];

__device__ __forceinline__ uint32_t smem_u32(const void* p) {
    uint32_t a;
    asm("{ .reg .u64 t; cvta.to.shared.u64 t, %1; cvt.u32.u64 %0, t; }" : "=r"(a) : "l"(p));
    return a;
}

struct SplitPack4 { uint2 hi, lo; };
__device__ __forceinline__ SplitPack4 split4bf(const float* v) {
    union { __nv_bfloat16 h[4]; uint2 u; } H;
    union { __nv_bfloat16 h[4]; uint2 u; } L;
#pragma unroll
    for (int j = 0; j < 4; j++) {
        __nv_bfloat16 hh = __float2bfloat16(v[j]);
        H.h[j] = hh;
        L.h[j] = __float2bfloat16(v[j] - __bfloat162float(hh));
    }
    SplitPack4 r; r.hi = H.u; r.lo = L.u; return r;
}
__device__ __forceinline__ uint2 pack4h(const float* v) {
    union { __half h[4]; uint2 u; } P;
#pragma unroll
    for (int j = 0; j < 4; j++) P.h[j] = __float2half(v[j]);
    return P.u;
}
__device__ __forceinline__ uint4 pack8h(float4 a, float4 b) {
    union { __half h[8]; uint4 u; } P;
    P.h[0] = __float2half(a.x); P.h[1] = __float2half(a.y);
    P.h[2] = __float2half(a.z); P.h[3] = __float2half(a.w);
    P.h[4] = __float2half(b.x); P.h[5] = __float2half(b.y);
    P.h[6] = __float2half(b.z); P.h[7] = __float2half(b.w);
    return P.u;
}
__device__ __forceinline__ uint32_t pack2h(float a, float b) {
    union { __half h[2]; uint32_t u; } P;
    P.h[0] = __float2half(a); P.h[1] = __float2half(b);
    return P.u;
}
__device__ __forceinline__ void splith(float v, __half* ph, __half* pl) {
    __half h = __float2half(v);
    *ph = h;
    *pl = __float2half(v - __half2float(h));
}

// ------------------------------- zero init ----------------------------------
__global__ void k_zero() {
    int i = blockIdx.x * 256 + threadIdx.x;     // < 65536
    float4 z = make_float4(0.f, 0.f, 0.f, 0.f);
    *(float4*)&d_xspec[i * 4] = z;
    if (i < 32768) *(int4*)&d_cnt[i * 4] = make_int4(0, 0, 0, 0);
    if (i < 384)   *(float4*)&d_stats[i * 4] = z;
}

// ========================= CSR build (both matrices) =========================
__global__ void k_hist(const int* __restrict__ gxr, const int* __restrict__ gyr) {
    int i = blockIdx.x * 256 + threadIdx.x;
    atomicAdd(&d_cnt[gxr[i]], 1);
    atomicAdd(&d_cnt[65536 + gyr[i]], 1);
}

__global__ void k_scan1() {
    __shared__ int sh[256];
    int tid = threadIdx.x;
    int i = blockIdx.x * 256 + tid;
    int v = d_cnt[i];
    sh[tid] = v;
    __syncthreads();
    for (int o = 1; o < 256; o <<= 1) {
        int t = (tid >= o) ? sh[tid - o] : 0;
        __syncthreads();
        sh[tid] += t;
        __syncthreads();
    }
    d_off[i] = sh[tid] - v;
    if (tid == 255) d_bsum[blockIdx.x] = sh[255];
}

__global__ void k_scan2() {
    __shared__ int sh[512];
    int tid = threadIdx.x;
    int v = d_bsum[tid];
    sh[tid] = v;
    __syncthreads();
    for (int o = 1; o < 512; o <<= 1) {
        int t = (tid >= o) ? sh[tid - o] : 0;
        __syncthreads();
        sh[tid] += t;
        __syncthreads();
    }
    d_bsum[tid] = sh[tid] - v;
}

__global__ void k_scan3() {
    int i = blockIdx.x * 256 + threadIdx.x;
    int v = d_off[i] + d_bsum[i >> 8];
    d_off[i] = v;
    d_cnt[i] = v;
}

__global__ void k_scatter(const int* __restrict__ gxr, const int* __restrict__ gyr) {
    int i = blockIdx.x * 256 + threadIdx.x;
    int p = atomicAdd(&d_cnt[gxr[i]], 1);
    d_perm[p] = i;
    int q = atomicAdd(&d_cnt[65536 + gyr[i]], 1);
    d_perm[q] = i;
}

// merged CSR spmm: gathers fp16 xd from d_Af cols [256..512).
// writes ONLY fp16 G operand ([gX|gY], ld 512). grid 32768, 256 thr
__global__ __launch_bounds__(256) void k_spmm_csr(
    const int* __restrict__ gxc, const float* __restrict__ gxv,
    const int* __restrict__ gyc, const float* __restrict__ gyv) {
    int g = threadIdx.x >> 6, t = threadIdx.x & 63;
    int idx = blockIdx.x * 4 + g;               // < 131072
    int isX = (idx < 65536);
    const int*   cols = isX ? gxc : gyc;
    const float* vals = isX ? gxv : gyv;
    int r = idx & 65535;
    int s = d_off[idx], e = d_cnt[idx];
    int c = t * 4;
    const __half* xdF = d_Af + 256 + c;         // row stride 768
    float4 acc = make_float4(0.f, 0.f, 0.f, 0.f);
    int p = s;
    for (; p + 4 <= e; p += 4) {
        int e0 = d_perm[p], e1 = d_perm[p+1], e2 = d_perm[p+2], e3 = d_perm[p+3];
        int c0 = cols[e0], c1 = cols[e1], c2 = cols[e2], c3 = cols[e3];
        float v0 = vals[e0], v1 = vals[e1], v2 = vals[e2], v3 = vals[e3];
        uint2 r0 = *(const uint2*)&xdF[(size_t)c0 * 768];
        uint2 r1 = *(const uint2*)&xdF[(size_t)c1 * 768];
        uint2 r2 = *(const uint2*)&xdF[(size_t)c2 * 768];
        uint2 r3 = *(const uint2*)&xdF[(size_t)c3 * 768];
        float2 a0 = __half22float2(*(__half2*)&r0.x), b0 = __half22float2(*(__half2*)&r0.y);
        float2 a1 = __half22float2(*(__half2*)&r1.x), b1 = __half22float2(*(__half2*)&r1.y);
        float2 a2 = __half22float2(*(__half2*)&r2.x), b2 = __half22float2(*(__half2*)&r2.y);
        float2 a3 = __half22float2(*(__half2*)&r3.x), b3 = __half22float2(*(__half2*)&r3.y);
        acc.x += v0*a0.x + v1*a1.x + v2*a2.x + v3*a3.x;
        acc.y += v0*a0.y + v1*a1.y + v2*a2.y + v3*a3.y;
        acc.z += v0*b0.x + v1*b1.x + v2*b2.x + v3*b3.x;
        acc.w += v0*b0.y + v1*b1.y + v2*b2.y + v3*b3.y;
    }
    for (; p < e; p++) {
        int ed = d_perm[p];
        int cl = cols[ed];
        float v = vals[ed];
        uint2 r0 = *(const uint2*)&xdF[(size_t)cl * 768];
        float2 a0 = __half22float2(*(__half2*)&r0.x), b0 = __half22float2(*(__half2*)&r0.y);
        acc.x += v*a0.x; acc.y += v*a0.y; acc.z += v*b0.x; acc.w += v*b0.y;
    }
    *(uint2*)&d_GhF[(size_t)r * 512 + (isX ? 0 : 256) + c] = pack4h(&acc.x);
}

// ===================== spectral operand preparation ==========================
__global__ __launch_bounds__(256) void k_trans_mevecs(
    const float* __restrict__ evecs, const float* __restrict__ mass) {
    __shared__ float tile[32][33];
    __shared__ float smass[32];
    int v0 = blockIdx.x * 32, k0 = blockIdx.y * 32, b = blockIdx.z;
    int tid = threadIdx.x;
    int tx = tid & 31, ty = tid >> 5;
    if (tid < 32) smass[tid] = mass[b * NV + v0 + tid];
#pragma unroll
    for (int i = 0; i < 4; i++) {
        int vl = ty + i * 8;
        tile[vl][tx] = evecs[(size_t)(b * NV + v0 + vl) * NK + k0 + tx];
    }
    __syncthreads();
    {
        int k = tid >> 3, vq = (tid & 7) * 4;
        float v[4];
#pragma unroll
        for (int j = 0; j < 4; j++) v[j] = tile[vq + j][k] * smass[vq + j];
        SplitPack4 p = split4bf(v);
        size_t o = (size_t)(b * NK + k0 + k) * NV + v0 + vq;
        *(uint2*)&d_mtH[o] = p.hi;
        *(uint2*)&d_mtL[o] = p.lo;
    }
    {
        int v = tid >> 3, kq = (tid & 7) * 4;
        float w[4];
#pragma unroll
        for (int j = 0; j < 4; j++) w[j] = tile[v][kq + j];
        size_t o = (size_t)(b * NV + v0 + v) * NK + k0 + kq;
        *(uint2*)&d_eF[o] = pack4h(w);
    }
}

__global__ __launch_bounds__(256) void k_trans_x(const float* __restrict__ x) {
    __shared__ float tile[32][33];
    int v0 = blockIdx.x * 32, c0 = blockIdx.y * 32, b = blockIdx.z;
    int tid = threadIdx.x;
    int tx = tid & 31, ty = tid >> 5;
#pragma unroll
    for (int i = 0; i < 4; i++) {
        int vl = ty + i * 8;
        tile[vl][tx] = x[(size_t)(b * NV + v0 + vl) * NC + c0 + tx];
    }
    __syncthreads();
    {
        int c = tid >> 3, vq = (tid & 7) * 4;
        float v[4];
#pragma unroll
        for (int j = 0; j < 4; j++) v[j] = tile[vq + j][c];
        SplitPack4 p = split4bf(v);
        size_t o = (size_t)(b * NC + c0 + c) * NV + v0 + vq;
        *(uint2*)&d_xtH[o] = p.hi;
        *(uint2*)&d_xtL[o] = p.lo;
    }
    {
        int v = tid >> 3, cq = (tid & 7) * 4;
        float w[4];
#pragma unroll
        for (int j = 0; j < 4; j++) w[j] = tile[v][cq + j];
        size_t o = (size_t)(b * NV + v0 + v) * 768 + c0 + cq;
        *(uint2*)&d_Af[o] = pack4h(w);
    }
}

__global__ void k_coefT(const float* __restrict__ evals, const float* __restrict__ dt) {
    int i = blockIdx.x * 256 + threadIdx.x;   // < 65536
    int kq = (i & 31) * 4;
    int c  = (i >> 5) & 255;
    int b  = i >> 13;
    float t = fmaxf(dt[c], 1e-8f);
    union { __half h[4]; uint2 u; } H, L;
#pragma unroll
    for (int j = 0; j < 4; j++) {
        float v = expf(-evals[b * NK + kq + j] * t) * d_xspec[(b * NK + kq + j) * NC + c];
        __half hh = __float2half(v);
        H.h[j] = hh;
        L.h[j] = __float2half(v - __half2float(hh));
    }
    int o = b * (NC * NK) + c * NK + kq;
    *(uint2*)&d_ytHf[o] = H.u;
    *(uint2*)&d_ytLf[o] = L.u;
}

// ============================ mma primitives =================================
__device__ __forceinline__ void ldsm_x4(uint32_t* r, uint32_t addr) {
    asm volatile("ldmatrix.sync.aligned.m8n8.x4.shared.b16 {%0,%1,%2,%3}, [%4];"
                 : "=r"(r[0]), "=r"(r[1]), "=r"(r[2]), "=r"(r[3]) : "r"(addr));
}
__device__ __forceinline__ void ldsm_x2(uint32_t* r, uint32_t addr) {
    asm volatile("ldmatrix.sync.aligned.m8n8.x2.shared.b16 {%0,%1}, [%2];"
                 : "=r"(r[0]), "=r"(r[1]) : "r"(addr));
}
__device__ __forceinline__ void mma16816(float* c, const uint32_t* a, const uint32_t* b) {
    asm volatile("mma.sync.aligned.m16n8k16.row.col.f32.bf16.bf16.f32 "
                 "{%0,%1,%2,%3}, {%4,%5,%6,%7}, {%8,%9}, {%0,%1,%2,%3};"
                 : "+f"(c[0]), "+f"(c[1]), "+f"(c[2]), "+f"(c[3])
                 : "r"(a[0]), "r"(a[1]), "r"(a[2]), "r"(a[3]), "r"(b[0]), "r"(b[1]));
}
__device__ __forceinline__ void mma16816h(float* c, const uint32_t* a, const uint32_t* b) {
    asm volatile("mma.sync.aligned.m16n8k16.row.col.f32.f16.f16.f32 "
                 "{%0,%1,%2,%3}, {%4,%5,%6,%7}, {%8,%9}, {%0,%1,%2,%3};"
                 : "+f"(c[0]), "+f"(c[1]), "+f"(c[2]), "+f"(c[3])
                 : "r"(a[0]), "r"(a[1]), "r"(a[2]), "r"(a[3]), "r"(b[0]), "r"(b[1]));
}
#define CP_ASYNC(sm, gm) \
    asm volatile("cp.async.cg.shared.global [%0], [%1], 16;" :: "r"(sm), "l"(gm))
#define CP_ASYNC_CA(sm, gm) \
    asm volatile("cp.async.ca.shared.global [%0], [%1], 16;" :: "r"(sm), "l"(gm))
#define CP_COMMIT() asm volatile("cp.async.commit_group;" ::: "memory")
#define CP_WAIT(n)  asm volatile("cp.async.wait_group %0;" :: "n"(n) : "memory")

#define ASTR 40
#define TILEEL (128*ASTR)
#define GEMM_SMEM (2*4*TILEEL*2)   // xspec bf16 kernel: 81920
#define SLOT3 (TILEEL*2)           // 10240 bytes
#define HSMEM 65536                // fp16 kernel

// ------------------- x_spec split-K mma (bf16 3-term): grid (32, 2, 8) -------
__global__ __launch_bounds__(256, 2) void k_xspec_mma() {
    extern __shared__ __align__(16) __nv_bfloat16 sm[];
    int tid = threadIdx.x;
    int wid = tid >> 5, lane = tid & 31;
    int wm = wid & 1, wn = wid >> 1;
    int kb = blockIdx.x, ch = blockIdx.y, b = blockIdx.z;
    const __nv_bfloat16* Ah = d_mtH + (size_t)b * NK * NV;
    const __nv_bfloat16* Al = d_mtL + (size_t)b * NK * NV;
    const __nv_bfloat16* Bh = d_xtH + (size_t)(b * NC + ch * 128) * NV;
    const __nv_bfloat16* Bl = d_xtL + (size_t)(b * NC + ch * 128) * NV;
    int kbase = kb * 256;

    float acc[4][4][4];
#pragma unroll
    for (int mi = 0; mi < 4; mi++)
#pragma unroll
        for (int ni = 0; ni < 4; ni++)
#pragma unroll
            for (int q = 0; q < 4; q++) acc[mi][ni][q] = 0.f;

    int idx0 = tid * 2, idx1 = tid * 2 + 1;
    int lr0 = idx0 >> 2, ls0 = idx0 & 3;
    int lr1 = idx1 >> 2, ls1 = idx1 & 3;
    uint32_t so0 = (uint32_t)(lr0 * ASTR + ls0 * 8) * 2;
    uint32_t so1 = (uint32_t)(lr1 * ASTR + ls1 * 8) * 2;
    uint32_t smbase = smem_u32(sm);

#define XLOAD(s) do { \
    uint32_t sb = smbase + (uint32_t)((s) & 1) * 4u * TILEEL * 2u; \
    int k0 = kbase + ((s) << 5); \
    CP_ASYNC(sb + so0, Ah + (size_t)lr0 * NV + k0 + ls0*8); \
    CP_ASYNC(sb + so1, Ah + (size_t)lr1 * NV + k0 + ls1*8); \
    CP_ASYNC(sb + TILEEL*2 + so0, Al + (size_t)lr0 * NV + k0 + ls0*8); \
    CP_ASYNC(sb + TILEEL*2 + so1, Al + (size_t)lr1 * NV + k0 + ls1*8); \
    CP_ASYNC(sb + 2*TILEEL*2 + so0, Bh + (size_t)lr0 * NV + k0 + ls0*8); \
    CP_ASYNC(sb + 2*TILEEL*2 + so1, Bh + (size_t)lr1 * NV + k0 + ls1*8); \
    CP_ASYNC(sb + 3*TILEEL*2 + so0, Bl + (size_t)lr0 * NV + k0 + ls0*8); \
    CP_ASYNC(sb + 3*TILEEL*2 + so1, Bl + (size_t)lr1 * NV + k0 + ls1*8); \
} while (0)

    XLOAD(0);
    CP_COMMIT();

    int arow = (lane & 15), acol = (lane >> 4) * 8;
    int brow = (lane & 7),  bcol = ((lane >> 3) & 1) * 8;

    for (int s = 0; s < 8; s++) {
        if (s + 1 < 8) { XLOAD(s + 1); CP_COMMIT(); CP_WAIT(1); }
        else           { CP_WAIT(0); }
        __syncthreads();
        uint32_t sb = smbase + (uint32_t)(s & 1) * 4u * TILEEL * 2u;
        uint32_t Ah_s = sb, Al_s = sb + TILEEL*2, Bh_s = sb + 2*TILEEL*2, Bl_s = sb + 3*TILEEL*2;
#pragma unroll
        for (int ks = 0; ks < 2; ks++) {
            int k0 = ks * 16;
            uint32_t aH[4][4], aL[4][4];
#pragma unroll
            for (int mi = 0; mi < 4; mi++) {
                uint32_t off = (uint32_t)((wm*64 + mi*16 + arow) * ASTR + k0 + acol) * 2;
                ldsm_x4(aH[mi], Ah_s + off);
                ldsm_x4(aL[mi], Al_s + off);
            }
            uint32_t bH[4][2], bL[4][2];
#pragma unroll
            for (int ni = 0; ni < 4; ni++) {
                uint32_t off = (uint32_t)((wn*32 + ni*8 + brow) * ASTR + k0 + bcol) * 2;
                ldsm_x2(bH[ni], Bh_s + off);
                ldsm_x2(bL[ni], Bl_s + off);
            }
#pragma unroll
            for (int mi = 0; mi < 4; mi++)
#pragma unroll
                for (int ni = 0; ni < 4; ni++)
                    mma16816(acc[mi][ni], aH[mi], bH[ni]);
#pragma unroll
            for (int mi = 0; mi < 4; mi++)
#pragma unroll
                for (int ni = 0; ni < 4; ni++)
                    mma16816(acc[mi][ni], aH[mi], bL[ni]);
#pragma unroll
            for (int mi = 0; mi < 4; mi++)
#pragma unroll
                for (int ni = 0; ni < 4; ni++)
                    mma16816(acc[mi][ni], aL[mi], bH[ni]);
        }
        __syncthreads();
    }

    int g4 = lane >> 2, t4 = lane & 3;
#pragma unroll
    for (int mi = 0; mi < 4; mi++) {
        int r = wm*64 + mi*16 + g4;
#pragma unroll
        for (int ni = 0; ni < 4; ni++) {
            int c = ch*128 + wn*32 + ni*8 + t4*2;
            float* o0 = &d_xspec[(b*NK + r) * NC + c];
            float* o1 = &d_xspec[(b*NK + r + 8) * NC + c];
            asm volatile("red.global.add.v2.f32 [%0], {%1,%2};"
                         :: "l"(o0), "f"(acc[mi][ni][0]), "f"(acc[mi][ni][1]) : "memory");
            asm volatile("red.global.add.v2.f32 [%0], {%1,%2};"
                         :: "l"(o1), "f"(acc[mi][ni][2]), "f"(acc[mi][ni][3]) : "memory");
        }
    }
}

// ========================== B-operand prep ==================================
__global__ void k_prep_cplxB(const float* __restrict__ Are, const float* __restrict__ Aim) {
    int i = blockIdx.x * 256 + threadIdx.x;   // < 262144
    int n = i >> 9, k = i & 511;
    int m = n >> 1;
    float v;
    if ((n & 1) == 0) v = (k < 256) ? Are[m*256 + k] : -Aim[m*256 + (k-256)];
    else              v = (k < 256) ? Aim[m*256 + k] :  Are[m*256 + (k-256)];
    splith(v, &d_BhC[i], &d_BlC[i]);
}

__global__ void k_prep_wT(const float* __restrict__ W, int K, int N, int off) {
    int i = blockIdx.x * 256 + threadIdx.x;
    if (i >= N * K) return;
    int n = i / K, k = i % K;
    splith(W[k*N + n], &d_BhW[off + i], &d_BlW[off + i]);
}

// relu(bn(h fp16)) -> A cols [0..255] (fp16). grid 8192, 256 thr
__global__ void k_bnsplit(const __half* __restrict__ h, int statoff,
                          const float* __restrict__ g, const float* __restrict__ be) {
    int tid = threadIdx.x;
    __shared__ float sc[256], sh[256];
    {
        float mean = d_stats[statoff + tid] * (1.0f / NN);
        float var  = d_stats[statoff + 256 + tid] * (1.0f / NN) - mean * mean;
        float s = rsqrtf(var + BNEPS) * g[tid];
        sc[tid] = s;
        sh[tid] = be[tid] - mean * s;
    }
    __syncthreads();
    int idx = blockIdx.x * 256 + tid;          // < 2097152
    size_t row = idx >> 5;
    int c = (idx & 31) * 8;
    uint4 hu = *(const uint4*)&h[row * 256 + c];
    float2 p0 = __half22float2(*(__half2*)&hu.x);
    float2 p1 = __half22float2(*(__half2*)&hu.y);
    float2 p2 = __half22float2(*(__half2*)&hu.z);
    float2 p3 = __half22float2(*(__half2*)&hu.w);
    float4 v0, v1;
    v0.x = fmaxf(p0.x * sc[c+0] + sh[c+0], 0.f);
    v0.y = fmaxf(p0.y * sc[c+1] + sh[c+1], 0.f);
    v0.z = fmaxf(p1.x * sc[c+2] + sh[c+2], 0.f);
    v0.w = fmaxf(p1.y * sc[c+3] + sh[c+3], 0.f);
    v1.x = fmaxf(p2.x * sc[c+4] + sh[c+4], 0.f);
    v1.y = fmaxf(p2.y * sc[c+5] + sh[c+5], 0.f);
    v1.z = fmaxf(p3.x * sc[c+6] + sh[c+6], 0.f);
    v1.w = fmaxf(p3.y * sc[c+7] + sh[c+7], 0.f);
    *(uint4*)&d_Af[row * 768 + c] = pack8h(v0, v1);
}

// =================== generic fp16 2-MMA GEMM =================================
// C = A(single fp16) @ (Bh+Bl)(fp16 split)^T.  grid (N/128, M/128), 256 thr.
// mode 0: optional fp16 out+bias (+stats, +fp16 asplit); mode 2: gf epilogue.
__global__ __launch_bounds__(256, 2) void k_mma_h(
    const __half* __restrict__ Af, int ldA,
    const __half* __restrict__ Bh, const __half* __restrict__ Bl,
    __half* __restrict__ out, int ldout, const float* __restrict__ bias, int K,
    float* __restrict__ stats, int bstrideB, int mode, int asplit_off)
{
    extern __shared__ __align__(16) __half smh[];
    int tid = threadIdx.x;
    int wid = tid >> 5, lane = tid & 31;
    int wm = wid & 1, wn = wid >> 1;
    int row0 = blockIdx.y * 128, n0 = blockIdx.x * 128;
    if (bstrideB) {
        int b = row0 / NV;
        Bh += (size_t)b * bstrideB;
        Bl += (size_t)b * bstrideB;
    }
    const int S = K >> 5;

    float acc[4][4][4];
#pragma unroll
    for (int mi = 0; mi < 4; mi++)
#pragma unroll
        for (int ni = 0; ni < 4; ni++)
#pragma unroll
            for (int q = 0; q < 4; q++) acc[mi][ni][q] = 0.f;

    int idx0 = tid * 2, idx1 = tid * 2 + 1;
    int lr0 = idx0 >> 2, ls0 = idx0 & 3;
    int lr1 = idx1 >> 2, ls1 = idx1 & 3;
    uint32_t so0 = (uint32_t)(lr0 * ASTR + ls0 * 8) * 2;
    uint32_t so1 = (uint32_t)(lr1 * ASTR + ls1 * 8) * 2;
    uint32_t smbase = smem_u32(smh);

#define HLOAD(s) do { \
    uint32_t sb = smbase + (uint32_t)((s) & 1) * 3u * (uint32_t)SLOT3; \
    int k0 = (s) << 5; \
    CP_ASYNC(sb + so0, Af + (size_t)(row0 + lr0) * ldA + k0 + ls0*8); \
    CP_ASYNC(sb + so1, Af + (size_t)(row0 + lr1) * ldA + k0 + ls1*8); \
    CP_ASYNC_CA(sb + SLOT3 + so0, Bh + (size_t)(n0 + lr0) * K + k0 + ls0*8); \
    CP_ASYNC_CA(sb + SLOT3 + so1, Bh + (size_t)(n0 + lr1) * K + k0 + ls1*8); \
    CP_ASYNC_CA(sb + 2*SLOT3 + so0, Bl + (size_t)(n0 + lr0) * K + k0 + ls0*8); \
    CP_ASYNC_CA(sb + 2*SLOT3 + so1, Bl + (size_t)(n0 + lr1) * K + k0 + ls1*8); \
} while (0)

    HLOAD(0);
    CP_COMMIT();

    int arow = (lane & 15), acol = (lane >> 4) * 8;
    int brow = (lane & 7),  bcol = ((lane >> 3) & 1) * 8;

    for (int s = 0; s < S; s++) {
        if (s + 1 < S) { HLOAD(s + 1); CP_COMMIT(); CP_WAIT(1); }
        else           { CP_WAIT(0); }
        __syncthreads();
        uint32_t sb = smbase + (uint32_t)(s & 1) * 3u * (uint32_t)SLOT3;
        uint32_t A_s = sb, Bh_s = sb + SLOT3, Bl_s = sb + 2*SLOT3;
#pragma unroll
        for (int ks = 0; ks < 2; ks++) {
            int k0 = ks * 16;
            uint32_t aF[4][4];
#pragma unroll
            for (int mi = 0; mi < 4; mi++) {
                uint32_t off = (uint32_t)((wm*64 + mi*16 + arow) * ASTR + k0 + acol) * 2;
                ldsm_x4(aF[mi], A_s + off);
            }
            uint32_t bH[4][2], bL[4][2];
#pragma unroll
            for (int ni = 0; ni < 4; ni++) {
                uint32_t off = (uint32_t)((wn*32 + ni*8 + brow) * ASTR + k0 + bcol) * 2;
                ldsm_x2(bH[ni], Bh_s + off);
                ldsm_x2(bL[ni], Bl_s + off);
            }
#pragma unroll
            for (int mi = 0; mi < 4; mi++)
#pragma unroll
                for (int ni = 0; ni < 4; ni++)
                    mma16816h(acc[mi][ni], aF[mi], bH[ni]);
#pragma unroll
            for (int mi = 0; mi < 4; mi++)
#pragma unroll
                for (int ni = 0; ni < 4; ni++)
                    mma16816h(acc[mi][ni], aF[mi], bL[ni]);
        }
        __syncthreads();
    }

    int g4 = lane >> 2, t4 = lane & 3;

    if (mode == 2) {
        // gf epilogue: gX/gY read from fp16 G operand (d_GhF)
        float2* sgf = (float2*)smh;
#pragma unroll
        for (int mi = 0; mi < 4; mi++) {
            int rl = wm*64 + mi*16 + g4;
#pragma unroll
            for (int ni = 0; ni < 4; ni++) {
                int chl = wn*16 + ni*4 + t4;
                sgf[rl*64 + chl]       = make_float2(acc[mi][ni][0], acc[mi][ni][1]);
                sgf[(rl+8)*64 + chl]   = make_float2(acc[mi][ni][2], acc[mi][ni][3]);
            }
        }
        __syncthreads();
        int rl = tid >> 1;
        int co = (tid & 1) * 32;
        int r = row0 + rl;
        int chbase = (n0 >> 1) + co;
        const __half* gxp = d_GhF + (size_t)r * 512 + chbase;
        const __half* gyp = gxp + 256;
        size_t ao = (size_t)r * 768 + 512 + chbase;
#pragma unroll
        for (int j0 = 0; j0 < 32; j0 += 8) {
            uint4 ux = *(const uint4*)(gxp + j0);
            uint4 uy = *(const uint4*)(gyp + j0);
            float2 gx01 = __half22float2(*(__half2*)&ux.x);
            float2 gx23 = __half22float2(*(__half2*)&ux.y);
            float2 gx45 = __half22float2(*(__half2*)&ux.z);
            float2 gx67 = __half22float2(*(__half2*)&ux.w);
            float2 gy01 = __half22float2(*(__half2*)&uy.x);
            float2 gy23 = __half22float2(*(__half2*)&uy.y);
            float2 gy45 = __half22float2(*(__half2*)&uy.z);
            float2 gy67 = __half22float2(*(__half2*)&uy.w);
            float4 t0, t1;
            float2 p;
            p = sgf[rl*64 + co + j0 + 0]; t0.x = tanhf(gx01.x*p.x + gy01.x*p.y);
            p = sgf[rl*64 + co + j0 + 1]; t0.y = tanhf(gx01.y*p.x + gy01.y*p.y);
            p = sgf[rl*64 + co + j0 + 2]; t0.z = tanhf(gx23.x*p.x + gy23.x*p.y);
            p = sgf[rl*64 + co + j0 + 3]; t0.w = tanhf(gx23.y*p.x + gy23.y*p.y);
            p = sgf[rl*64 + co + j0 + 4]; t1.x = tanhf(gx45.x*p.x + gy45.x*p.y);
            p = sgf[rl*64 + co + j0 + 5]; t1.y = tanhf(gx45.y*p.x + gy45.y*p.y);
            p = sgf[rl*64 + co + j0 + 6]; t1.z = tanhf(gx67.x*p.x + gy67.x*p.y);
            p = sgf[rl*64 + co + j0 + 7]; t1.w = tanhf(gx67.y*p.x + gy67.y*p.y);
            *(uint4*)&d_Af[ao + j0] = pack8h(t0, t1);
        }
        return;
    }

    // mode 0
    float cs[4][2], cq[4][2];
#pragma unroll
    for (int ni = 0; ni < 4; ni++) { cs[ni][0]=cs[ni][1]=cq[ni][0]=cq[ni][1]=0.f; }

#pragma unroll
    for (int mi = 0; mi < 4; mi++) {
        int r = row0 + wm*64 + mi*16 + g4;
#pragma unroll
        for (int ni = 0; ni < 4; ni++) {
            int c = n0 + wn*32 + ni*8 + t4*2;
            float b0 = 0.f, b1 = 0.f;
            if (bias) { b0 = bias[c]; b1 = bias[c+1]; }
            float v0 = acc[mi][ni][0] + b0, v1 = acc[mi][ni][1] + b1;
            float v2 = acc[mi][ni][2] + b0, v3 = acc[mi][ni][3] + b1;
            if (out) {
                *(uint32_t*)&out[(size_t)r * ldout + c]     = pack2h(v0, v1);
                *(uint32_t*)&out[(size_t)(r+8) * ldout + c] = pack2h(v2, v3);
            }
            if (asplit_off >= 0) {
                *(uint32_t*)&d_Af[(size_t)r * 768 + asplit_off + c]     = pack2h(v0, v1);
                *(uint32_t*)&d_Af[(size_t)(r+8) * 768 + asplit_off + c] = pack2h(v2, v3);
            }
            cs[ni][0] += v0 + v2;  cq[ni][0] += v0*v0 + v2*v2;
            cs[ni][1] += v1 + v3;  cq[ni][1] += v1*v1 + v3*v3;
        }
    }
    if (stats) {
#pragma unroll
        for (int ni = 0; ni < 4; ni++) {
#pragma unroll
            for (int h = 0; h < 2; h++) {
                float s = cs[ni][h], q = cq[ni][h];
                s += __shfl_xor_sync(0xFFFFFFFFu, s, 4);
                q += __shfl_xor_sync(0xFFFFFFFFu, q, 4);
                s += __shfl_xor_sync(0xFFFFFFFFu, s, 8);
                q += __shfl_xor_sync(0xFFFFFFFFu, q, 8);
                s += __shfl_xor_sync(0xFFFFFFFFu, s, 16);
                q += __shfl_xor_sync(0xFFFFFFFFu, q, 16);
                if (g4 == 0) {
                    int c = n0 + wn*32 + ni*8 + t4*2 + h;
                    atomicAdd(&stats[c], s);
                    atomicAdd(&stats[256 + c], q);
                }
            }
        }
    }
}

// out = bn(h2 fp16) + x
__global__ void k_final(const float* __restrict__ x, const float* __restrict__ g,
                        const float* __restrict__ be, float* __restrict__ out) {
    int tid = threadIdx.x;
    __shared__ float sc[256], sh[256];
    {
        float mean = d_stats[1024 + tid] * (1.0f / NN);
        float var  = d_stats[1280 + tid] * (1.0f / NN) - mean * mean;
        float s = rsqrtf(var + BNEPS) * g[tid];
        sc[tid] = s;
        sh[tid] = be[tid] - mean * s;
    }
    __syncthreads();
    size_t i = (size_t)(blockIdx.x * 256 + tid) * 4;
    int c = (int)(i & 255);
    uint2 hu = *(const uint2*)&d_h2[i];
    float2 h01 = __half22float2(*(__half2*)&hu.x);
    float2 h23 = __half22float2(*(__half2*)&hu.y);
    float4 xv = *(const float4*)&x[i];
    float4 o;
    o.x = h01.x * sc[c+0] + sh[c+0] + xv.x;
    o.y = h01.y * sc[c+1] + sh[c+1] + xv.y;
    o.z = h23.x * sc[c+2] + sh[c+2] + xv.z;
    o.w = h23.y * sc[c+3] + sh[c+3] + xv.w;
    *(float4*)&out[i] = o;
}

// ------------------------------- launch --------------------------------------
extern "C" void kernel_launch(void* const* d_in, const int* in_sizes, int n_in,
                              void* d_out, int out_size) {
    const float* x       = (const float*)d_in[0];
    const float* mass    = (const float*)d_in[1];
    const float* evals   = (const float*)d_in[2];
    const float* evecs   = (const float*)d_in[3];
    const int*   gx_rows = (const int*)  d_in[4];
    const int*   gx_cols = (const int*)  d_in[5];
    const float* gx_vals = (const float*)d_in[6];
    const int*   gy_rows = (const int*)  d_in[7];
    const int*   gy_cols = (const int*)  d_in[8];
    const float* gy_vals = (const float*)d_in[9];
    const float* dt      = (const float*)d_in[10];
    const float* A_re    = (const float*)d_in[11];
    const float* A_im    = (const float*)d_in[12];
    const float* W0      = (const float*)d_in[13];
    const float* b0      = (const float*)d_in[14];
    const float* g0      = (const float*)d_in[15];
    const float* be0     = (const float*)d_in[16];
    const float* W1      = (const float*)d_in[17];
    const float* b1      = (const float*)d_in[18];
    const float* g1      = (const float*)d_in[19];
    const float* be1     = (const float*)d_in[20];
    const float* W2      = (const float*)d_in[21];
    const float* b2      = (const float*)d_in[22];
    const float* g2      = (const float*)d_in[23];
    const float* be2     = (const float*)d_in[24];
    float* out = (float*)d_out;

    static int smem_set = 0;
    if (!smem_set) {
        cudaFuncSetAttribute(k_xspec_mma, cudaFuncAttributeMaxDynamicSharedMemorySize, GEMM_SMEM);
        cudaFuncSetAttribute(k_mma_h, cudaFuncAttributeMaxDynamicSharedMemorySize, HSMEM);
        smem_set = 1;
    }

    __half *Af, *GhF, *BhC, *BlC, *BhW, *BlW, *eF, *ytHf, *ytLf, *h0, *h1, *h2;
    float *stats;
    cudaGetSymbolAddress((void**)&Af, d_Af);
    cudaGetSymbolAddress((void**)&GhF, d_GhF);
    cudaGetSymbolAddress((void**)&BhC, d_BhC);
    cudaGetSymbolAddress((void**)&BlC, d_BlC);
    cudaGetSymbolAddress((void**)&BhW, d_BhW);
    cudaGetSymbolAddress((void**)&BlW, d_BlW);
    cudaGetSymbolAddress((void**)&eF, d_eF);
    cudaGetSymbolAddress((void**)&ytHf, d_ytHf);
    cudaGetSymbolAddress((void**)&ytLf, d_ytLf);
    cudaGetSymbolAddress((void**)&h0, d_h0);
    cudaGetSymbolAddress((void**)&h1, d_h1);
    cudaGetSymbolAddress((void**)&h2, d_h2);
    cudaGetSymbolAddress((void**)&stats, d_stats);

    k_zero<<<256, 256>>>();
    k_trans_mevecs<<<dim3(256, 4, 8), 256>>>(evecs, mass);
    k_trans_x<<<dim3(256, 8, 8), 256>>>(x);
    k_xspec_mma<<<dim3(32, 2, 8), 256, GEMM_SMEM>>>();
    k_coefT<<<256, 256>>>(evals, dt);
    // x_diffuse (fp16 2-MMA, per-batch B): fp16 only -> A cols [256..512)
    k_mma_h<<<dim3(2, 512), 256, HSMEM>>>(eF, NK, ytHf, ytLf,
                                          nullptr, 0, nullptr, NK, nullptr, NC*NK, 0, 256);
    // CSR build
    k_hist<<<4096, 256>>>(gx_rows, gy_rows);
    k_scan1<<<512, 256>>>();
    k_scan2<<<1, 512>>>();
    k_scan3<<<512, 256>>>();
    k_scatter<<<4096, 256>>>(gx_rows, gy_rows);
    // sparse gradients: fp16 gathers from A[256..512) -> fp16 G operand only
    k_spmm_csr<<<32768, 256>>>(gx_cols, gx_vals, gy_cols, gy_vals);

    // weight prep
    k_prep_cplxB<<<1024, 256>>>(A_re, A_im);
    k_prep_wT<<<768, 256>>>(W0, 768, 256, BOFF_W0);
    k_prep_wT<<<256, 256>>>(W1, 256, 256, BOFF_W1);
    k_prep_wT<<<256, 256>>>(W2, 256, 256, BOFF_W2);

    // cplx GEMM (fp16 2-MMA) with fused tanh epilogue -> A cols [512..768)
    k_mma_h<<<dim3(4, 512), 256, HSMEM>>>(GhF, 512, BhC, BlC,
                                          nullptr, 0, nullptr, 512, nullptr, 0, 2, -1);

    // MLP (fp16 2-MMA, stats fused; h buffers fp16)
    k_mma_h<<<dim3(2, 512), 256, HSMEM>>>(Af, 768, BhW + BOFF_W0, BlW + BOFF_W0,
                                          h0, 256, b0, 768, stats, 0, 0, -1);
    k_bnsplit<<<8192, 256>>>(h0, 0, g0, be0);
    k_mma_h<<<dim3(2, 512), 256, HSMEM>>>(Af, 768, BhW + BOFF_W1, BlW + BOFF_W1,
                                          h1, 256, b1, 256, stats + 512, 0, 0, -1);
    k_bnsplit<<<8192, 256>>>(h1, 512, g1, be1);
    k_mma_h<<<dim3(2, 512), 256, HSMEM>>>(Af, 768, BhW + BOFF_W2, BlW + BOFF_W2,
                                          h2, 256, b2, 256, stats + 1024, 0, 0, -1);
    k_final<<<16384, 256>>>(x, g2, be2, out);
}